// round 1
// baseline (speedup 1.0000x reference)
#include <cuda_runtime.h>
#include <math.h>

// ---------------- problem constants ----------------
#define HRES   56
#define C_     192
#define NHEAD  6
#define WS_    7
#define NTOK   49          // tokens per window
#define HID_   768
#define NWIN   64          // windows per image (8x8)
#define HEADD  32
#define BATCH  32
#define NWTOT  2048        // BATCH * NWIN
#define MROWS  100352      // NWTOT * 49 == BATCH * 3136

// ---------------- scratch (device globals; no runtime alloc) ----------------
__device__ float g_xw  [(size_t)MROWS * C_];       //  77 MB  LN1+shift+partition
__device__ float g_qkv [(size_t)MROWS * 3 * C_];   // 231 MB
__device__ float g_attn[(size_t)MROWS * C_];       //  77 MB
__device__ float g_x1  [(size_t)MROWS * C_];       //  77 MB  residual stream after attn
__device__ float g_xn2 [(size_t)MROWS * C_];       //  77 MB  LN2 output
__device__ float g_h1  [(size_t)MROWS * HID_];     // 308 MB  MLP hidden

// ---------------- helpers ----------------
__device__ __forceinline__ float warp_sum(float v) {
#pragma unroll
    for (int o = 16; o; o >>= 1) v += __shfl_xor_sync(0xffffffffu, v, o);
    return v;
}

__device__ __forceinline__ float gelu_exact(float x) {
    return 0.5f * x * (1.0f + erff(x * 0.70710678118654752f));
}

// ---------------- LN1 + cyclic shift + window partition ----------------
// out row idx = ((b*8+wh)*8+ww)*49 + n   reads x[b, h*56+w, :] with
// h=(wh*7 + n/7 + 3) mod 56, w=(ww*7 + n%7 + 3) mod 56  (roll by -3)
__global__ void ln_partition_kernel(const float* __restrict__ x,
                                    const float* __restrict__ g,
                                    const float* __restrict__ bt,
                                    float* __restrict__ out) {
    int warp = (blockIdx.x * blockDim.x + threadIdx.x) >> 5;
    int lane = threadIdx.x & 31;
    if (warp >= MROWS) return;
    int n = warp % 49;
    int window = warp / 49;
    int wi = window & 63;
    int b  = window >> 6;
    int wh = wi >> 3, ww = wi & 7;
    int h = wh * 7 + n / 7 + 3; if (h >= 56) h -= 56;
    int w = ww * 7 + n % 7 + 3; if (w >= 56) w -= 56;
    const float* xi = x + ((size_t)b * 3136 + h * 56 + w) * 192;

    float v[6]; float s1 = 0.f;
#pragma unroll
    for (int j = 0; j < 6; j++) { v[j] = xi[lane + 32 * j]; s1 += v[j]; }
    s1 = warp_sum(s1);
    float mean = s1 * (1.0f / 192.0f);
    float s2 = 0.f;
#pragma unroll
    for (int j = 0; j < 6; j++) { float d = v[j] - mean; s2 += d * d; }
    s2 = warp_sum(s2);
    float inv = rsqrtf(s2 * (1.0f / 192.0f) + 1e-5f);
    float* o = out + (size_t)warp * 192;
#pragma unroll
    for (int j = 0; j < 6; j++) {
        int c = lane + 32 * j;
        o[c] = (v[j] - mean) * inv * g[c] + bt[c];
    }
}

// ---------------- plain LN (LN2) ----------------
__global__ void ln_plain_kernel(const float* __restrict__ x,
                                const float* __restrict__ g,
                                const float* __restrict__ bt,
                                float* __restrict__ out) {
    int warp = (blockIdx.x * blockDim.x + threadIdx.x) >> 5;
    int lane = threadIdx.x & 31;
    if (warp >= MROWS) return;
    const float* xi = x + (size_t)warp * 192;
    float v[6]; float s1 = 0.f;
#pragma unroll
    for (int j = 0; j < 6; j++) { v[j] = xi[lane + 32 * j]; s1 += v[j]; }
    s1 = warp_sum(s1);
    float mean = s1 * (1.0f / 192.0f);
    float s2 = 0.f;
#pragma unroll
    for (int j = 0; j < 6; j++) { float d = v[j] - mean; s2 += d * d; }
    s2 = warp_sum(s2);
    float inv = rsqrtf(s2 * (1.0f / 192.0f) + 1e-5f);
    float* o = out + (size_t)warp * 192;
#pragma unroll
    for (int j = 0; j < 6; j++) {
        int c = lane + 32 * j;
        o[c] = (v[j] - mean) * inv * g[c] + bt[c];
    }
}

// ---------------- attention: one block per (window, head) ----------------
__global__ void attn_kernel(const float* __restrict__ qkv,
                            const float* __restrict__ bias_table,
                            float* __restrict__ outp) {
    __shared__ float sq[49 * 32];
    __shared__ float sk[49 * 32];
    __shared__ float sv[49 * 32];
    __shared__ float S[49 * 49];
    __shared__ int   sreg[49];

    int head   = blockIdx.x % NHEAD;
    int window = blockIdx.x / NHEAD;
    int tid = threadIdx.x;

    const float* base = qkv + (size_t)window * 49 * 576 + head * 32;
    for (int i = tid; i < 49 * 8; i += 128) {
        int nrow = i >> 3, d4 = (i & 7) * 4;
        const float* rp = base + (size_t)nrow * 576 + d4;
        *(float4*)(sq + nrow * 32 + d4) = *(const float4*)(rp);
        *(float4*)(sk + nrow * 32 + d4) = *(const float4*)(rp + 192);
        *(float4*)(sv + nrow * 32 + d4) = *(const float4*)(rp + 384);
    }
    if (tid < 49) {
        int wi = window & 63;
        int wh = wi >> 3, ww = wi & 7;
        int h = wh * 7 + tid / 7;          // shifted-grid coords (mask image)
        int w = ww * 7 + tid % 7;
        int rh = (h < 49) ? 0 : (h < 53 ? 1 : 2);
        int rw = (w < 49) ? 0 : (w < 53 ? 1 : 2);
        sreg[tid] = rh * 3 + rw;
    }
    __syncthreads();

    const float scale = 0.17677669529663687f;  // 1/sqrt(32)
    for (int idx = tid; idx < 2401; idx += 128) {
        int i = idx / 49, j = idx % 49;
        const float* qi = sq + i * 32;
        const float* kj = sk + j * 32;
        float d = 0.f;
#pragma unroll
        for (int t = 0; t < 32; t++) d = fmaf(qi[t], kj[t], d);
        int rel = (i / 7 - j / 7 + 6) * 13 + (i % 7 - j % 7 + 6);
        float bias = bias_table[rel * NHEAD + head];
        float mask = (sreg[i] != sreg[j]) ? -100.0f : 0.0f;
        S[idx] = d * scale + bias + mask;
    }
    __syncthreads();

    if (tid < 49) {
        float* row = S + tid * 49;
        float m = row[0];
        for (int j = 1; j < 49; j++) m = fmaxf(m, row[j]);
        float sum = 0.f;
        for (int j = 0; j < 49; j++) { float e = expf(row[j] - m); row[j] = e; sum += e; }
        float inv = 1.0f / sum;
        for (int j = 0; j < 49; j++) row[j] *= inv;
    }
    __syncthreads();

    for (int idx = tid; idx < 49 * 32; idx += 128) {
        int nrow = idx >> 5, d = idx & 31;
        const float* srow = S + nrow * 49;
        float acc = 0.f;
#pragma unroll 7
        for (int j = 0; j < 49; j++) acc = fmaf(srow[j], sv[j * 32 + d], acc);
        outp[((size_t)window * 49 + nrow) * 192 + head * 32 + d] = acc;
    }
}

// ---------------- tiled SGEMM: C[M,N] = A[M,K] @ W[N,K]^T + bias, fused epilogues ----
#define BM 128
#define BN 64
#define BK 16

enum { EPI_NONE = 0, EPI_PROJ = 1, EPI_GELU = 2, EPI_RES = 3 };

template<int EPI>
__global__ void __launch_bounds__(256)
gemm_kernel(const float* __restrict__ A, const float* __restrict__ W,
            const float* __restrict__ bias, float* __restrict__ Cout,
            int Nn, int K, const float* __restrict__ extra) {
    __shared__ __align__(16) float As[BK][BM + 4];
    __shared__ __align__(16) float Bs[BK][BN + 4];

    const int tid = threadIdx.x;
    const int bm = blockIdx.y * BM;
    const int bn = blockIdx.x * BN;
    const int tx = tid & 15, ty = tid >> 4;

    float acc[8][4];
#pragma unroll
    for (int i = 0; i < 8; i++)
#pragma unroll
        for (int j = 0; j < 4; j++) acc[i][j] = 0.f;

    const int lr = tid >> 2;             // 0..63
    const int lc = (tid & 3) << 2;       // 0,4,8,12
    const float* Ap0 = A + (size_t)(bm + lr) * K + lc;
    const float* Ap1 = A + (size_t)(bm + lr + 64) * K + lc;
    const float* Wp  = W + (size_t)(bn + lr) * K + lc;

    for (int k0 = 0; k0 < K; k0 += BK) {
        float4 a0 = *(const float4*)(Ap0 + k0);
        float4 a1 = *(const float4*)(Ap1 + k0);
        float4 b0 = *(const float4*)(Wp + k0);
        As[lc + 0][lr] = a0.x; As[lc + 1][lr] = a0.y; As[lc + 2][lr] = a0.z; As[lc + 3][lr] = a0.w;
        As[lc + 0][lr + 64] = a1.x; As[lc + 1][lr + 64] = a1.y; As[lc + 2][lr + 64] = a1.z; As[lc + 3][lr + 64] = a1.w;
        Bs[lc + 0][lr] = b0.x; Bs[lc + 1][lr] = b0.y; Bs[lc + 2][lr] = b0.z; Bs[lc + 3][lr] = b0.w;
        __syncthreads();
#pragma unroll
        for (int kk = 0; kk < BK; kk++) {
            float ar[8], br[4];
            *(float4*)(ar)     = *(const float4*)(&As[kk][ty * 8]);
            *(float4*)(ar + 4) = *(const float4*)(&As[kk][ty * 8 + 4]);
            *(float4*)(br)     = *(const float4*)(&Bs[kk][tx * 4]);
#pragma unroll
            for (int i = 0; i < 8; i++)
#pragma unroll
                for (int j = 0; j < 4; j++) acc[i][j] = fmaf(ar[i], br[j], acc[i][j]);
        }
        __syncthreads();
    }

    float4 bv = *(const float4*)(bias + bn + tx * 4);
#pragma unroll
    for (int i = 0; i < 8; i++) {
        int m = bm + ty * 8 + i;
        float4 v;
        v.x = acc[i][0] + bv.x; v.y = acc[i][1] + bv.y;
        v.z = acc[i][2] + bv.z; v.w = acc[i][3] + bv.w;
        if (EPI == EPI_NONE) {
            *(float4*)(Cout + (size_t)m * Nn + bn + tx * 4) = v;
        } else if (EPI == EPI_GELU) {
            v.x = gelu_exact(v.x); v.y = gelu_exact(v.y);
            v.z = gelu_exact(v.z); v.w = gelu_exact(v.w);
            *(float4*)(Cout + (size_t)m * Nn + bn + tx * 4) = v;
        } else if (EPI == EPI_RES) {
            const float4 r = *(const float4*)(extra + (size_t)m * Nn + bn + tx * 4);
            v.x += r.x; v.y += r.y; v.z += r.z; v.w += r.w;
            *(float4*)(Cout + (size_t)m * Nn + bn + tx * 4) = v;
        } else {  // EPI_PROJ: reverse window partition + roll(+3) scatter + shortcut add
            int n = m % 49; int window = m / 49;
            int wi = window & 63, b = window >> 6;
            int wh = wi >> 3, ww = wi & 7;
            int h = wh * 7 + n / 7 + 3; if (h >= 56) h -= 56;
            int w = ww * 7 + n % 7 + 3; if (w >= 56) w -= 56;
            size_t orow = ((size_t)b * 3136 + h * 56 + w) * 192;
            const float4 sc = *(const float4*)(extra + orow + bn + tx * 4);
            v.x += sc.x; v.y += sc.y; v.z += sc.z; v.w += sc.w;
            *(float4*)(Cout + orow + bn + tx * 4) = v;
        }
    }
}

// ---------------- launch ----------------
extern "C" void kernel_launch(void* const* d_in, const int* in_sizes, int n_in,
                              void* d_out, int out_size) {
    const float* x      = (const float*)d_in[0];
    const float* g1     = (const float*)d_in[1];
    const float* b1     = (const float*)d_in[2];
    const float* qkv_w  = (const float*)d_in[3];
    const float* qkv_b  = (const float*)d_in[4];
    const float* proj_w = (const float*)d_in[5];
    const float* proj_b = (const float*)d_in[6];
    const float* bias_t = (const float*)d_in[7];
    const float* g2     = (const float*)d_in[8];
    const float* b2     = (const float*)d_in[9];
    const float* fc1_w  = (const float*)d_in[10];
    const float* fc1_b  = (const float*)d_in[11];
    const float* fc2_w  = (const float*)d_in[12];
    const float* fc2_b  = (const float*)d_in[13];
    float* out = (float*)d_out;

    float *p_xw, *p_qkv, *p_attn, *p_x1, *p_xn2, *p_h1;
    cudaGetSymbolAddress((void**)&p_xw,   g_xw);
    cudaGetSymbolAddress((void**)&p_qkv,  g_qkv);
    cudaGetSymbolAddress((void**)&p_attn, g_attn);
    cudaGetSymbolAddress((void**)&p_x1,   g_x1);
    cudaGetSymbolAddress((void**)&p_xn2,  g_xn2);
    cudaGetSymbolAddress((void**)&p_h1,   g_h1);

    // 1) LN1 + shift + partition
    ln_partition_kernel<<<MROWS / 8, 256>>>(x, g1, b1, p_xw);
    // 2) QKV GEMM  [100352,192] x [576,192]^T
    gemm_kernel<EPI_NONE><<<dim3(576 / BN, MROWS / BM), 256>>>(p_xw, qkv_w, qkv_b, p_qkv, 576, 192, nullptr);
    // 3) windowed attention (rel-pos bias + shift mask + softmax)
    attn_kernel<<<NWTOT * NHEAD, 128>>>(p_qkv, bias_t, p_attn);
    // 4) proj GEMM + reverse/unshift scatter + shortcut residual -> g_x1
    gemm_kernel<EPI_PROJ><<<dim3(192 / BN, MROWS / BM), 256>>>(p_attn, proj_w, proj_b, p_x1, 192, 192, x);
    // 5) LN2
    ln_plain_kernel<<<MROWS / 8, 256>>>(p_x1, g2, b2, p_xn2);
    // 6) fc1 GEMM + exact GELU
    gemm_kernel<EPI_GELU><<<dim3(768 / BN, MROWS / BM), 256>>>(p_xn2, fc1_w, fc1_b, p_h1, 768, 192, nullptr);
    // 7) fc2 GEMM + residual -> d_out
    gemm_kernel<EPI_RES><<<dim3(192 / BN, MROWS / BM), 256>>>(p_h1, fc2_w, fc2_b, out, 192, 768, p_x1);
}

// round 3
// speedup vs baseline: 1.3969x; 1.3969x over previous
#include <cuda_runtime.h>
#include <cuda_bf16.h>
#include <math.h>
#include <stdint.h>

// ---------------- problem constants ----------------
#define C_     192
#define NHEAD  6
#define HID_   768
#define BATCH  32
#define NWTOT  2048
#define MROWS  100352      // NWTOT * 49

// ---------------- scratch (device globals) ----------------
__device__ float          g_qkv [(size_t)MROWS * 3 * C_];   // fp32 QKV
__device__ float          g_x1  [(size_t)MROWS * C_];       // residual stream
__device__ __nv_bfloat16  g_xw_hi [(size_t)MROWS * C_];
__device__ __nv_bfloat16  g_xw_lo [(size_t)MROWS * C_];
__device__ __nv_bfloat16  g_at_hi [(size_t)MROWS * C_];
__device__ __nv_bfloat16  g_at_lo [(size_t)MROWS * C_];
__device__ __nv_bfloat16  g_x2_hi [(size_t)MROWS * C_];
__device__ __nv_bfloat16  g_x2_lo [(size_t)MROWS * C_];
__device__ __nv_bfloat16  g_h1_hi [(size_t)MROWS * HID_];
__device__ __nv_bfloat16  g_h1_lo [(size_t)MROWS * HID_];
// weight hi/lo planes
__device__ __nv_bfloat16  g_wq_hi[576 * 192], g_wq_lo[576 * 192];
__device__ __nv_bfloat16  g_wp_hi[192 * 192], g_wp_lo[192 * 192];
__device__ __nv_bfloat16  g_w1_hi[768 * 192], g_w1_lo[768 * 192];
__device__ __nv_bfloat16  g_w2_hi[192 * 768], g_w2_lo[192 * 768];

// ---------------- helpers ----------------
__device__ __forceinline__ uint32_t smem_u32(const void* p) {
    uint32_t a;
    asm("{ .reg .u64 t; cvta.to.shared.u64 t, %1; cvt.u32.u64 %0, t; }" : "=r"(a) : "l"(p));
    return a;
}
__device__ __forceinline__ float warp_sum(float v) {
#pragma unroll
    for (int o = 16; o; o >>= 1) v += __shfl_xor_sync(0xffffffffu, v, o);
    return v;
}
__device__ __forceinline__ float gelu_exact(float x) {
    return 0.5f * x * (1.0f + erff(x * 0.70710678118654752f));
}
__device__ __forceinline__ void split_hilo(float v, __nv_bfloat16& h, __nv_bfloat16& l) {
    h = __float2bfloat16(v);
    l = __float2bfloat16(v - __bfloat162float(h));
}
__device__ __forceinline__ uint32_t pack_bf2(__nv_bfloat16 a, __nv_bfloat16 b) {
    return ((uint32_t)__bfloat16_as_ushort(b) << 16) | __bfloat16_as_ushort(a);
}

__device__ __forceinline__ void ldmat4(uint32_t* r, uint32_t addr) {
    asm volatile("ldmatrix.sync.aligned.m8n8.x4.shared.b16 {%0,%1,%2,%3}, [%4];"
        : "=r"(r[0]), "=r"(r[1]), "=r"(r[2]), "=r"(r[3]) : "r"(addr));
}
__device__ __forceinline__ void mma16816(float* d, const uint32_t* a, const uint32_t* b) {
    asm volatile("mma.sync.aligned.m16n8k16.row.col.f32.bf16.bf16.f32 "
        "{%0,%1,%2,%3}, {%4,%5,%6,%7}, {%8,%9}, {%0,%1,%2,%3};"
        : "+f"(d[0]), "+f"(d[1]), "+f"(d[2]), "+f"(d[3])
        : "r"(a[0]), "r"(a[1]), "r"(a[2]), "r"(a[3]), "r"(b[0]), "r"(b[1]));
}

// ---------------- weight fp32 -> bf16 hi/lo planes ----------------
__global__ void convert_hilo(const float* __restrict__ src,
                             __nv_bfloat16* __restrict__ hi,
                             __nv_bfloat16* __restrict__ lo, int n) {
    int i = blockIdx.x * blockDim.x + threadIdx.x;
    if (i >= n) return;
    __nv_bfloat16 h, l;
    split_hilo(src[i], h, l);
    hi[i] = h; lo[i] = l;
}

// ---------------- LN1 + shift + partition -> bf16 planes ----------------
__global__ void ln_partition_kernel(const float* __restrict__ x,
                                    const float* __restrict__ g,
                                    const float* __restrict__ bt,
                                    __nv_bfloat16* __restrict__ ohi,
                                    __nv_bfloat16* __restrict__ olo) {
    int warp = (blockIdx.x * blockDim.x + threadIdx.x) >> 5;
    int lane = threadIdx.x & 31;
    if (warp >= MROWS) return;
    int n = warp % 49;
    int window = warp / 49;
    int wi = window & 63;
    int b  = window >> 6;
    int wh = wi >> 3, ww = wi & 7;
    int h = wh * 7 + n / 7 + 3; if (h >= 56) h -= 56;
    int w = ww * 7 + n % 7 + 3; if (w >= 56) w -= 56;
    const float* xi = x + ((size_t)b * 3136 + h * 56 + w) * 192;

    float v[6]; float s1 = 0.f;
#pragma unroll
    for (int j = 0; j < 6; j++) { v[j] = xi[lane + 32 * j]; s1 += v[j]; }
    s1 = warp_sum(s1);
    float mean = s1 * (1.0f / 192.0f);
    float s2 = 0.f;
#pragma unroll
    for (int j = 0; j < 6; j++) { float d = v[j] - mean; s2 += d * d; }
    s2 = warp_sum(s2);
    float inv = rsqrtf(s2 * (1.0f / 192.0f) + 1e-5f);
    size_t base = (size_t)warp * 192;
#pragma unroll
    for (int j = 0; j < 6; j++) {
        int c = lane + 32 * j;
        float val = (v[j] - mean) * inv * g[c] + bt[c];
        __nv_bfloat16 hh, ll; split_hilo(val, hh, ll);
        ohi[base + c] = hh; olo[base + c] = ll;
    }
}

// ---------------- LN2 -> bf16 planes ----------------
__global__ void ln_plain_kernel(const float* __restrict__ x,
                                const float* __restrict__ g,
                                const float* __restrict__ bt,
                                __nv_bfloat16* __restrict__ ohi,
                                __nv_bfloat16* __restrict__ olo) {
    int warp = (blockIdx.x * blockDim.x + threadIdx.x) >> 5;
    int lane = threadIdx.x & 31;
    if (warp >= MROWS) return;
    const float* xi = x + (size_t)warp * 192;
    float v[6]; float s1 = 0.f;
#pragma unroll
    for (int j = 0; j < 6; j++) { v[j] = xi[lane + 32 * j]; s1 += v[j]; }
    s1 = warp_sum(s1);
    float mean = s1 * (1.0f / 192.0f);
    float s2 = 0.f;
#pragma unroll
    for (int j = 0; j < 6; j++) { float d = v[j] - mean; s2 += d * d; }
    s2 = warp_sum(s2);
    float inv = rsqrtf(s2 * (1.0f / 192.0f) + 1e-5f);
    size_t base = (size_t)warp * 192;
#pragma unroll
    for (int j = 0; j < 6; j++) {
        int c = lane + 32 * j;
        float val = (v[j] - mean) * inv * g[c] + bt[c];
        __nv_bfloat16 hh, ll; split_hilo(val, hh, ll);
        ohi[base + c] = hh; olo[base + c] = ll;
    }
}

// ---------------- attention: one block per (window, head) ----------------
__global__ void attn_kernel(const float* __restrict__ qkv,
                            const float* __restrict__ bias_table,
                            __nv_bfloat16* __restrict__ ohi,
                            __nv_bfloat16* __restrict__ olo) {
    __shared__ float sq[49 * 32];
    __shared__ float sk[49 * 32];
    __shared__ float sv[49 * 32];
    __shared__ float S[49 * 49];
    __shared__ int   sreg[49];

    int head   = blockIdx.x % NHEAD;
    int window = blockIdx.x / NHEAD;
    int tid = threadIdx.x;

    const float* base = qkv + (size_t)window * 49 * 576 + head * 32;
    for (int i = tid; i < 49 * 8; i += 128) {
        int nrow = i >> 3, d4 = (i & 7) * 4;
        const float* rp = base + (size_t)nrow * 576 + d4;
        *(float4*)(sq + nrow * 32 + d4) = *(const float4*)(rp);
        *(float4*)(sk + nrow * 32 + d4) = *(const float4*)(rp + 192);
        *(float4*)(sv + nrow * 32 + d4) = *(const float4*)(rp + 384);
    }
    if (tid < 49) {
        int wi = window & 63;
        int wh = wi >> 3, ww = wi & 7;
        int h = wh * 7 + tid / 7;
        int w = ww * 7 + tid % 7;
        int rh = (h < 49) ? 0 : (h < 53 ? 1 : 2);
        int rw = (w < 49) ? 0 : (w < 53 ? 1 : 2);
        sreg[tid] = rh * 3 + rw;
    }
    __syncthreads();

    const float scale = 0.17677669529663687f;
    for (int idx = tid; idx < 2401; idx += 128) {
        int i = idx / 49, j = idx % 49;
        const float* qi = sq + i * 32;
        const float* kj = sk + j * 32;
        float d = 0.f;
#pragma unroll
        for (int t = 0; t < 32; t++) d = fmaf(qi[t], kj[t], d);
        int rel = (i / 7 - j / 7 + 6) * 13 + (i % 7 - j % 7 + 6);
        float bias = bias_table[rel * NHEAD + head];
        float mask = (sreg[i] != sreg[j]) ? -100.0f : 0.0f;
        S[idx] = d * scale + bias + mask;
    }
    __syncthreads();

    if (tid < 49) {
        float* row = S + tid * 49;
        float m = row[0];
        for (int j = 1; j < 49; j++) m = fmaxf(m, row[j]);
        float sum = 0.f;
        for (int j = 0; j < 49; j++) { float e = expf(row[j] - m); row[j] = e; sum += e; }
        float inv = 1.0f / sum;
        for (int j = 0; j < 49; j++) row[j] *= inv;
    }
    __syncthreads();

    for (int idx = tid; idx < 49 * 32; idx += 128) {
        int nrow = idx >> 5, d = idx & 31;
        const float* srow = S + nrow * 49;
        float acc = 0.f;
#pragma unroll 7
        for (int j = 0; j < 49; j++) acc = fmaf(srow[j], sv[j * 32 + d], acc);
        size_t oi = ((size_t)window * 49 + nrow) * 192 + head * 32 + d;
        __nv_bfloat16 hh, ll; split_hilo(acc, hh, ll);
        ohi[oi] = hh; olo[oi] = ll;
    }
}

// ---------------- bf16 hi/lo mma GEMM ----------------
// C[128,64-tile] = A[128,K] @ W[64,K]^T via 3 bf16 passes (hi*hi + hi*lo + lo*hi)
// smem: padded 80B rows (32 bf16 data + 16B pad) -> conflict-free ldmatrix
#define SA_HI 0
#define SA_LO 10240
#define SB_HI 20480
#define SB_LO 25600
#define SM_TOT 30720

enum { EPI_NONE = 0, EPI_PROJ = 1, EPI_GELU = 2, EPI_RES = 3 };

__device__ __forceinline__ size_t proj_row(int m) {
    int n = m % 49, window = m / 49;
    int wi = window & 63, b = window >> 6;
    int wh = wi >> 3, ww = wi & 7;
    int hh = wh * 7 + n / 7 + 3; if (hh >= 56) hh -= 56;
    int wc = ww * 7 + n % 7 + 3; if (wc >= 56) wc -= 56;
    return ((size_t)b * 3136 + (size_t)hh * 56 + wc) * 192;
}

template<int EPI>
__global__ void __launch_bounds__(256)
gemm_mma(const __nv_bfloat16* __restrict__ Ahi, const __nv_bfloat16* __restrict__ Alo,
         const __nv_bfloat16* __restrict__ Whi, const __nv_bfloat16* __restrict__ Wlo,
         const float* __restrict__ bias, float* __restrict__ Cout,
         int Nn, int Ktot, const float* __restrict__ extra,
         __nv_bfloat16* __restrict__ ohi, __nv_bfloat16* __restrict__ olo) {
    __shared__ __align__(16) char sm[SM_TOT];
    const uint32_t sb = smem_u32(sm);
    const int tid  = threadIdx.x;
    const int wid  = tid >> 5;
    const int lane = tid & 31;
    const int warpM = wid >> 1;            // 0..3
    const int warpN = wid & 1;             // 0..1
    const int bm = blockIdx.y * 128;
    const int bn = blockIdx.x * 64;

    const __nv_bfloat16* Ahi_b = Ahi + (size_t)bm * Ktot;
    const __nv_bfloat16* Alo_b = Alo + (size_t)bm * Ktot;
    const __nv_bfloat16* Whi_b = Whi + (size_t)bn * Ktot;
    const __nv_bfloat16* Wlo_b = Wlo + (size_t)bn * Ktot;

    float acc[2][4][4];
#pragma unroll
    for (int i = 0; i < 2; i++)
#pragma unroll
        for (int j = 0; j < 4; j++)
#pragma unroll
            for (int k = 0; k < 4; k++) acc[i][j][k] = 0.f;

    // ldmatrix source addresses (within smem tiles)
    const uint32_t a_off = (uint32_t)(warpM * 32 + (lane & 15)) * 80 + ((lane >> 4) * 16);
    const uint32_t b_off = (uint32_t)(warpN * 32 + ((lane >> 4) & 1) * 8 + (lane & 7)) * 80
                         + (((lane >> 3) & 1) * 16);
    const uint32_t aaddr_hi = sb + SA_HI + a_off;
    const uint32_t aaddr_lo = sb + SA_LO + a_off;
    const uint32_t baddr_hi = sb + SB_HI + b_off;
    const uint32_t baddr_lo = sb + SB_LO + b_off;

    for (int k0 = 0; k0 < Ktot; k0 += 32) {
        // stage A (128x32) hi+lo, B (64x32) hi+lo
#pragma unroll
        for (int it = 0; it < 2; it++) {
            int c = tid + it * 256;
            int row = c >> 2, q = c & 3;
            const size_t goff = (size_t)row * Ktot + k0 + q * 8;
            *(uint4*)(sm + SA_HI + row * 80 + q * 16) = *(const uint4*)(Ahi_b + goff);
            *(uint4*)(sm + SA_LO + row * 80 + q * 16) = *(const uint4*)(Alo_b + goff);
        }
        {
            int row = tid >> 2, q = tid & 3;
            const size_t goff = (size_t)row * Ktot + k0 + q * 8;
            *(uint4*)(sm + SB_HI + row * 80 + q * 16) = *(const uint4*)(Whi_b + goff);
            *(uint4*)(sm + SB_LO + row * 80 + q * 16) = *(const uint4*)(Wlo_b + goff);
        }
        __syncthreads();

#pragma unroll
        for (int ki = 0; ki < 2; ki++) {
            uint32_t ah0[4], ah1[4], al0[4], al1[4];
            ldmat4(ah0, aaddr_hi + ki * 32);
            ldmat4(ah1, aaddr_hi + 16 * 80 + ki * 32);
            ldmat4(al0, aaddr_lo + ki * 32);
            ldmat4(al1, aaddr_lo + 16 * 80 + ki * 32);
#pragma unroll
            for (int ng = 0; ng < 2; ng++) {
                uint32_t bh[4], bl[4];
                ldmat4(bh, baddr_hi + ng * 16 * 80 + ki * 32);
                ldmat4(bl, baddr_lo + ng * 16 * 80 + ki * 32);
#pragma unroll
                for (int q = 0; q < 2; q++) {
                    int ni = ng * 2 + q;
                    mma16816(acc[0][ni], ah0, bh + 2 * q);
                    mma16816(acc[0][ni], ah0, bl + 2 * q);
                    mma16816(acc[0][ni], al0, bh + 2 * q);
                    mma16816(acc[1][ni], ah1, bh + 2 * q);
                    mma16816(acc[1][ni], ah1, bl + 2 * q);
                    mma16816(acc[1][ni], al1, bh + 2 * q);
                }
            }
        }
        __syncthreads();
    }

    // ---------------- epilogue ----------------
    const int lrow = lane >> 2, lcol = (lane & 3) * 2;
#pragma unroll
    for (int mi = 0; mi < 2; mi++) {
        int m0 = bm + warpM * 32 + mi * 16 + lrow;
        int m1 = m0 + 8;
        size_t r0, r1;
        if (EPI == EPI_PROJ) { r0 = proj_row(m0); r1 = proj_row(m1); }
        else { r0 = (size_t)m0 * Nn; r1 = (size_t)m1 * Nn; }
#pragma unroll
        for (int ni = 0; ni < 4; ni++) {
            int n = bn + warpN * 32 + ni * 8 + lcol;
            float bx = bias[n], by = bias[n + 1];
            float v0x = acc[mi][ni][0] + bx, v0y = acc[mi][ni][1] + by;
            float v1x = acc[mi][ni][2] + bx, v1y = acc[mi][ni][3] + by;
            if (EPI == EPI_NONE) {
                *(float2*)(Cout + r0 + n) = make_float2(v0x, v0y);
                *(float2*)(Cout + r1 + n) = make_float2(v1x, v1y);
            } else if (EPI == EPI_GELU) {
                v0x = gelu_exact(v0x); v0y = gelu_exact(v0y);
                v1x = gelu_exact(v1x); v1y = gelu_exact(v1y);
                __nv_bfloat16 hx, lx, hy, ly;
                split_hilo(v0x, hx, lx); split_hilo(v0y, hy, ly);
                *(uint32_t*)(ohi + r0 + n) = pack_bf2(hx, hy);
                *(uint32_t*)(olo + r0 + n) = pack_bf2(lx, ly);
                split_hilo(v1x, hx, lx); split_hilo(v1y, hy, ly);
                *(uint32_t*)(ohi + r1 + n) = pack_bf2(hx, hy);
                *(uint32_t*)(olo + r1 + n) = pack_bf2(lx, ly);
            } else if (EPI == EPI_RES) {
                float2 e0 = *(const float2*)(extra + r0 + n);
                float2 e1 = *(const float2*)(extra + r1 + n);
                *(float2*)(Cout + r0 + n) = make_float2(v0x + e0.x, v0y + e0.y);
                *(float2*)(Cout + r1 + n) = make_float2(v1x + e1.x, v1y + e1.y);
            } else {  // EPI_PROJ: scatter + shortcut residual
                float2 e0 = *(const float2*)(extra + r0 + n);
                float2 e1 = *(const float2*)(extra + r1 + n);
                *(float2*)(Cout + r0 + n) = make_float2(v0x + e0.x, v0y + e0.y);
                *(float2*)(Cout + r1 + n) = make_float2(v1x + e1.x, v1y + e1.y);
            }
        }
    }
}

// ---------------- launch ----------------
extern "C" void kernel_launch(void* const* d_in, const int* in_sizes, int n_in,
                              void* d_out, int out_size) {
    const float* x      = (const float*)d_in[0];
    const float* g1     = (const float*)d_in[1];
    const float* b1     = (const float*)d_in[2];
    const float* qkv_w  = (const float*)d_in[3];
    const float* qkv_b  = (const float*)d_in[4];
    const float* proj_w = (const float*)d_in[5];
    const float* proj_b = (const float*)d_in[6];
    const float* bias_t = (const float*)d_in[7];
    const float* g2     = (const float*)d_in[8];
    const float* b2     = (const float*)d_in[9];
    const float* fc1_w  = (const float*)d_in[10];
    const float* fc1_b  = (const float*)d_in[11];
    const float* fc2_w  = (const float*)d_in[12];
    const float* fc2_b  = (const float*)d_in[13];
    float* out = (float*)d_out;

    float *p_qkv, *p_x1;
    __nv_bfloat16 *p_xw_hi, *p_xw_lo, *p_at_hi, *p_at_lo, *p_x2_hi, *p_x2_lo, *p_h1_hi, *p_h1_lo;
    __nv_bfloat16 *p_wq_hi, *p_wq_lo, *p_wp_hi, *p_wp_lo, *p_w1_hi, *p_w1_lo, *p_w2_hi, *p_w2_lo;
    cudaGetSymbolAddress((void**)&p_qkv,   g_qkv);
    cudaGetSymbolAddress((void**)&p_x1,    g_x1);
    cudaGetSymbolAddress((void**)&p_xw_hi, g_xw_hi);
    cudaGetSymbolAddress((void**)&p_xw_lo, g_xw_lo);
    cudaGetSymbolAddress((void**)&p_at_hi, g_at_hi);
    cudaGetSymbolAddress((void**)&p_at_lo, g_at_lo);
    cudaGetSymbolAddress((void**)&p_x2_hi, g_x2_hi);
    cudaGetSymbolAddress((void**)&p_x2_lo, g_x2_lo);
    cudaGetSymbolAddress((void**)&p_h1_hi, g_h1_hi);
    cudaGetSymbolAddress((void**)&p_h1_lo, g_h1_lo);
    cudaGetSymbolAddress((void**)&p_wq_hi, g_wq_hi);
    cudaGetSymbolAddress((void**)&p_wq_lo, g_wq_lo);
    cudaGetSymbolAddress((void**)&p_wp_hi, g_wp_hi);
    cudaGetSymbolAddress((void**)&p_wp_lo, g_wp_lo);
    cudaGetSymbolAddress((void**)&p_w1_hi, g_w1_hi);
    cudaGetSymbolAddress((void**)&p_w1_lo, g_w1_lo);
    cudaGetSymbolAddress((void**)&p_w2_hi, g_w2_hi);
    cudaGetSymbolAddress((void**)&p_w2_lo, g_w2_lo);

    // weight conversions (small)
    convert_hilo<<<(576 * 192 + 255) / 256, 256>>>(qkv_w, p_wq_hi, p_wq_lo, 576 * 192);
    convert_hilo<<<(192 * 192 + 255) / 256, 256>>>(proj_w, p_wp_hi, p_wp_lo, 192 * 192);
    convert_hilo<<<(768 * 192 + 255) / 256, 256>>>(fc1_w, p_w1_hi, p_w1_lo, 768 * 192);
    convert_hilo<<<(192 * 768 + 255) / 256, 256>>>(fc2_w, p_w2_hi, p_w2_lo, 192 * 768);

    const int MB = MROWS / 128;  // 784

    // 1) LN1 + shift + partition -> bf16 planes
    ln_partition_kernel<<<MROWS / 8, 256>>>(x, g1, b1, p_xw_hi, p_xw_lo);
    // 2) QKV GEMM -> fp32
    gemm_mma<EPI_NONE><<<dim3(576 / 64, MB), 256>>>(p_xw_hi, p_xw_lo, p_wq_hi, p_wq_lo,
                                                    qkv_b, p_qkv, 576, 192, nullptr, nullptr, nullptr);
    // 3) attention -> bf16 planes
    attn_kernel<<<NWTOT * NHEAD, 128>>>(p_qkv, bias_t, p_at_hi, p_at_lo);
    // 4) proj GEMM + scatter + residual -> fp32 x1
    gemm_mma<EPI_PROJ><<<dim3(192 / 64, MB), 256>>>(p_at_hi, p_at_lo, p_wp_hi, p_wp_lo,
                                                    proj_b, p_x1, 192, 192, x, nullptr, nullptr);
    // 5) LN2 -> bf16 planes
    ln_plain_kernel<<<MROWS / 8, 256>>>(p_x1, g2, b2, p_x2_hi, p_x2_lo);
    // 6) fc1 GEMM + GELU -> bf16 planes
    gemm_mma<EPI_GELU><<<dim3(768 / 64, MB), 256>>>(p_x2_hi, p_x2_lo, p_w1_hi, p_w1_lo,
                                                    fc1_b, nullptr, 768, 192, nullptr, p_h1_hi, p_h1_lo);
    // 7) fc2 GEMM + residual -> out
    gemm_mma<EPI_RES><<<dim3(192 / 64, MB), 256>>>(p_h1_hi, p_h1_lo, p_w2_hi, p_w2_lo,
                                                   fc2_b, out, 192, 768, p_x1, nullptr, nullptr);
}

// round 4
// speedup vs baseline: 1.4258x; 1.0207x over previous
#include <cuda_runtime.h>
#include <cuda_bf16.h>
#include <math.h>
#include <stdint.h>

// ---------------- problem constants ----------------
#define C_     192
#define NHEAD  6
#define HID_   768
#define BATCH  32
#define NWTOT  2048
#define MROWS  100352      // NWTOT * 49

// ---------------- scratch (device globals) ----------------
__device__ float          g_qkv [(size_t)MROWS * 3 * C_];
__device__ float          g_x1  [(size_t)MROWS * C_];
__device__ __nv_bfloat16  g_xw_hi [(size_t)MROWS * C_];
__device__ __nv_bfloat16  g_xw_lo [(size_t)MROWS * C_];
__device__ __nv_bfloat16  g_at_hi [(size_t)MROWS * C_];
__device__ __nv_bfloat16  g_at_lo [(size_t)MROWS * C_];
__device__ __nv_bfloat16  g_x2_hi [(size_t)MROWS * C_];
__device__ __nv_bfloat16  g_x2_lo [(size_t)MROWS * C_];
__device__ __nv_bfloat16  g_h1_hi [(size_t)MROWS * HID_];
__device__ __nv_bfloat16  g_h1_lo [(size_t)MROWS * HID_];
__device__ __nv_bfloat16  g_wq_hi[576 * 192], g_wq_lo[576 * 192];
__device__ __nv_bfloat16  g_wp_hi[192 * 192], g_wp_lo[192 * 192];
__device__ __nv_bfloat16  g_w1_hi[768 * 192], g_w1_lo[768 * 192];
__device__ __nv_bfloat16  g_w2_hi[192 * 768], g_w2_lo[192 * 768];

// ---------------- helpers ----------------
__device__ __forceinline__ uint32_t smem_u32(const void* p) {
    uint32_t a;
    asm("{ .reg .u64 t; cvta.to.shared.u64 t, %1; cvt.u32.u64 %0, t; }" : "=r"(a) : "l"(p));
    return a;
}
__device__ __forceinline__ float warp_sum(float v) {
#pragma unroll
    for (int o = 16; o; o >>= 1) v += __shfl_xor_sync(0xffffffffu, v, o);
    return v;
}
__device__ __forceinline__ float warp_max(float v) {
#pragma unroll
    for (int o = 16; o; o >>= 1) v = fmaxf(v, __shfl_xor_sync(0xffffffffu, v, o));
    return v;
}
__device__ __forceinline__ float gelu_exact(float x) {
    return 0.5f * x * (1.0f + erff(x * 0.70710678118654752f));
}
__device__ __forceinline__ void split_hilo(float v, __nv_bfloat16& h, __nv_bfloat16& l) {
    h = __float2bfloat16(v);
    l = __float2bfloat16(v - __bfloat162float(h));
}
__device__ __forceinline__ uint32_t pack_bf2(__nv_bfloat16 a, __nv_bfloat16 b) {
    return ((uint32_t)__bfloat16_as_ushort(b) << 16) | __bfloat16_as_ushort(a);
}
// FMA-only exp (exp2 poly); inputs <= 0 in softmax use
__device__ __forceinline__ float fast_exp(float x) {
    float t = fmaxf(x * 1.4426950408889634f, -126.0f);
    float n = floorf(t);
    float f = t - n;
    float p = 1.8775767e-3f;
    p = fmaf(p, f, 8.9893397e-3f);
    p = fmaf(p, f, 5.5804084e-2f);
    p = fmaf(p, f, 2.4013971e-1f);
    p = fmaf(p, f, 6.9314718e-1f);
    p = fmaf(p, f, 1.0f);
    return p * __int_as_float(((int)n + 127) << 23);
}

__device__ __forceinline__ void ldmat4(uint32_t* r, uint32_t addr) {
    asm volatile("ldmatrix.sync.aligned.m8n8.x4.shared.b16 {%0,%1,%2,%3}, [%4];"
        : "=r"(r[0]), "=r"(r[1]), "=r"(r[2]), "=r"(r[3]) : "r"(addr));
}
__device__ __forceinline__ void mma16816(float* d, const uint32_t* a, const uint32_t* b) {
    asm volatile("mma.sync.aligned.m16n8k16.row.col.f32.bf16.bf16.f32 "
        "{%0,%1,%2,%3}, {%4,%5,%6,%7}, {%8,%9}, {%0,%1,%2,%3};"
        : "+f"(d[0]), "+f"(d[1]), "+f"(d[2]), "+f"(d[3])
        : "r"(a[0]), "r"(a[1]), "r"(a[2]), "r"(a[3]), "r"(b[0]), "r"(b[1]));
}
#define CP16(dst, src) \
    asm volatile("cp.async.cg.shared.global [%0], [%1], 16;" :: "r"(dst), "l"(src))
#define CP_COMMIT() asm volatile("cp.async.commit_group;" ::: "memory")
#define CP_WAIT(n)  asm volatile("cp.async.wait_group %0;" :: "n"(n) : "memory")

// ---------------- weight fp32 -> bf16 hi/lo planes ----------------
__global__ void convert_hilo(const float* __restrict__ src,
                             __nv_bfloat16* __restrict__ hi,
                             __nv_bfloat16* __restrict__ lo, int n) {
    int i = blockIdx.x * blockDim.x + threadIdx.x;
    if (i >= n) return;
    __nv_bfloat16 h, l;
    split_hilo(src[i], h, l);
    hi[i] = h; lo[i] = l;
}

// ---------------- LN1 + shift + partition -> bf16 planes ----------------
__global__ void ln_partition_kernel(const float* __restrict__ x,
                                    const float* __restrict__ g,
                                    const float* __restrict__ bt,
                                    __nv_bfloat16* __restrict__ ohi,
                                    __nv_bfloat16* __restrict__ olo) {
    int warp = (blockIdx.x * blockDim.x + threadIdx.x) >> 5;
    int lane = threadIdx.x & 31;
    if (warp >= MROWS) return;
    int n = warp % 49;
    int window = warp / 49;
    int wi = window & 63;
    int b  = window >> 6;
    int wh = wi >> 3, ww = wi & 7;
    int h = wh * 7 + n / 7 + 3; if (h >= 56) h -= 56;
    int w = ww * 7 + n % 7 + 3; if (w >= 56) w -= 56;
    const float* xi = x + ((size_t)b * 3136 + h * 56 + w) * 192;

    float v[6]; float s1 = 0.f;
#pragma unroll
    for (int j = 0; j < 6; j++) { v[j] = xi[lane + 32 * j]; s1 += v[j]; }
    s1 = warp_sum(s1);
    float mean = s1 * (1.0f / 192.0f);
    float s2 = 0.f;
#pragma unroll
    for (int j = 0; j < 6; j++) { float d = v[j] - mean; s2 += d * d; }
    s2 = warp_sum(s2);
    float inv = rsqrtf(s2 * (1.0f / 192.0f) + 1e-5f);
    size_t base = (size_t)warp * 192;
#pragma unroll
    for (int j = 0; j < 6; j++) {
        int c = lane + 32 * j;
        float val = (v[j] - mean) * inv * g[c] + bt[c];
        __nv_bfloat16 hh, ll; split_hilo(val, hh, ll);
        ohi[base + c] = hh; olo[base + c] = ll;
    }
}

// ---------------- LN2 -> bf16 planes ----------------
__global__ void ln_plain_kernel(const float* __restrict__ x,
                                const float* __restrict__ g,
                                const float* __restrict__ bt,
                                __nv_bfloat16* __restrict__ ohi,
                                __nv_bfloat16* __restrict__ olo) {
    int warp = (blockIdx.x * blockDim.x + threadIdx.x) >> 5;
    int lane = threadIdx.x & 31;
    if (warp >= MROWS) return;
    const float* xi = x + (size_t)warp * 192;
    float v[6]; float s1 = 0.f;
#pragma unroll
    for (int j = 0; j < 6; j++) { v[j] = xi[lane + 32 * j]; s1 += v[j]; }
    s1 = warp_sum(s1);
    float mean = s1 * (1.0f / 192.0f);
    float s2 = 0.f;
#pragma unroll
    for (int j = 0; j < 6; j++) { float d = v[j] - mean; s2 += d * d; }
    s2 = warp_sum(s2);
    float inv = rsqrtf(s2 * (1.0f / 192.0f) + 1e-5f);
    size_t base = (size_t)warp * 192;
#pragma unroll
    for (int j = 0; j < 6; j++) {
        int c = lane + 32 * j;
        float val = (v[j] - mean) * inv * g[c] + bt[c];
        __nv_bfloat16 hh, ll; split_hilo(val, hh, ll);
        ohi[base + c] = hh; olo[base + c] = ll;
    }
}

// ---------------- attention: one block per (window, head) ----------------
__global__ void attn_kernel(const float* __restrict__ qkv,
                            const float* __restrict__ bias_table,
                            __nv_bfloat16* __restrict__ ohi,
                            __nv_bfloat16* __restrict__ olo) {
    __shared__ float sq[49 * 32];
    __shared__ float sk[49 * 32];
    __shared__ float sv[49 * 32];
    __shared__ float S[49 * 49];
    __shared__ int   sreg[49];

    int head   = blockIdx.x % NHEAD;
    int window = blockIdx.x / NHEAD;
    int tid = threadIdx.x;
    int wrp = tid >> 5, ln = tid & 31;

    const float* base = qkv + (size_t)window * 49 * 576 + head * 32;
    for (int i = tid; i < 49 * 8; i += 128) {
        int nrow = i >> 3, d4 = (i & 7) * 4;
        const float* rp = base + (size_t)nrow * 576 + d4;
        *(float4*)(sq + nrow * 32 + d4) = *(const float4*)(rp);
        *(float4*)(sk + nrow * 32 + d4) = *(const float4*)(rp + 192);
        *(float4*)(sv + nrow * 32 + d4) = *(const float4*)(rp + 384);
    }
    if (tid < 49) {
        int wi = window & 63;
        int wh = wi >> 3, ww = wi & 7;
        int h = wh * 7 + tid / 7;
        int w = ww * 7 + tid % 7;
        int rh = (h < 49) ? 0 : (h < 53 ? 1 : 2);
        int rw = (w < 49) ? 0 : (w < 53 ? 1 : 2);
        sreg[tid] = rh * 3 + rw;
    }
    __syncthreads();

    const float scale = 0.17677669529663687f;
    for (int idx = tid; idx < 2401; idx += 128) {
        int i = idx / 49, j = idx % 49;
        const float* qi = sq + i * 32;
        const float* kj = sk + j * 32;
        float d = 0.f;
#pragma unroll
        for (int t = 0; t < 32; t++) d = fmaf(qi[t], kj[t], d);
        int rel = (i / 7 - j / 7 + 6) * 13 + (i % 7 - j % 7 + 6);
        float bias = bias_table[rel * NHEAD + head];
        float mask = (sreg[i] != sreg[j]) ? -100.0f : 0.0f;
        S[idx] = d * scale + bias + mask;
    }
    __syncthreads();

    // warp-parallel softmax: one warp per row, FMA-only exp
    for (int r = wrp; r < 49; r += 4) {
        float* row = S + r * 49;
        float v0 = row[ln];
        bool has1 = (ln + 32) < 49;
        float v1 = has1 ? row[ln + 32] : -1e30f;
        float m = warp_max(fmaxf(v0, v1));
        float e0 = fast_exp(v0 - m);
        float e1 = has1 ? fast_exp(v1 - m) : 0.f;
        float s = warp_sum(e0 + e1);
        float inv = __frcp_rn(s);
        row[ln] = e0 * inv;
        if (has1) row[ln + 32] = e1 * inv;
    }
    __syncthreads();

    for (int idx = tid; idx < 49 * 32; idx += 128) {
        int nrow = idx >> 5, d = idx & 31;
        const float* srow = S + nrow * 49;
        float acc = 0.f;
#pragma unroll 7
        for (int j = 0; j < 49; j++) acc = fmaf(srow[j], sv[j * 32 + d], acc);
        size_t oi = ((size_t)window * 49 + nrow) * 192 + head * 32 + d;
        __nv_bfloat16 hh, ll; split_hilo(acc, hh, ll);
        ohi[oi] = hh; olo[oi] = ll;
    }
}

// ---------------- bf16 hi/lo mma GEMM, cp.async double-buffered ----------------
// per-stage smem: A(hi,lo) 128x(32bf16+pad)=2x10240, B(hi,lo) 64x(...)=2x5120
#define SA_HI 0
#define SA_LO 10240
#define SB_HI 20480
#define SB_LO 25600
#define STAGE 30720
#define SM_TOT (2 * STAGE)

enum { EPI_NONE = 0, EPI_PROJ = 1, EPI_GELU = 2, EPI_RES = 3 };

__device__ __forceinline__ size_t proj_row(int m) {
    int n = m % 49, window = m / 49;
    int wi = window & 63, b = window >> 6;
    int wh = wi >> 3, ww = wi & 7;
    int hh = wh * 7 + n / 7 + 3; if (hh >= 56) hh -= 56;
    int wc = ww * 7 + n % 7 + 3; if (wc >= 56) wc -= 56;
    return ((size_t)b * 3136 + (size_t)hh * 56 + wc) * 192;
}

template<int EPI>
__global__ void __launch_bounds__(256, 2)
gemm_mma(const __nv_bfloat16* __restrict__ Ahi, const __nv_bfloat16* __restrict__ Alo,
         const __nv_bfloat16* __restrict__ Whi, const __nv_bfloat16* __restrict__ Wlo,
         const float* __restrict__ bias, float* __restrict__ Cout,
         int Nn, int Ktot, const float* __restrict__ extra,
         __nv_bfloat16* __restrict__ ohi, __nv_bfloat16* __restrict__ olo) {
    extern __shared__ __align__(16) char sm[];
    const uint32_t sb = smem_u32(sm);
    const int tid  = threadIdx.x;
    const int wid  = tid >> 5;
    const int lane = tid & 31;
    const int warpM = wid >> 1;
    const int warpN = wid & 1;
    const int bm = blockIdx.y * 128;
    const int bn = blockIdx.x * 64;

    const __nv_bfloat16* Ahi_b = Ahi + (size_t)bm * Ktot;
    const __nv_bfloat16* Alo_b = Alo + (size_t)bm * Ktot;
    const __nv_bfloat16* Whi_b = Whi + (size_t)bn * Ktot;
    const __nv_bfloat16* Wlo_b = Wlo + (size_t)bn * Ktot;

    // staging indices
    const int arow0 = tid >> 2;          // 0..63
    const int arow1 = arow0 + 64;
    const int aq = (tid & 3) * 16;       // byte offset in 64B row-data
    const int brow = tid >> 2;
    // ldmatrix offsets
    const uint32_t a_off = (uint32_t)(warpM * 32 + (lane & 15)) * 80 + ((lane >> 4) * 16);
    const uint32_t b_off = (uint32_t)(warpN * 32 + ((lane >> 4) & 1) * 8 + (lane & 7)) * 80
                         + (((lane >> 3) & 1) * 16);

    float acc[2][4][4];
#pragma unroll
    for (int i = 0; i < 2; i++)
#pragma unroll
        for (int j = 0; j < 4; j++)
#pragma unroll
            for (int k = 0; k < 4; k++) acc[i][j][k] = 0.f;

    const int NK = Ktot >> 5;

    // stage loader
    auto stage_load = [&](int s, int k0) {
        uint32_t d = sb + s * STAGE;
        size_t ga = (size_t)arow0 * Ktot + k0;
        size_t gb = (size_t)arow1 * Ktot + k0;
        size_t gw = (size_t)brow * Ktot + k0;
        int aqe = aq >> 1;  // element offset (bf16)
        CP16(d + SA_HI + arow0 * 80 + aq, Ahi_b + ga + aqe);
        CP16(d + SA_HI + arow1 * 80 + aq, Ahi_b + gb + aqe);
        CP16(d + SA_LO + arow0 * 80 + aq, Alo_b + ga + aqe);
        CP16(d + SA_LO + arow1 * 80 + aq, Alo_b + gb + aqe);
        CP16(d + SB_HI + brow * 80 + aq, Whi_b + gw + aqe);
        CP16(d + SB_LO + brow * 80 + aq, Wlo_b + gw + aqe);
        CP_COMMIT();
    };

    stage_load(0, 0);

    for (int k = 0; k < NK; k++) {
        if (k + 1 < NK) {
            stage_load((k + 1) & 1, (k + 1) << 5);
            CP_WAIT(1);
        } else {
            CP_WAIT(0);
        }
        __syncthreads();

        const uint32_t soff = sb + (k & 1) * STAGE;
        const uint32_t aaddr_hi = soff + SA_HI + a_off;
        const uint32_t aaddr_lo = soff + SA_LO + a_off;
        const uint32_t baddr_hi = soff + SB_HI + b_off;
        const uint32_t baddr_lo = soff + SB_LO + b_off;

#pragma unroll
        for (int ki = 0; ki < 2; ki++) {
            uint32_t ah0[4], ah1[4], al0[4], al1[4];
            ldmat4(ah0, aaddr_hi + ki * 32);
            ldmat4(ah1, aaddr_hi + 16 * 80 + ki * 32);
            ldmat4(al0, aaddr_lo + ki * 32);
            ldmat4(al1, aaddr_lo + 16 * 80 + ki * 32);
#pragma unroll
            for (int ng = 0; ng < 2; ng++) {
                uint32_t bh[4], bl[4];
                ldmat4(bh, baddr_hi + ng * 16 * 80 + ki * 32);
                ldmat4(bl, baddr_lo + ng * 16 * 80 + ki * 32);
#pragma unroll
                for (int q = 0; q < 2; q++) {
                    int ni = ng * 2 + q;
                    mma16816(acc[0][ni], ah0, bh + 2 * q);
                    mma16816(acc[0][ni], ah0, bl + 2 * q);
                    mma16816(acc[0][ni], al0, bh + 2 * q);
                    mma16816(acc[1][ni], ah1, bh + 2 * q);
                    mma16816(acc[1][ni], ah1, bl + 2 * q);
                    mma16816(acc[1][ni], al1, bh + 2 * q);
                }
            }
        }
        __syncthreads();
    }

    // ---------------- epilogue ----------------
    const int lrow = lane >> 2, lcol = (lane & 3) * 2;
#pragma unroll
    for (int mi = 0; mi < 2; mi++) {
        int m0 = bm + warpM * 32 + mi * 16 + lrow;
        int m1 = m0 + 8;
        size_t r0, r1;
        if (EPI == EPI_PROJ) { r0 = proj_row(m0); r1 = proj_row(m1); }
        else { r0 = (size_t)m0 * Nn; r1 = (size_t)m1 * Nn; }
#pragma unroll
        for (int ni = 0; ni < 4; ni++) {
            int n = bn + warpN * 32 + ni * 8 + lcol;
            float bx = bias[n], by = bias[n + 1];
            float v0x = acc[mi][ni][0] + bx, v0y = acc[mi][ni][1] + by;
            float v1x = acc[mi][ni][2] + bx, v1y = acc[mi][ni][3] + by;
            if (EPI == EPI_NONE) {
                *(float2*)(Cout + r0 + n) = make_float2(v0x, v0y);
                *(float2*)(Cout + r1 + n) = make_float2(v1x, v1y);
            } else if (EPI == EPI_GELU) {
                v0x = gelu_exact(v0x); v0y = gelu_exact(v0y);
                v1x = gelu_exact(v1x); v1y = gelu_exact(v1y);
                __nv_bfloat16 hx, lx, hy, ly;
                split_hilo(v0x, hx, lx); split_hilo(v0y, hy, ly);
                *(uint32_t*)(ohi + r0 + n) = pack_bf2(hx, hy);
                *(uint32_t*)(olo + r0 + n) = pack_bf2(lx, ly);
                split_hilo(v1x, hx, lx); split_hilo(v1y, hy, ly);
                *(uint32_t*)(ohi + r1 + n) = pack_bf2(hx, hy);
                *(uint32_t*)(olo + r1 + n) = pack_bf2(lx, ly);
            } else {
                float2 e0 = *(const float2*)(extra + r0 + n);
                float2 e1 = *(const float2*)(extra + r1 + n);
                *(float2*)(Cout + r0 + n) = make_float2(v0x + e0.x, v0y + e0.y);
                *(float2*)(Cout + r1 + n) = make_float2(v1x + e1.x, v1y + e1.y);
            }
        }
    }
}

// ---------------- launch ----------------
extern "C" void kernel_launch(void* const* d_in, const int* in_sizes, int n_in,
                              void* d_out, int out_size) {
    const float* x      = (const float*)d_in[0];
    const float* g1     = (const float*)d_in[1];
    const float* b1     = (const float*)d_in[2];
    const float* qkv_w  = (const float*)d_in[3];
    const float* qkv_b  = (const float*)d_in[4];
    const float* proj_w = (const float*)d_in[5];
    const float* proj_b = (const float*)d_in[6];
    const float* bias_t = (const float*)d_in[7];
    const float* g2     = (const float*)d_in[8];
    const float* b2     = (const float*)d_in[9];
    const float* fc1_w  = (const float*)d_in[10];
    const float* fc1_b  = (const float*)d_in[11];
    const float* fc2_w  = (const float*)d_in[12];
    const float* fc2_b  = (const float*)d_in[13];
    float* out = (float*)d_out;

    float *p_qkv, *p_x1;
    __nv_bfloat16 *p_xw_hi, *p_xw_lo, *p_at_hi, *p_at_lo, *p_x2_hi, *p_x2_lo, *p_h1_hi, *p_h1_lo;
    __nv_bfloat16 *p_wq_hi, *p_wq_lo, *p_wp_hi, *p_wp_lo, *p_w1_hi, *p_w1_lo, *p_w2_hi, *p_w2_lo;
    cudaGetSymbolAddress((void**)&p_qkv,   g_qkv);
    cudaGetSymbolAddress((void**)&p_x1,    g_x1);
    cudaGetSymbolAddress((void**)&p_xw_hi, g_xw_hi);
    cudaGetSymbolAddress((void**)&p_xw_lo, g_xw_lo);
    cudaGetSymbolAddress((void**)&p_at_hi, g_at_hi);
    cudaGetSymbolAddress((void**)&p_at_lo, g_at_lo);
    cudaGetSymbolAddress((void**)&p_x2_hi, g_x2_hi);
    cudaGetSymbolAddress((void**)&p_x2_lo, g_x2_lo);
    cudaGetSymbolAddress((void**)&p_h1_hi, g_h1_hi);
    cudaGetSymbolAddress((void**)&p_h1_lo, g_h1_lo);
    cudaGetSymbolAddress((void**)&p_wq_hi, g_wq_hi);
    cudaGetSymbolAddress((void**)&p_wq_lo, g_wq_lo);
    cudaGetSymbolAddress((void**)&p_wp_hi, g_wp_hi);
    cudaGetSymbolAddress((void**)&p_wp_lo, g_wp_lo);
    cudaGetSymbolAddress((void**)&p_w1_hi, g_w1_hi);
    cudaGetSymbolAddress((void**)&p_w1_lo, g_w1_lo);
    cudaGetSymbolAddress((void**)&p_w2_hi, g_w2_hi);
    cudaGetSymbolAddress((void**)&p_w2_lo, g_w2_lo);

    cudaFuncSetAttribute(gemm_mma<EPI_NONE>, cudaFuncAttributeMaxDynamicSharedMemorySize, SM_TOT);
    cudaFuncSetAttribute(gemm_mma<EPI_PROJ>, cudaFuncAttributeMaxDynamicSharedMemorySize, SM_TOT);
    cudaFuncSetAttribute(gemm_mma<EPI_GELU>, cudaFuncAttributeMaxDynamicSharedMemorySize, SM_TOT);
    cudaFuncSetAttribute(gemm_mma<EPI_RES>,  cudaFuncAttributeMaxDynamicSharedMemorySize, SM_TOT);

    const int MB = MROWS / 128;  // 784

    // 1) LN1 + shift + partition -> bf16 planes
    ln_partition_kernel<<<MROWS / 8, 256>>>(x, g1, b1, p_xw_hi, p_xw_lo);
    // weight conversions
    convert_hilo<<<(576 * 192 + 255) / 256, 256>>>(qkv_w, p_wq_hi, p_wq_lo, 576 * 192);
    convert_hilo<<<(192 * 192 + 255) / 256, 256>>>(proj_w, p_wp_hi, p_wp_lo, 192 * 192);
    convert_hilo<<<(768 * 192 + 255) / 256, 256>>>(fc1_w, p_w1_hi, p_w1_lo, 768 * 192);
    convert_hilo<<<(192 * 768 + 255) / 256, 256>>>(fc2_w, p_w2_hi, p_w2_lo, 192 * 768);
    // 2) QKV GEMM -> fp32   (6th launch: ncu -s 5 should land here)
    gemm_mma<EPI_NONE><<<dim3(576 / 64, MB), 256, SM_TOT>>>(p_xw_hi, p_xw_lo, p_wq_hi, p_wq_lo,
                                                    qkv_b, p_qkv, 576, 192, nullptr, nullptr, nullptr);
    // 3) attention -> bf16 planes
    attn_kernel<<<NWTOT * NHEAD, 128>>>(p_qkv, bias_t, p_at_hi, p_at_lo);
    // 4) proj GEMM + scatter + residual -> fp32 x1
    gemm_mma<EPI_PROJ><<<dim3(192 / 64, MB), 256, SM_TOT>>>(p_at_hi, p_at_lo, p_wp_hi, p_wp_lo,
                                                    proj_b, p_x1, 192, 192, x, nullptr, nullptr);
    // 5) LN2 -> bf16 planes
    ln_plain_kernel<<<MROWS / 8, 256>>>(p_x1, g2, b2, p_x2_hi, p_x2_lo);
    // 6) fc1 GEMM + GELU -> bf16 planes
    gemm_mma<EPI_GELU><<<dim3(768 / 64, MB), 256, SM_TOT>>>(p_x2_hi, p_x2_lo, p_w1_hi, p_w1_lo,
                                                    fc1_b, nullptr, 768, 192, nullptr, p_h1_hi, p_h1_lo);
    // 7) fc2 GEMM + residual -> out
    gemm_mma<EPI_RES><<<dim3(192 / 64, MB), 256, SM_TOT>>>(p_h1_hi, p_h1_lo, p_w2_hi, p_w2_lo,
                                                   fc2_b, out, 192, 768, p_x1, nullptr, nullptr);
}

// round 5
// speedup vs baseline: 1.8343x; 1.2865x over previous
#include <cuda_runtime.h>
#include <cuda_bf16.h>
#include <math.h>
#include <stdint.h>

// ---------------- problem constants ----------------
#define C_     192
#define NHEAD  6
#define HID_   768
#define BATCH  32
#define NWTOT  2048
#define MROWS  100352      // NWTOT * 49

// ---------------- scratch (device globals) ----------------
__device__ __nv_bfloat16  g_qkv [(size_t)MROWS * 3 * C_];   // bf16 QKV
__device__ float          g_x1  [(size_t)MROWS * C_];       // residual stream (fp32)
__device__ __nv_bfloat16  g_xw  [(size_t)MROWS * C_];       // LN1+partition out
__device__ __nv_bfloat16  g_at  [(size_t)MROWS * C_];       // attention out
__device__ __nv_bfloat16  g_x2  [(size_t)MROWS * C_];       // LN2 out
__device__ __nv_bfloat16  g_h1  [(size_t)MROWS * HID_];     // MLP hidden
__device__ __nv_bfloat16  g_wq[576 * 192];
__device__ __nv_bfloat16  g_wp[192 * 192];
__device__ __nv_bfloat16  g_w1[768 * 192];
__device__ __nv_bfloat16  g_w2[192 * 768];

// ---------------- helpers ----------------
__device__ __forceinline__ uint32_t smem_u32(const void* p) {
    uint32_t a;
    asm("{ .reg .u64 t; cvta.to.shared.u64 t, %1; cvt.u32.u64 %0, t; }" : "=r"(a) : "l"(p));
    return a;
}
__device__ __forceinline__ float warp_sum(float v) {
#pragma unroll
    for (int o = 16; o; o >>= 1) v += __shfl_xor_sync(0xffffffffu, v, o);
    return v;
}
__device__ __forceinline__ float warp_max(float v) {
#pragma unroll
    for (int o = 16; o; o >>= 1) v = fmaxf(v, __shfl_xor_sync(0xffffffffu, v, o));
    return v;
}
__device__ __forceinline__ float gelu_exact(float x) {
    return 0.5f * x * (1.0f + erff(x * 0.70710678118654752f));
}
__device__ __forceinline__ uint32_t pack_bf2(float a, float b) {
    __nv_bfloat162 t = __floats2bfloat162_rn(a, b);
    return *(uint32_t*)&t;
}
// FMA-only exp (exp2 poly)
__device__ __forceinline__ float fast_exp(float x) {
    float t = fmaxf(x * 1.4426950408889634f, -126.0f);
    float n = floorf(t);
    float f = t - n;
    float p = 1.8775767e-3f;
    p = fmaf(p, f, 8.9893397e-3f);
    p = fmaf(p, f, 5.5804084e-2f);
    p = fmaf(p, f, 2.4013971e-1f);
    p = fmaf(p, f, 6.9314718e-1f);
    p = fmaf(p, f, 1.0f);
    return p * __int_as_float(((int)n + 127) << 23);
}

__device__ __forceinline__ void ldmat4(uint32_t* r, uint32_t addr) {
    asm volatile("ldmatrix.sync.aligned.m8n8.x4.shared.b16 {%0,%1,%2,%3}, [%4];"
        : "=r"(r[0]), "=r"(r[1]), "=r"(r[2]), "=r"(r[3]) : "r"(addr));
}
__device__ __forceinline__ void mma16816(float* d, const uint32_t* a, const uint32_t* b) {
    asm volatile("mma.sync.aligned.m16n8k16.row.col.f32.bf16.bf16.f32 "
        "{%0,%1,%2,%3}, {%4,%5,%6,%7}, {%8,%9}, {%0,%1,%2,%3};"
        : "+f"(d[0]), "+f"(d[1]), "+f"(d[2]), "+f"(d[3])
        : "r"(a[0]), "r"(a[1]), "r"(a[2]), "r"(a[3]), "r"(b[0]), "r"(b[1]));
}
#define CP16(dst, src) \
    asm volatile("cp.async.cg.shared.global [%0], [%1], 16;" :: "r"(dst), "l"(src))
#define CP_COMMIT() asm volatile("cp.async.commit_group;" ::: "memory")
#define CP_WAIT(n)  asm volatile("cp.async.wait_group %0;" :: "n"(n) : "memory")

// ---------------- all weights fp32 -> bf16, one launch ----------------
#define SEG0 110592          // 576*192
#define SEG1 147456          // +192*192
#define SEG2 294912          // +768*192
#define SEG3 442368          // +192*768
__global__ void convert_all(const float* __restrict__ qkv_w, const float* __restrict__ proj_w,
                            const float* __restrict__ fc1_w, const float* __restrict__ fc2_w,
                            __nv_bfloat16* __restrict__ wq, __nv_bfloat16* __restrict__ wp,
                            __nv_bfloat16* __restrict__ w1, __nv_bfloat16* __restrict__ w2) {
    int i = blockIdx.x * blockDim.x + threadIdx.x;
    if (i < SEG0)       wq[i]        = __float2bfloat16(qkv_w[i]);
    else if (i < SEG1)  wp[i - SEG0] = __float2bfloat16(proj_w[i - SEG0]);
    else if (i < SEG2)  w1[i - SEG1] = __float2bfloat16(fc1_w[i - SEG1]);
    else if (i < SEG3)  w2[i - SEG2] = __float2bfloat16(fc2_w[i - SEG2]);
}

// ---------------- LN1 + cyclic shift + window partition -> bf16 ----------------
__global__ void ln_partition_kernel(const float* __restrict__ x,
                                    const float* __restrict__ g,
                                    const float* __restrict__ bt,
                                    __nv_bfloat16* __restrict__ o) {
    int warp = (blockIdx.x * blockDim.x + threadIdx.x) >> 5;
    int lane = threadIdx.x & 31;
    if (warp >= MROWS) return;
    int n = warp % 49;
    int window = warp / 49;
    int wi = window & 63;
    int b  = window >> 6;
    int wh = wi >> 3, ww = wi & 7;
    int h = wh * 7 + n / 7 + 3; if (h >= 56) h -= 56;
    int w = ww * 7 + n % 7 + 3; if (w >= 56) w -= 56;
    const float* xi = x + ((size_t)b * 3136 + h * 56 + w) * 192;

    float v[6]; float s1 = 0.f;
#pragma unroll
    for (int j = 0; j < 6; j++) { v[j] = xi[lane + 32 * j]; s1 += v[j]; }
    s1 = warp_sum(s1);
    float mean = s1 * (1.0f / 192.0f);
    float s2 = 0.f;
#pragma unroll
    for (int j = 0; j < 6; j++) { float d = v[j] - mean; s2 += d * d; }
    s2 = warp_sum(s2);
    float inv = rsqrtf(s2 * (1.0f / 192.0f) + 1e-5f);
    size_t base = (size_t)warp * 192;
#pragma unroll
    for (int j = 0; j < 6; j++) {
        int c = lane + 32 * j;
        o[base + c] = __float2bfloat16((v[j] - mean) * inv * g[c] + bt[c]);
    }
}

// ---------------- LN2 -> bf16 ----------------
__global__ void ln_plain_kernel(const float* __restrict__ x,
                                const float* __restrict__ g,
                                const float* __restrict__ bt,
                                __nv_bfloat16* __restrict__ o) {
    int warp = (blockIdx.x * blockDim.x + threadIdx.x) >> 5;
    int lane = threadIdx.x & 31;
    if (warp >= MROWS) return;
    const float* xi = x + (size_t)warp * 192;
    float v[6]; float s1 = 0.f;
#pragma unroll
    for (int j = 0; j < 6; j++) { v[j] = xi[lane + 32 * j]; s1 += v[j]; }
    s1 = warp_sum(s1);
    float mean = s1 * (1.0f / 192.0f);
    float s2 = 0.f;
#pragma unroll
    for (int j = 0; j < 6; j++) { float d = v[j] - mean; s2 += d * d; }
    s2 = warp_sum(s2);
    float inv = rsqrtf(s2 * (1.0f / 192.0f) + 1e-5f);
    size_t base = (size_t)warp * 192;
#pragma unroll
    for (int j = 0; j < 6; j++) {
        int c = lane + 32 * j;
        o[base + c] = __float2bfloat16((v[j] - mean) * inv * g[c] + bt[c]);
    }
}

// ---------------- attention: one block per (window, head), bf16 I/O ----------------
__device__ __forceinline__ void unpack8(float* dst, uint4 u) {
    float2 f;
    f = __bfloat1622float2(*(__nv_bfloat162*)&u.x); dst[0] = f.x; dst[1] = f.y;
    f = __bfloat1622float2(*(__nv_bfloat162*)&u.y); dst[2] = f.x; dst[3] = f.y;
    f = __bfloat1622float2(*(__nv_bfloat162*)&u.z); dst[4] = f.x; dst[5] = f.y;
    f = __bfloat1622float2(*(__nv_bfloat162*)&u.w); dst[6] = f.x; dst[7] = f.y;
}

__global__ void attn_kernel(const __nv_bfloat16* __restrict__ qkv,
                            const float* __restrict__ bias_table,
                            __nv_bfloat16* __restrict__ outp) {
    __shared__ float sq[49 * 32];
    __shared__ float sk[49 * 32];
    __shared__ float sv[49 * 32];
    __shared__ float S[49 * 49];
    __shared__ int   sreg[49];

    int head   = blockIdx.x % NHEAD;
    int window = blockIdx.x / NHEAD;
    int tid = threadIdx.x;
    int wrp = tid >> 5, ln = tid & 31;

    const __nv_bfloat16* base = qkv + (size_t)window * 49 * 576 + head * 32;
    for (int i = tid; i < 49 * 4; i += 128) {
        int nrow = i >> 2, seg = (i & 3) * 8;
        const __nv_bfloat16* rp = base + (size_t)nrow * 576 + seg;
        unpack8(sq + nrow * 32 + seg, *(const uint4*)(rp));
        unpack8(sk + nrow * 32 + seg, *(const uint4*)(rp + 192));
        unpack8(sv + nrow * 32 + seg, *(const uint4*)(rp + 384));
    }
    if (tid < 49) {
        int wi = window & 63;
        int wh = wi >> 3, ww = wi & 7;
        int h = wh * 7 + tid / 7;
        int w = ww * 7 + tid % 7;
        int rh = (h < 49) ? 0 : (h < 53 ? 1 : 2);
        int rw = (w < 49) ? 0 : (w < 53 ? 1 : 2);
        sreg[tid] = rh * 3 + rw;
    }
    __syncthreads();

    const float scale = 0.17677669529663687f;
    for (int idx = tid; idx < 2401; idx += 128) {
        int i = idx / 49, j = idx % 49;
        const float* qi = sq + i * 32;
        const float* kj = sk + j * 32;
        float d = 0.f;
#pragma unroll
        for (int t = 0; t < 32; t++) d = fmaf(qi[t], kj[t], d);
        int rel = (i / 7 - j / 7 + 6) * 13 + (i % 7 - j % 7 + 6);
        float bias = bias_table[rel * NHEAD + head];
        float mask = (sreg[i] != sreg[j]) ? -100.0f : 0.0f;
        S[idx] = d * scale + bias + mask;
    }
    __syncthreads();

    // warp-parallel softmax: one warp per row
    for (int r = wrp; r < 49; r += 4) {
        float* row = S + r * 49;
        float v0 = row[ln];
        bool has1 = (ln + 32) < 49;
        float v1 = has1 ? row[ln + 32] : -1e30f;
        float m = warp_max(fmaxf(v0, v1));
        float e0 = fast_exp(v0 - m);
        float e1 = has1 ? fast_exp(v1 - m) : 0.f;
        float s = warp_sum(e0 + e1);
        float inv = __frcp_rn(s);
        row[ln] = e0 * inv;
        if (has1) row[ln + 32] = e1 * inv;
    }
    __syncthreads();

    for (int idx = tid; idx < 49 * 32; idx += 128) {
        int nrow = idx >> 5, d = idx & 31;
        const float* srow = S + nrow * 49;
        float acc = 0.f;
#pragma unroll 7
        for (int j = 0; j < 49; j++) acc = fmaf(srow[j], sv[j * 32 + d], acc);
        outp[((size_t)window * 49 + nrow) * 192 + head * 32 + d] = __float2bfloat16(acc);
    }
}

// ---------------- single-pass bf16 mma GEMM, cp.async double-buffered ----------------
#define SA_OFF 0
#define SB_OFF 10240
#define STAGE  15360
#define SM_TOT (2 * STAGE)

enum { EPI_QKV = 0, EPI_PROJ = 1, EPI_GELU = 2, EPI_RES = 3 };

__device__ __forceinline__ size_t proj_row(int m) {
    int n = m % 49, window = m / 49;
    int wi = window & 63, b = window >> 6;
    int wh = wi >> 3, ww = wi & 7;
    int hh = wh * 7 + n / 7 + 3; if (hh >= 56) hh -= 56;
    int wc = ww * 7 + n % 7 + 3; if (wc >= 56) wc -= 56;
    return ((size_t)b * 3136 + (size_t)hh * 56 + wc) * 192;
}

template<int EPI>
__global__ void __launch_bounds__(256, 2)
gemm_mma(const __nv_bfloat16* __restrict__ A, const __nv_bfloat16* __restrict__ W,
         const float* __restrict__ bias, float* __restrict__ Cout,
         int Nn, int Ktot, const float* __restrict__ extra,
         __nv_bfloat16* __restrict__ obf) {
    extern __shared__ __align__(16) char sm[];
    const uint32_t sb = smem_u32(sm);
    const int tid  = threadIdx.x;
    const int wid  = tid >> 5;
    const int lane = tid & 31;
    const int warpM = wid >> 1;
    const int warpN = wid & 1;
    const int bm = blockIdx.y * 128;
    const int bn = blockIdx.x * 64;

    const __nv_bfloat16* A_b = A + (size_t)bm * Ktot;
    const __nv_bfloat16* W_b = W + (size_t)bn * Ktot;

    const int arow0 = tid >> 2;
    const int arow1 = arow0 + 64;
    const int aq = (tid & 3) * 16;       // byte offset within 64B of row data
    const uint32_t a_off = (uint32_t)(warpM * 32 + (lane & 15)) * 80 + ((lane >> 4) * 16);
    const uint32_t b_off = (uint32_t)(warpN * 32 + ((lane >> 4) & 1) * 8 + (lane & 7)) * 80
                         + (((lane >> 3) & 1) * 16);

    float acc[2][4][4];
#pragma unroll
    for (int i = 0; i < 2; i++)
#pragma unroll
        for (int j = 0; j < 4; j++)
#pragma unroll
            for (int k = 0; k < 4; k++) acc[i][j][k] = 0.f;

    const int NK = Ktot >> 5;

    auto stage_load = [&](int s, int k0) {
        uint32_t d = sb + s * STAGE;
        int aqe = aq >> 1;
        CP16(d + SA_OFF + arow0 * 80 + aq, A_b + (size_t)arow0 * Ktot + k0 + aqe);
        CP16(d + SA_OFF + arow1 * 80 + aq, A_b + (size_t)arow1 * Ktot + k0 + aqe);
        CP16(d + SB_OFF + arow0 * 80 + aq, W_b + (size_t)arow0 * Ktot + k0 + aqe);
        CP_COMMIT();
    };

    stage_load(0, 0);

    for (int k = 0; k < NK; k++) {
        if (k + 1 < NK) {
            stage_load((k + 1) & 1, (k + 1) << 5);
            CP_WAIT(1);
        } else {
            CP_WAIT(0);
        }
        __syncthreads();

        const uint32_t soff = sb + (k & 1) * STAGE;
        const uint32_t aaddr = soff + SA_OFF + a_off;
        const uint32_t baddr = soff + SB_OFF + b_off;

#pragma unroll
        for (int ki = 0; ki < 2; ki++) {
            uint32_t a0[4], a1[4];
            ldmat4(a0, aaddr + ki * 32);
            ldmat4(a1, aaddr + 16 * 80 + ki * 32);
#pragma unroll
            for (int ng = 0; ng < 2; ng++) {
                uint32_t bh[4];
                ldmat4(bh, baddr + ng * 16 * 80 + ki * 32);
#pragma unroll
                for (int q = 0; q < 2; q++) {
                    int ni = ng * 2 + q;
                    mma16816(acc[0][ni], a0, bh + 2 * q);
                    mma16816(acc[1][ni], a1, bh + 2 * q);
                }
            }
        }
        __syncthreads();
    }

    // ---------------- epilogue ----------------
    const int lrow = lane >> 2, lcol = (lane & 3) * 2;
#pragma unroll
    for (int mi = 0; mi < 2; mi++) {
        int m0 = bm + warpM * 32 + mi * 16 + lrow;
        int m1 = m0 + 8;
        size_t r0, r1;
        if (EPI == EPI_PROJ) { r0 = proj_row(m0); r1 = proj_row(m1); }
        else { r0 = (size_t)m0 * Nn; r1 = (size_t)m1 * Nn; }
#pragma unroll
        for (int ni = 0; ni < 4; ni++) {
            int n = bn + warpN * 32 + ni * 8 + lcol;
            float bx = bias[n], by = bias[n + 1];
            float v0x = acc[mi][ni][0] + bx, v0y = acc[mi][ni][1] + by;
            float v1x = acc[mi][ni][2] + bx, v1y = acc[mi][ni][3] + by;
            if (EPI == EPI_QKV) {
                *(uint32_t*)(obf + r0 + n) = pack_bf2(v0x, v0y);
                *(uint32_t*)(obf + r1 + n) = pack_bf2(v1x, v1y);
            } else if (EPI == EPI_GELU) {
                *(uint32_t*)(obf + r0 + n) = pack_bf2(gelu_exact(v0x), gelu_exact(v0y));
                *(uint32_t*)(obf + r1 + n) = pack_bf2(gelu_exact(v1x), gelu_exact(v1y));
            } else {
                float2 e0 = *(const float2*)(extra + r0 + n);
                float2 e1 = *(const float2*)(extra + r1 + n);
                *(float2*)(Cout + r0 + n) = make_float2(v0x + e0.x, v0y + e0.y);
                *(float2*)(Cout + r1 + n) = make_float2(v1x + e1.x, v1y + e1.y);
            }
        }
    }
}

// ---------------- launch ----------------
extern "C" void kernel_launch(void* const* d_in, const int* in_sizes, int n_in,
                              void* d_out, int out_size) {
    const float* x      = (const float*)d_in[0];
    const float* g1     = (const float*)d_in[1];
    const float* b1     = (const float*)d_in[2];
    const float* qkv_w  = (const float*)d_in[3];
    const float* qkv_b  = (const float*)d_in[4];
    const float* proj_w = (const float*)d_in[5];
    const float* proj_b = (const float*)d_in[6];
    const float* bias_t = (const float*)d_in[7];
    const float* g2     = (const float*)d_in[8];
    const float* b2     = (const float*)d_in[9];
    const float* fc1_w  = (const float*)d_in[10];
    const float* fc1_b  = (const float*)d_in[11];
    const float* fc2_w  = (const float*)d_in[12];
    const float* fc2_b  = (const float*)d_in[13];
    float* out = (float*)d_out;

    float* p_x1;
    __nv_bfloat16 *p_qkv, *p_xw, *p_at, *p_x2, *p_h1, *p_wq, *p_wp, *p_w1, *p_w2;
    cudaGetSymbolAddress((void**)&p_qkv, g_qkv);
    cudaGetSymbolAddress((void**)&p_x1,  g_x1);
    cudaGetSymbolAddress((void**)&p_xw,  g_xw);
    cudaGetSymbolAddress((void**)&p_at,  g_at);
    cudaGetSymbolAddress((void**)&p_x2,  g_x2);
    cudaGetSymbolAddress((void**)&p_h1,  g_h1);
    cudaGetSymbolAddress((void**)&p_wq,  g_wq);
    cudaGetSymbolAddress((void**)&p_wp,  g_wp);
    cudaGetSymbolAddress((void**)&p_w1,  g_w1);
    cudaGetSymbolAddress((void**)&p_w2,  g_w2);

    cudaFuncSetAttribute(gemm_mma<EPI_QKV>,  cudaFuncAttributeMaxDynamicSharedMemorySize, SM_TOT);
    cudaFuncSetAttribute(gemm_mma<EPI_PROJ>, cudaFuncAttributeMaxDynamicSharedMemorySize, SM_TOT);
    cudaFuncSetAttribute(gemm_mma<EPI_GELU>, cudaFuncAttributeMaxDynamicSharedMemorySize, SM_TOT);
    cudaFuncSetAttribute(gemm_mma<EPI_RES>,  cudaFuncAttributeMaxDynamicSharedMemorySize, SM_TOT);

    const int MB = MROWS / 128;  // 784

    // launch 0: all weight conversions
    convert_all<<<SEG3 / 256, 256>>>(qkv_w, proj_w, fc1_w, fc2_w, p_wq, p_wp, p_w1, p_w2);
    // launch 1: LN1 + shift + partition
    ln_partition_kernel<<<MROWS / 8, 256>>>(x, g1, b1, p_xw);
    // launch 2: QKV GEMM -> bf16
    gemm_mma<EPI_QKV><<<dim3(576 / 64, MB), 256, SM_TOT>>>(p_xw, p_wq, qkv_b, nullptr, 576, 192, nullptr, p_qkv);
    // launch 3: attention (ncu capture target)
    attn_kernel<<<NWTOT * NHEAD, 128>>>(p_qkv, bias_t, p_at);
    // launch 4: proj GEMM + scatter + residual -> fp32 x1
    gemm_mma<EPI_PROJ><<<dim3(192 / 64, MB), 256, SM_TOT>>>(p_at, p_wp, proj_b, p_x1, 192, 192, x, nullptr);
    // launch 5: LN2
    ln_plain_kernel<<<MROWS / 8, 256>>>(p_x1, g2, b2, p_x2);
    // launch 6: fc1 GEMM + GELU -> bf16
    gemm_mma<EPI_GELU><<<dim3(768 / 64, MB), 256, SM_TOT>>>(p_x2, p_w1, fc1_b, nullptr, 768, 192, nullptr, p_h1);
    // launch 7: fc2 GEMM + residual -> out
    gemm_mma<EPI_RES><<<dim3(192 / 64, MB), 256, SM_TOT>>>(p_h1, p_w2, fc2_b, out, 192, 768, p_x1, nullptr);
}

// round 6
// speedup vs baseline: 3.7025x; 2.0185x over previous
#include <cuda_runtime.h>
#include <cuda_bf16.h>
#include <math.h>
#include <stdint.h>

// ---------------- problem constants ----------------
#define C_     192
#define NHEAD  6
#define HID_   768
#define BATCH  32
#define NWTOT  2048
#define MROWS  100352      // NWTOT * 49

// ---------------- scratch (device globals) ----------------
__device__ __nv_bfloat16  g_qkv [(size_t)MROWS * 3 * C_];
__device__ float          g_x1  [(size_t)MROWS * C_];
__device__ __nv_bfloat16  g_xw  [(size_t)MROWS * C_];
__device__ __nv_bfloat16  g_at  [(size_t)MROWS * C_];
__device__ __nv_bfloat16  g_x2  [(size_t)MROWS * C_];
__device__ __nv_bfloat16  g_h1  [(size_t)MROWS * HID_];
__device__ __nv_bfloat16  g_wq[576 * 192];
__device__ __nv_bfloat16  g_wp[192 * 192];
__device__ __nv_bfloat16  g_w1[768 * 192];
__device__ __nv_bfloat16  g_w2[192 * 768];

// ---------------- helpers ----------------
__device__ __forceinline__ uint32_t smem_u32(const void* p) {
    uint32_t a;
    asm("{ .reg .u64 t; cvta.to.shared.u64 t, %1; cvt.u32.u64 %0, t; }" : "=r"(a) : "l"(p));
    return a;
}
__device__ __forceinline__ float warp_sum(float v) {
#pragma unroll
    for (int o = 16; o; o >>= 1) v += __shfl_xor_sync(0xffffffffu, v, o);
    return v;
}
__device__ __forceinline__ float warp_max(float v) {
#pragma unroll
    for (int o = 16; o; o >>= 1) v = fmaxf(v, __shfl_xor_sync(0xffffffffu, v, o));
    return v;
}
__device__ __forceinline__ float gelu_exact(float x) {
    return 0.5f * x * (1.0f + erff(x * 0.70710678118654752f));
}
__device__ __forceinline__ uint32_t pack_bf2(float a, float b) {
    __nv_bfloat162 t = __floats2bfloat162_rn(a, b);
    return *(uint32_t*)&t;
}
// FMA-only exp (exp2 poly)
__device__ __forceinline__ float fast_exp(float x) {
    float t = fmaxf(x * 1.4426950408889634f, -126.0f);
    float n = floorf(t);
    float f = t - n;
    float p = 1.8775767e-3f;
    p = fmaf(p, f, 8.9893397e-3f);
    p = fmaf(p, f, 5.5804084e-2f);
    p = fmaf(p, f, 2.4013971e-1f);
    p = fmaf(p, f, 6.9314718e-1f);
    p = fmaf(p, f, 1.0f);
    return p * __int_as_float(((int)n + 127) << 23);
}

__device__ __forceinline__ void ldmat4(uint32_t* r, uint32_t addr) {
    asm volatile("ldmatrix.sync.aligned.m8n8.x4.shared.b16 {%0,%1,%2,%3}, [%4];"
        : "=r"(r[0]), "=r"(r[1]), "=r"(r[2]), "=r"(r[3]) : "r"(addr));
}
__device__ __forceinline__ void mma16816(float* d, const uint32_t* a, const uint32_t* b) {
    asm volatile("mma.sync.aligned.m16n8k16.row.col.f32.bf16.bf16.f32 "
        "{%0,%1,%2,%3}, {%4,%5,%6,%7}, {%8,%9}, {%0,%1,%2,%3};"
        : "+f"(d[0]), "+f"(d[1]), "+f"(d[2]), "+f"(d[3])
        : "r"(a[0]), "r"(a[1]), "r"(a[2]), "r"(a[3]), "r"(b[0]), "r"(b[1]));
}
#define CP16(dst, src) \
    asm volatile("cp.async.cg.shared.global [%0], [%1], 16;" :: "r"(dst), "l"(src))
#define CP_COMMIT() asm volatile("cp.async.commit_group;" ::: "memory")
#define CP_WAIT(n)  asm volatile("cp.async.wait_group %0;" :: "n"(n) : "memory")

// ---------------- all weights fp32 -> bf16, one launch ----------------
#define SEG0 110592
#define SEG1 147456
#define SEG2 294912
#define SEG3 442368
__global__ void convert_all(const float* __restrict__ qkv_w, const float* __restrict__ proj_w,
                            const float* __restrict__ fc1_w, const float* __restrict__ fc2_w,
                            __nv_bfloat16* __restrict__ wq, __nv_bfloat16* __restrict__ wp,
                            __nv_bfloat16* __restrict__ w1, __nv_bfloat16* __restrict__ w2) {
    int i = blockIdx.x * blockDim.x + threadIdx.x;
    if (i < SEG0)       wq[i]        = __float2bfloat16(qkv_w[i]);
    else if (i < SEG1)  wp[i - SEG0] = __float2bfloat16(proj_w[i - SEG0]);
    else if (i < SEG2)  w1[i - SEG1] = __float2bfloat16(fc1_w[i - SEG1]);
    else if (i < SEG3)  w2[i - SEG2] = __float2bfloat16(fc2_w[i - SEG2]);
}

// ---------------- LN1 + cyclic shift + window partition -> bf16 ----------------
__global__ void ln_partition_kernel(const float* __restrict__ x,
                                    const float* __restrict__ g,
                                    const float* __restrict__ bt,
                                    __nv_bfloat16* __restrict__ o) {
    int warp = (blockIdx.x * blockDim.x + threadIdx.x) >> 5;
    int lane = threadIdx.x & 31;
    if (warp >= MROWS) return;
    int n = warp % 49;
    int window = warp / 49;
    int wi = window & 63;
    int b  = window >> 6;
    int wh = wi >> 3, ww = wi & 7;
    int h = wh * 7 + n / 7 + 3; if (h >= 56) h -= 56;
    int w = ww * 7 + n % 7 + 3; if (w >= 56) w -= 56;
    const float* xi = x + ((size_t)b * 3136 + h * 56 + w) * 192;

    float v[6]; float s1 = 0.f;
#pragma unroll
    for (int j = 0; j < 6; j++) { v[j] = xi[lane + 32 * j]; s1 += v[j]; }
    s1 = warp_sum(s1);
    float mean = s1 * (1.0f / 192.0f);
    float s2 = 0.f;
#pragma unroll
    for (int j = 0; j < 6; j++) { float d = v[j] - mean; s2 += d * d; }
    s2 = warp_sum(s2);
    float inv = rsqrtf(s2 * (1.0f / 192.0f) + 1e-5f);
    size_t base = (size_t)warp * 192;
#pragma unroll
    for (int j = 0; j < 6; j++) {
        int c = lane + 32 * j;
        o[base + c] = __float2bfloat16((v[j] - mean) * inv * g[c] + bt[c]);
    }
}

// ---------------- LN2 -> bf16 ----------------
__global__ void ln_plain_kernel(const float* __restrict__ x,
                                const float* __restrict__ g,
                                const float* __restrict__ bt,
                                __nv_bfloat16* __restrict__ o) {
    int warp = (blockIdx.x * blockDim.x + threadIdx.x) >> 5;
    int lane = threadIdx.x & 31;
    if (warp >= MROWS) return;
    const float* xi = x + (size_t)warp * 192;
    float v[6]; float s1 = 0.f;
#pragma unroll
    for (int j = 0; j < 6; j++) { v[j] = xi[lane + 32 * j]; s1 += v[j]; }
    s1 = warp_sum(s1);
    float mean = s1 * (1.0f / 192.0f);
    float s2 = 0.f;
#pragma unroll
    for (int j = 0; j < 6; j++) { float d = v[j] - mean; s2 += d * d; }
    s2 = warp_sum(s2);
    float inv = rsqrtf(s2 * (1.0f / 192.0f) + 1e-5f);
    size_t base = (size_t)warp * 192;
#pragma unroll
    for (int j = 0; j < 6; j++) {
        int c = lane + 32 * j;
        o[base + c] = __float2bfloat16((v[j] - mean) * inv * g[c] + bt[c]);
    }
}

// ---------------- attention v2: conflict-free, register-tiled ----------------
__device__ __forceinline__ void unpack8v(float4* dst, uint4 u) {
    float2 f0 = __bfloat1622float2(*(__nv_bfloat162*)&u.x);
    float2 f1 = __bfloat1622float2(*(__nv_bfloat162*)&u.y);
    float2 f2 = __bfloat1622float2(*(__nv_bfloat162*)&u.z);
    float2 f3 = __bfloat1622float2(*(__nv_bfloat162*)&u.w);
    dst[0] = make_float4(f0.x, f0.y, f1.x, f1.y);
    dst[1] = make_float4(f2.x, f2.y, f3.x, f3.y);
}

__global__ void __launch_bounds__(128)
attn_kernel(const __nv_bfloat16* __restrict__ qkv,
            const float* __restrict__ bias_table,
            __nv_bfloat16* __restrict__ outp) {
    __shared__ __align__(16) float sq [49 * 32];        // q row-major
    __shared__ __align__(16) float skT[32 * 52 + 32];   // k transposed [t][j], padded
    __shared__ __align__(16) float sv [52 * 32];        // v row-major, rows 49-51 zeroed
    __shared__ __align__(16) float S  [52 * 52];        // scores, 52-padded rows
    __shared__ float sbias[169];
    __shared__ int   sreg[49];

    const int head   = blockIdx.x % NHEAD;
    const int window = blockIdx.x / NHEAD;
    const int tid = threadIdx.x;
    const int wrp = tid >> 5, ln = tid & 31;

    // ---- staging ----
    const __nv_bfloat16* base = qkv + (size_t)window * 49 * 576 + head * 32;
    for (int i = tid; i < 49 * 4; i += 128) {
        int row = i >> 2, seg = (i & 3) * 8;
        const __nv_bfloat16* rp = base + (size_t)row * 576 + seg;
        float4 t2[2];
        unpack8v(t2, *(const uint4*)(rp));              // q
        *(float4*)&sq[row * 32 + seg]     = t2[0];
        *(float4*)&sq[row * 32 + seg + 4] = t2[1];
        unpack8v(t2, *(const uint4*)(rp + 192));        // k -> transposed
        const float* tf = (const float*)t2;
#pragma unroll
        for (int u = 0; u < 8; u++) skT[(seg + u) * 52 + row] = tf[u];
        unpack8v(t2, *(const uint4*)(rp + 384));        // v
        *(float4*)&sv[row * 32 + seg]     = t2[0];
        *(float4*)&sv[row * 32 + seg + 4] = t2[1];
    }
    if (tid < 96) sv[49 * 32 + tid] = 0.f;              // zero pad rows of v
    if (tid < 49) {
        int wi = window & 63;
        int wh = wi >> 3, ww = wi & 7;
        int h = wh * 7 + tid / 7;
        int w = ww * 7 + tid % 7;
        int rh = (h < 49) ? 0 : (h < 53 ? 1 : 2);
        int rw = (w < 49) ? 0 : (w < 53 ? 1 : 2);
        sreg[tid] = rh * 3 + rw;
    }
    for (int i = tid; i < 169; i += 128) sbias[i] = bias_table[i * NHEAD + head];
    __syncthreads();

    // ---- QK^T: lane owns columns j0=ln, j1=ln+32; K columns in registers ----
    const float scale = 0.17677669529663687f;
    float kreg0[32], kreg1[32];
#pragma unroll
    for (int t = 0; t < 32; t++) kreg0[t] = skT[t * 52 + ln];
#pragma unroll
    for (int t = 0; t < 32; t++) kreg1[t] = skT[t * 52 + ln + 32];  // garbage for ln>=17 (padded, unused)

    const bool j1ok = (ln < 17);
    const int rj0 = sreg[ln];
    const int rj1 = j1ok ? sreg[ln + 32] : 0;
    const int jd0 = ln / 7, jm0 = ln % 7;
    const int jd1 = (ln + 32) / 7, jm1 = (ln + 32) % 7;

    for (int r = wrp; r < 49; r += 4) {
        float acc0 = 0.f, acc1 = 0.f;
#pragma unroll
        for (int tq = 0; tq < 8; tq++) {
            float4 qv = *(const float4*)&sq[r * 32 + tq * 4];
            acc0 = fmaf(qv.x, kreg0[tq * 4 + 0], acc0);
            acc1 = fmaf(qv.x, kreg1[tq * 4 + 0], acc1);
            acc0 = fmaf(qv.y, kreg0[tq * 4 + 1], acc0);
            acc1 = fmaf(qv.y, kreg1[tq * 4 + 1], acc1);
            acc0 = fmaf(qv.z, kreg0[tq * 4 + 2], acc0);
            acc1 = fmaf(qv.z, kreg1[tq * 4 + 2], acc1);
            acc0 = fmaf(qv.w, kreg0[tq * 4 + 3], acc0);
            acc1 = fmaf(qv.w, kreg1[tq * 4 + 3], acc1);
        }
        int ri = sreg[r];
        int id7 = r / 7, im7 = r % 7;
        {
            int rel = (id7 - jd0 + 6) * 13 + (im7 - jm0 + 6);
            S[r * 52 + ln] = fmaf(acc0, scale, sbias[rel] + ((ri != rj0) ? -100.f : 0.f));
        }
        if (j1ok) {
            int rel = (id7 - jd1 + 6) * 13 + (im7 - jm1 + 6);
            S[r * 52 + ln + 32] = fmaf(acc1, scale, sbias[rel] + ((ri != rj1) ? -100.f : 0.f));
        }
        if (ln >= 17 && ln < 20) S[r * 52 + 32 + ln] = 0.f;  // zero cols 49..51
    }
    __syncthreads();

    // ---- softmax: one warp per row ----
    for (int r = wrp; r < 49; r += 4) {
        float* row = S + r * 52;
        float v0 = row[ln];
        bool has1 = (ln + 32) < 49;
        float v1 = has1 ? row[ln + 32] : -1e30f;
        float m = warp_max(fmaxf(v0, v1));
        float e0 = fast_exp(v0 - m);
        float e1 = has1 ? fast_exp(v1 - m) : 0.f;
        float s = warp_sum(e0 + e1);
        float inv = __frcp_rn(s);
        row[ln] = e0 * inv;
        if (has1) row[ln + 32] = e1 * inv;
    }
    __syncthreads();

    // ---- A@V: 4 output rows per tile, lane = d; V loaded once per j, reused 4x ----
    for (int tt = wrp; tt < 13; tt += 4) {
        int n0 = tt * 4;
        int nr = (n0 + 4 <= 49) ? 4 : (49 - n0);
        float acc[4] = {0.f, 0.f, 0.f, 0.f};
#pragma unroll
        for (int jq = 0; jq < 13; jq++) {
            float v0 = sv[(jq * 4 + 0) * 32 + ln];
            float v1 = sv[(jq * 4 + 1) * 32 + ln];
            float v2 = sv[(jq * 4 + 2) * 32 + ln];
            float v3 = sv[(jq * 4 + 3) * 32 + ln];
#pragma unroll
            for (int r = 0; r < 4; r++) {
                float4 s4 = *(const float4*)&S[(n0 + r) * 52 + jq * 4];
                acc[r] = fmaf(s4.x, v0, acc[r]);
                acc[r] = fmaf(s4.y, v1, acc[r]);
                acc[r] = fmaf(s4.z, v2, acc[r]);
                acc[r] = fmaf(s4.w, v3, acc[r]);
            }
        }
        for (int r = 0; r < nr; r++) {
            outp[((size_t)window * 49 + n0 + r) * 192 + head * 32 + ln] = __float2bfloat16(acc[r]);
        }
    }
}

// ---------------- single-pass bf16 mma GEMM, cp.async double-buffered ----------------
#define SA_OFF 0
#define SB_OFF 10240
#define STAGE  15360
#define SM_TOT (2 * STAGE)

enum { EPI_QKV = 0, EPI_PROJ = 1, EPI_GELU = 2, EPI_RES = 3 };

__device__ __forceinline__ size_t proj_row(int m) {
    int n = m % 49, window = m / 49;
    int wi = window & 63, b = window >> 6;
    int wh = wi >> 3, ww = wi & 7;
    int hh = wh * 7 + n / 7 + 3; if (hh >= 56) hh -= 56;
    int wc = ww * 7 + n % 7 + 3; if (wc >= 56) wc -= 56;
    return ((size_t)b * 3136 + (size_t)hh * 56 + wc) * 192;
}

template<int EPI>
__global__ void __launch_bounds__(256, 2)
gemm_mma(const __nv_bfloat16* __restrict__ A, const __nv_bfloat16* __restrict__ W,
         const float* __restrict__ bias, float* __restrict__ Cout,
         int Nn, int Ktot, const float* __restrict__ extra,
         __nv_bfloat16* __restrict__ obf) {
    extern __shared__ __align__(16) char sm[];
    const uint32_t sb = smem_u32(sm);
    const int tid  = threadIdx.x;
    const int wid  = tid >> 5;
    const int lane = tid & 31;
    const int warpM = wid >> 1;
    const int warpN = wid & 1;
    const int bm = blockIdx.y * 128;
    const int bn = blockIdx.x * 64;

    const __nv_bfloat16* A_b = A + (size_t)bm * Ktot;
    const __nv_bfloat16* W_b = W + (size_t)bn * Ktot;

    const int arow0 = tid >> 2;
    const int arow1 = arow0 + 64;
    const int aq = (tid & 3) * 16;
    const uint32_t a_off = (uint32_t)(warpM * 32 + (lane & 15)) * 80 + ((lane >> 4) * 16);
    const uint32_t b_off = (uint32_t)(warpN * 32 + ((lane >> 4) & 1) * 8 + (lane & 7)) * 80
                         + (((lane >> 3) & 1) * 16);

    float acc[2][4][4];
#pragma unroll
    for (int i = 0; i < 2; i++)
#pragma unroll
        for (int j = 0; j < 4; j++)
#pragma unroll
            for (int k = 0; k < 4; k++) acc[i][j][k] = 0.f;

    const int NK = Ktot >> 5;

    auto stage_load = [&](int s, int k0) {
        uint32_t d = sb + s * STAGE;
        int aqe = aq >> 1;
        CP16(d + SA_OFF + arow0 * 80 + aq, A_b + (size_t)arow0 * Ktot + k0 + aqe);
        CP16(d + SA_OFF + arow1 * 80 + aq, A_b + (size_t)arow1 * Ktot + k0 + aqe);
        CP16(d + SB_OFF + arow0 * 80 + aq, W_b + (size_t)arow0 * Ktot + k0 + aqe);
        CP_COMMIT();
    };

    stage_load(0, 0);

    for (int k = 0; k < NK; k++) {
        if (k + 1 < NK) {
            stage_load((k + 1) & 1, (k + 1) << 5);
            CP_WAIT(1);
        } else {
            CP_WAIT(0);
        }
        __syncthreads();

        const uint32_t soff = sb + (k & 1) * STAGE;
        const uint32_t aaddr = soff + SA_OFF + a_off;
        const uint32_t baddr = soff + SB_OFF + b_off;

#pragma unroll
        for (int ki = 0; ki < 2; ki++) {
            uint32_t a0[4], a1[4];
            ldmat4(a0, aaddr + ki * 32);
            ldmat4(a1, aaddr + 16 * 80 + ki * 32);
#pragma unroll
            for (int ng = 0; ng < 2; ng++) {
                uint32_t bh[4];
                ldmat4(bh, baddr + ng * 16 * 80 + ki * 32);
#pragma unroll
                for (int q = 0; q < 2; q++) {
                    int ni = ng * 2 + q;
                    mma16816(acc[0][ni], a0, bh + 2 * q);
                    mma16816(acc[1][ni], a1, bh + 2 * q);
                }
            }
        }
        __syncthreads();
    }

    // ---------------- epilogue ----------------
    const int lrow = lane >> 2, lcol = (lane & 3) * 2;
#pragma unroll
    for (int mi = 0; mi < 2; mi++) {
        int m0 = bm + warpM * 32 + mi * 16 + lrow;
        int m1 = m0 + 8;
        size_t r0, r1;
        if (EPI == EPI_PROJ) { r0 = proj_row(m0); r1 = proj_row(m1); }
        else { r0 = (size_t)m0 * Nn; r1 = (size_t)m1 * Nn; }
#pragma unroll
        for (int ni = 0; ni < 4; ni++) {
            int n = bn + warpN * 32 + ni * 8 + lcol;
            float bx = bias[n], by = bias[n + 1];
            float v0x = acc[mi][ni][0] + bx, v0y = acc[mi][ni][1] + by;
            float v1x = acc[mi][ni][2] + bx, v1y = acc[mi][ni][3] + by;
            if (EPI == EPI_QKV) {
                *(uint32_t*)(obf + r0 + n) = pack_bf2(v0x, v0y);
                *(uint32_t*)(obf + r1 + n) = pack_bf2(v1x, v1y);
            } else if (EPI == EPI_GELU) {
                *(uint32_t*)(obf + r0 + n) = pack_bf2(gelu_exact(v0x), gelu_exact(v0y));
                *(uint32_t*)(obf + r1 + n) = pack_bf2(gelu_exact(v1x), gelu_exact(v1y));
            } else {
                float2 e0 = *(const float2*)(extra + r0 + n);
                float2 e1 = *(const float2*)(extra + r1 + n);
                *(float2*)(Cout + r0 + n) = make_float2(v0x + e0.x, v0y + e0.y);
                *(float2*)(Cout + r1 + n) = make_float2(v1x + e1.x, v1y + e1.y);
            }
        }
    }
}

// ---------------- launch ----------------
extern "C" void kernel_launch(void* const* d_in, const int* in_sizes, int n_in,
                              void* d_out, int out_size) {
    const float* x      = (const float*)d_in[0];
    const float* g1     = (const float*)d_in[1];
    const float* b1     = (const float*)d_in[2];
    const float* qkv_w  = (const float*)d_in[3];
    const float* qkv_b  = (const float*)d_in[4];
    const float* proj_w = (const float*)d_in[5];
    const float* proj_b = (const float*)d_in[6];
    const float* bias_t = (const float*)d_in[7];
    const float* g2     = (const float*)d_in[8];
    const float* b2     = (const float*)d_in[9];
    const float* fc1_w  = (const float*)d_in[10];
    const float* fc1_b  = (const float*)d_in[11];
    const float* fc2_w  = (const float*)d_in[12];
    const float* fc2_b  = (const float*)d_in[13];
    float* out = (float*)d_out;

    float* p_x1;
    __nv_bfloat16 *p_qkv, *p_xw, *p_at, *p_x2, *p_h1, *p_wq, *p_wp, *p_w1, *p_w2;
    cudaGetSymbolAddress((void**)&p_qkv, g_qkv);
    cudaGetSymbolAddress((void**)&p_x1,  g_x1);
    cudaGetSymbolAddress((void**)&p_xw,  g_xw);
    cudaGetSymbolAddress((void**)&p_at,  g_at);
    cudaGetSymbolAddress((void**)&p_x2,  g_x2);
    cudaGetSymbolAddress((void**)&p_h1,  g_h1);
    cudaGetSymbolAddress((void**)&p_wq,  g_wq);
    cudaGetSymbolAddress((void**)&p_wp,  g_wp);
    cudaGetSymbolAddress((void**)&p_w1,  g_w1);
    cudaGetSymbolAddress((void**)&p_w2,  g_w2);

    cudaFuncSetAttribute(gemm_mma<EPI_QKV>,  cudaFuncAttributeMaxDynamicSharedMemorySize, SM_TOT);
    cudaFuncSetAttribute(gemm_mma<EPI_PROJ>, cudaFuncAttributeMaxDynamicSharedMemorySize, SM_TOT);
    cudaFuncSetAttribute(gemm_mma<EPI_GELU>, cudaFuncAttributeMaxDynamicSharedMemorySize, SM_TOT);
    cudaFuncSetAttribute(gemm_mma<EPI_RES>,  cudaFuncAttributeMaxDynamicSharedMemorySize, SM_TOT);

    const int MB = MROWS / 128;  // 784

    // launch 0: weight conversions
    convert_all<<<SEG3 / 256, 256>>>(qkv_w, proj_w, fc1_w, fc2_w, p_wq, p_wp, p_w1, p_w2);
    // launch 1: LN1 + shift + partition
    ln_partition_kernel<<<MROWS / 8, 256>>>(x, g1, b1, p_xw);
    // launch 2: QKV GEMM -> bf16
    gemm_mma<EPI_QKV><<<dim3(576 / 64, MB), 256, SM_TOT>>>(p_xw, p_wq, qkv_b, nullptr, 576, 192, nullptr, p_qkv);
    // launch 3: attention (ncu capture target)
    attn_kernel<<<NWTOT * NHEAD, 128>>>(p_qkv, bias_t, p_at);
    // launch 4: proj GEMM + scatter + residual -> fp32 x1
    gemm_mma<EPI_PROJ><<<dim3(192 / 64, MB), 256, SM_TOT>>>(p_at, p_wp, proj_b, p_x1, 192, 192, x, nullptr);
    // launch 5: LN2
    ln_plain_kernel<<<MROWS / 8, 256>>>(p_x1, g2, b2, p_x2);
    // launch 6: fc1 GEMM + GELU -> bf16
    gemm_mma<EPI_GELU><<<dim3(768 / 64, MB), 256, SM_TOT>>>(p_x2, p_w1, fc1_b, nullptr, 768, 192, nullptr, p_h1);
    // launch 7: fc2 GEMM + residual -> out
    gemm_mma<EPI_RES><<<dim3(192 / 64, MB), 256, SM_TOT>>>(p_h1, p_w2, fc2_b, out, 192, 768, p_x1, nullptr);
}

// round 7
// speedup vs baseline: 4.3619x; 1.1781x over previous
#include <cuda_runtime.h>
#include <cuda_bf16.h>
#include <math.h>
#include <stdint.h>

// ---------------- problem constants ----------------
#define C_     192
#define NHEAD  6
#define HID_   768
#define BATCH  32
#define NWTOT  2048
#define MROWS  100352      // NWTOT * 49

// ---------------- scratch (device globals) ----------------
__device__ __nv_bfloat16  g_qkv [(size_t)MROWS * 3 * C_];
__device__ float          g_x1  [(size_t)MROWS * C_];
__device__ __nv_bfloat16  g_xw  [(size_t)MROWS * C_];
__device__ __nv_bfloat16  g_at  [(size_t)MROWS * C_];
__device__ __nv_bfloat16  g_x2  [(size_t)MROWS * C_];
__device__ __nv_bfloat16  g_h1  [(size_t)MROWS * HID_];
__device__ __nv_bfloat16  g_wq[576 * 192];
__device__ __nv_bfloat16  g_wp[192 * 192];
__device__ __nv_bfloat16  g_w1[768 * 192];
__device__ __nv_bfloat16  g_w2[192 * 768];
__device__ float          g_battn[24 * 4096];   // [class(4) x head(6)][64x64] bias+mask table

// ---------------- helpers ----------------
__device__ __forceinline__ uint32_t smem_u32(const void* p) {
    uint32_t a;
    asm("{ .reg .u64 t; cvta.to.shared.u64 t, %1; cvt.u32.u64 %0, t; }" : "=r"(a) : "l"(p));
    return a;
}
__device__ __forceinline__ float warp_sum(float v) {
#pragma unroll
    for (int o = 16; o; o >>= 1) v += __shfl_xor_sync(0xffffffffu, v, o);
    return v;
}
__device__ __forceinline__ float gelu_exact(float x) {
    return 0.5f * x * (1.0f + erff(x * 0.70710678118654752f));
}
__device__ __forceinline__ uint32_t pack_bf2(float a, float b) {
    __nv_bfloat162 t = __floats2bfloat162_rn(a, b);
    return *(uint32_t*)&t;
}
// FMA-only exp (exp2 poly)
__device__ __forceinline__ float fast_exp(float x) {
    float t = fmaxf(x * 1.4426950408889634f, -126.0f);
    float n = floorf(t);
    float f = t - n;
    float p = 1.8775767e-3f;
    p = fmaf(p, f, 8.9893397e-3f);
    p = fmaf(p, f, 5.5804084e-2f);
    p = fmaf(p, f, 2.4013971e-1f);
    p = fmaf(p, f, 6.9314718e-1f);
    p = fmaf(p, f, 1.0f);
    return p * __int_as_float(((int)n + 127) << 23);
}

__device__ __forceinline__ void ldmat4(uint32_t* r, uint32_t addr) {
    asm volatile("ldmatrix.sync.aligned.m8n8.x4.shared.b16 {%0,%1,%2,%3}, [%4];"
        : "=r"(r[0]), "=r"(r[1]), "=r"(r[2]), "=r"(r[3]) : "r"(addr));
}
__device__ __forceinline__ void ldmat2(uint32_t* r, uint32_t addr) {
    asm volatile("ldmatrix.sync.aligned.m8n8.x2.shared.b16 {%0,%1}, [%2];"
        : "=r"(r[0]), "=r"(r[1]) : "r"(addr));
}
__device__ __forceinline__ void ldmat2t(uint32_t* r, uint32_t addr) {
    asm volatile("ldmatrix.sync.aligned.m8n8.x2.trans.shared.b16 {%0,%1}, [%2];"
        : "=r"(r[0]), "=r"(r[1]) : "r"(addr));
}
__device__ __forceinline__ void mma16816(float* d, const uint32_t* a, const uint32_t* b) {
    asm volatile("mma.sync.aligned.m16n8k16.row.col.f32.bf16.bf16.f32 "
        "{%0,%1,%2,%3}, {%4,%5,%6,%7}, {%8,%9}, {%0,%1,%2,%3};"
        : "+f"(d[0]), "+f"(d[1]), "+f"(d[2]), "+f"(d[3])
        : "r"(a[0]), "r"(a[1]), "r"(a[2]), "r"(a[3]), "r"(b[0]), "r"(b[1]));
}
#define CP16(dst, src) \
    asm volatile("cp.async.cg.shared.global [%0], [%1], 16;" :: "r"(dst), "l"(src))
#define CP_COMMIT() asm volatile("cp.async.commit_group;" ::: "memory")
#define CP_WAIT(n)  asm volatile("cp.async.wait_group %0;" :: "n"(n) : "memory")

// ---------------- all weights fp32 -> bf16, one launch ----------------
#define SEG0 110592
#define SEG1 147456
#define SEG2 294912
#define SEG3 442368
__global__ void convert_all(const float* __restrict__ qkv_w, const float* __restrict__ proj_w,
                            const float* __restrict__ fc1_w, const float* __restrict__ fc2_w,
                            __nv_bfloat16* __restrict__ wq, __nv_bfloat16* __restrict__ wp,
                            __nv_bfloat16* __restrict__ w1, __nv_bfloat16* __restrict__ w2) {
    int i = blockIdx.x * blockDim.x + threadIdx.x;
    if (i < SEG0)       wq[i]        = __float2bfloat16(qkv_w[i]);
    else if (i < SEG1)  wp[i - SEG0] = __float2bfloat16(proj_w[i - SEG0]);
    else if (i < SEG2)  w1[i - SEG1] = __float2bfloat16(fc1_w[i - SEG1]);
    else if (i < SEG3)  w2[i - SEG2] = __float2bfloat16(fc2_w[i - SEG2]);
}

// ---------------- build attention bias+mask tables: [4 classes][6 heads][64x64] ----------------
__global__ void build_battn(const float* __restrict__ bt, float* __restrict__ battn) {
    int cls  = blockIdx.x / NHEAD;
    int head = blockIdx.x % NHEAD;
    float* T = battn + (size_t)blockIdx.x * 4096;
    for (int i = threadIdx.x; i < 4096; i += 256) {
        int r = i >> 6, c = i & 63;
        float v = -1e30f;
        if (r < 49 && c < 49) {
            int rr = ((cls & 1) ? ((r / 7 < 4) ? 1 : 2) : 0) * 3
                   + ((cls & 2) ? ((r % 7 < 4) ? 1 : 2) : 0);
            int rc = ((cls & 1) ? ((c / 7 < 4) ? 1 : 2) : 0) * 3
                   + ((cls & 2) ? ((c % 7 < 4) ? 1 : 2) : 0);
            int rel = (r / 7 - c / 7 + 6) * 13 + (r % 7 - c % 7 + 6);
            v = bt[rel * NHEAD + head] + ((rr != rc) ? -100.0f : 0.0f);
        }
        T[i] = v;
    }
}

// ---------------- LN1 + cyclic shift + window partition -> bf16 ----------------
__global__ void ln_partition_kernel(const float* __restrict__ x,
                                    const float* __restrict__ g,
                                    const float* __restrict__ bt,
                                    __nv_bfloat16* __restrict__ o) {
    int warp = (blockIdx.x * blockDim.x + threadIdx.x) >> 5;
    int lane = threadIdx.x & 31;
    if (warp >= MROWS) return;
    int n = warp % 49;
    int window = warp / 49;
    int wi = window & 63;
    int b  = window >> 6;
    int wh = wi >> 3, ww = wi & 7;
    int h = wh * 7 + n / 7 + 3; if (h >= 56) h -= 56;
    int w = ww * 7 + n % 7 + 3; if (w >= 56) w -= 56;
    const float* xi = x + ((size_t)b * 3136 + h * 56 + w) * 192;

    float v[6]; float s1 = 0.f;
#pragma unroll
    for (int j = 0; j < 6; j++) { v[j] = xi[lane + 32 * j]; s1 += v[j]; }
    s1 = warp_sum(s1);
    float mean = s1 * (1.0f / 192.0f);
    float s2 = 0.f;
#pragma unroll
    for (int j = 0; j < 6; j++) { float d = v[j] - mean; s2 += d * d; }
    s2 = warp_sum(s2);
    float inv = rsqrtf(s2 * (1.0f / 192.0f) + 1e-5f);
    size_t base = (size_t)warp * 192;
#pragma unroll
    for (int j = 0; j < 6; j++) {
        int c = lane + 32 * j;
        o[base + c] = __float2bfloat16((v[j] - mean) * inv * g[c] + bt[c]);
    }
}

// ---------------- LN2 -> bf16 ----------------
__global__ void ln_plain_kernel(const float* __restrict__ x,
                                const float* __restrict__ g,
                                const float* __restrict__ bt,
                                __nv_bfloat16* __restrict__ o) {
    int warp = (blockIdx.x * blockDim.x + threadIdx.x) >> 5;
    int lane = threadIdx.x & 31;
    if (warp >= MROWS) return;
    const float* xi = x + (size_t)warp * 192;
    float v[6]; float s1 = 0.f;
#pragma unroll
    for (int j = 0; j < 6; j++) { v[j] = xi[lane + 32 * j]; s1 += v[j]; }
    s1 = warp_sum(s1);
    float mean = s1 * (1.0f / 192.0f);
    float s2 = 0.f;
#pragma unroll
    for (int j = 0; j < 6; j++) { float d = v[j] - mean; s2 += d * d; }
    s2 = warp_sum(s2);
    float inv = rsqrtf(s2 * (1.0f / 192.0f) + 1e-5f);
    size_t base = (size_t)warp * 192;
#pragma unroll
    for (int j = 0; j < 6; j++) {
        int c = lane + 32 * j;
        o[base + c] = __float2bfloat16((v[j] - mean) * inv * g[c] + bt[c]);
    }
}

// ---------------- attention v3: HMMA (mma.sync bf16), one block per (window, head) ----------------
// smem: Q/K/V as 64x32 bf16 with 80B row pitch (rows 49-63 zeroed), plus 64x64 f32 add-table.
__global__ void __launch_bounds__(128)
attn_kernel(const __nv_bfloat16* __restrict__ qkv,
            const float* __restrict__ battn,
            __nv_bfloat16* __restrict__ outp) {
    __shared__ __align__(16) char sQ[64 * 80];
    __shared__ __align__(16) char sK[64 * 80];
    __shared__ __align__(16) char sV[64 * 80];
    __shared__ __align__(16) float sT[4096];

    const int head   = blockIdx.x % NHEAD;
    const int window = blockIdx.x / NHEAD;
    const int tid  = threadIdx.x;
    const int wrp  = tid >> 5;
    const int lane = tid & 31;

    // ---- stage QKV (bf16, no conversion) ----
    const __nv_bfloat16* wbase = qkv + (size_t)window * 49 * 576 + head * 32;
    for (int i = tid; i < 588; i += 128) {            // 3 mats * 49 rows * 4 chunks(16B)
        int mat = i / 196, rem = i - mat * 196;
        int row = rem >> 2, ch = rem & 3;
        uint4 v = *(const uint4*)(wbase + (size_t)row * 576 + mat * 192 + ch * 8);
        char* dst = (mat == 0) ? sQ : (mat == 1) ? sK : sV;
        *(uint4*)(dst + row * 80 + ch * 16) = v;
    }
    for (int t = tid; t < 225; t += 128) {            // zero pad rows 49..63 (15 rows * 5 chunks * 3)
        int mat = t / 75, rr = t - mat * 75;
        int row = 49 + rr / 5, ch = rr % 5;
        char* dst = (mat == 0) ? sQ : (mat == 1) ? sK : sV;
        *(uint4*)(dst + row * 80 + ch * 16) = make_uint4(0, 0, 0, 0);
    }
    {   // stage bias+mask table for this (class, head)
        int wi = window & 63;
        int cls = ((wi >> 3) == 7 ? 1 : 0) + ((wi & 7) == 7 ? 2 : 0);
        const float* gT = battn + (size_t)(cls * NHEAD + head) * 4096;
        for (int i = tid; i < 1024; i += 128)
            *(float4*)(sT + i * 4) = *(const float4*)(gT + i * 4);
    }
    __syncthreads();

    const uint32_t sQu = smem_u32(sQ), sKu = smem_u32(sK), sVu = smem_u32(sV);

    // ---- QK^T: warp owns rows 16*wrp..16*wrp+15; S[16 x 64] in acc ----
    uint32_t qa[2][4];
    {
        uint32_t qaddr = sQu + (uint32_t)(16 * wrp + (lane & 15)) * 80 + ((lane >> 4) * 16);
        ldmat4(qa[0], qaddr);
        ldmat4(qa[1], qaddr + 32);
    }
    float acc[8][4];
#pragma unroll
    for (int nt = 0; nt < 8; nt++)
#pragma unroll
        for (int q = 0; q < 4; q++) acc[nt][q] = 0.f;

    const uint32_t krow = (uint32_t)(lane & 7) * 80 + ((lane & 8) ? 16 : 0);
#pragma unroll
    for (int nt = 0; nt < 8; nt++) {
#pragma unroll
        for (int kk = 0; kk < 2; kk++) {
            uint32_t b[2];
            ldmat2(b, sKu + nt * 640 + kk * 32 + krow);
            mma16816(acc[nt], qa[kk], b);
        }
    }

    // ---- add scale*S + bias+mask table ----
    const float scale = 0.17677669529663687f;
    const int tr = lane >> 2;                 // 0..7
    const int tc = (lane & 3) * 2;            // 0,2,4,6
    const float* T0 = sT + (16 * wrp + tr) * 64;
    const float* T1 = T0 + 8 * 64;
#pragma unroll
    for (int nt = 0; nt < 8; nt++) {
        int c = 8 * nt + tc;
        acc[nt][0] = fmaf(acc[nt][0], scale, T0[c]);
        acc[nt][1] = fmaf(acc[nt][1], scale, T0[c + 1]);
        acc[nt][2] = fmaf(acc[nt][2], scale, T1[c]);
        acc[nt][3] = fmaf(acc[nt][3], scale, T1[c + 1]);
    }

    // ---- register softmax (rows spread over 4-lane groups) ----
    float m0 = -1e30f, m1 = -1e30f;
#pragma unroll
    for (int nt = 0; nt < 8; nt++) {
        m0 = fmaxf(m0, fmaxf(acc[nt][0], acc[nt][1]));
        m1 = fmaxf(m1, fmaxf(acc[nt][2], acc[nt][3]));
    }
    m0 = fmaxf(m0, __shfl_xor_sync(0xffffffffu, m0, 1));
    m0 = fmaxf(m0, __shfl_xor_sync(0xffffffffu, m0, 2));
    m1 = fmaxf(m1, __shfl_xor_sync(0xffffffffu, m1, 1));
    m1 = fmaxf(m1, __shfl_xor_sync(0xffffffffu, m1, 2));
    float s0 = 0.f, s1 = 0.f;
#pragma unroll
    for (int nt = 0; nt < 8; nt++) {
        acc[nt][0] = fast_exp(acc[nt][0] - m0); s0 += acc[nt][0];
        acc[nt][1] = fast_exp(acc[nt][1] - m0); s0 += acc[nt][1];
        acc[nt][2] = fast_exp(acc[nt][2] - m1); s1 += acc[nt][2];
        acc[nt][3] = fast_exp(acc[nt][3] - m1); s1 += acc[nt][3];
    }
    s0 += __shfl_xor_sync(0xffffffffu, s0, 1);
    s0 += __shfl_xor_sync(0xffffffffu, s0, 2);
    s1 += __shfl_xor_sync(0xffffffffu, s1, 1);
    s1 += __shfl_xor_sync(0xffffffffu, s1, 2);
    const float i0 = __frcp_rn(s0), i1 = __frcp_rn(s1);

    // ---- P -> bf16 A-frags (register-only; acc layout == a-frag layout) ----
    uint32_t pa[4][4];
#pragma unroll
    for (int kk = 0; kk < 4; kk++) {
        pa[kk][0] = pack_bf2(acc[2 * kk][0] * i0, acc[2 * kk][1] * i0);
        pa[kk][1] = pack_bf2(acc[2 * kk][2] * i1, acc[2 * kk][3] * i1);
        pa[kk][2] = pack_bf2(acc[2 * kk + 1][0] * i0, acc[2 * kk + 1][1] * i0);
        pa[kk][3] = pack_bf2(acc[2 * kk + 1][2] * i1, acc[2 * kk + 1][3] * i1);
    }

    // ---- O = P @ V : ldmatrix.x2.trans on V[j][d] ----
    float o[4][4];
#pragma unroll
    for (int nt = 0; nt < 4; nt++)
#pragma unroll
        for (int q = 0; q < 4; q++) o[nt][q] = 0.f;

    const uint32_t vrow = sVu + (uint32_t)(lane & 15) * 80;
#pragma unroll
    for (int kk = 0; kk < 4; kk++) {
#pragma unroll
        for (int nt = 0; nt < 4; nt++) {
            uint32_t b[2];
            ldmat2t(b, vrow + kk * (16 * 80) + nt * 16);
            mma16816(o[nt], pa[kk], b);
        }
    }

    // ---- epilogue: store rows < 49 as bf16 ----
    const int gr0 = 16 * wrp + tr, gr1 = gr0 + 8;
    __nv_bfloat16* ob = outp + (size_t)window * 49 * 192 + head * 32;
#pragma unroll
    for (int nt = 0; nt < 4; nt++) {
        int d = 8 * nt + tc;
        if (gr0 < 49) *(uint32_t*)(ob + (size_t)gr0 * 192 + d) = pack_bf2(o[nt][0], o[nt][1]);
        if (gr1 < 49) *(uint32_t*)(ob + (size_t)gr1 * 192 + d) = pack_bf2(o[nt][2], o[nt][3]);
    }
}

// ---------------- single-pass bf16 mma GEMM, cp.async double-buffered ----------------
#define SA_OFF 0
#define SB_OFF 10240
#define STAGE  15360
#define SM_TOT (2 * STAGE)

enum { EPI_QKV = 0, EPI_PROJ = 1, EPI_GELU = 2, EPI_RES = 3 };

__device__ __forceinline__ size_t proj_row(int m) {
    int n = m % 49, window = m / 49;
    int wi = window & 63, b = window >> 6;
    int wh = wi >> 3, ww = wi & 7;
    int hh = wh * 7 + n / 7 + 3; if (hh >= 56) hh -= 56;
    int wc = ww * 7 + n % 7 + 3; if (wc >= 56) wc -= 56;
    return ((size_t)b * 3136 + (size_t)hh * 56 + wc) * 192;
}

template<int EPI>
__global__ void __launch_bounds__(256, 2)
gemm_mma(const __nv_bfloat16* __restrict__ A, const __nv_bfloat16* __restrict__ W,
         const float* __restrict__ bias, float* __restrict__ Cout,
         int Nn, int Ktot, const float* __restrict__ extra,
         __nv_bfloat16* __restrict__ obf) {
    extern __shared__ __align__(16) char sm[];
    const uint32_t sb = smem_u32(sm);
    const int tid  = threadIdx.x;
    const int wid  = tid >> 5;
    const int lane = tid & 31;
    const int warpM = wid >> 1;
    const int warpN = wid & 1;
    const int bm = blockIdx.y * 128;
    const int bn = blockIdx.x * 64;

    const __nv_bfloat16* A_b = A + (size_t)bm * Ktot;
    const __nv_bfloat16* W_b = W + (size_t)bn * Ktot;

    const int arow0 = tid >> 2;
    const int arow1 = arow0 + 64;
    const int aq = (tid & 3) * 16;
    const uint32_t a_off = (uint32_t)(warpM * 32 + (lane & 15)) * 80 + ((lane >> 4) * 16);
    const uint32_t b_off = (uint32_t)(warpN * 32 + ((lane >> 4) & 1) * 8 + (lane & 7)) * 80
                         + (((lane >> 3) & 1) * 16);

    float acc[2][4][4];
#pragma unroll
    for (int i = 0; i < 2; i++)
#pragma unroll
        for (int j = 0; j < 4; j++)
#pragma unroll
            for (int k = 0; k < 4; k++) acc[i][j][k] = 0.f;

    const int NK = Ktot >> 5;

    auto stage_load = [&](int s, int k0) {
        uint32_t d = sb + s * STAGE;
        int aqe = aq >> 1;
        CP16(d + SA_OFF + arow0 * 80 + aq, A_b + (size_t)arow0 * Ktot + k0 + aqe);
        CP16(d + SA_OFF + arow1 * 80 + aq, A_b + (size_t)arow1 * Ktot + k0 + aqe);
        CP16(d + SB_OFF + arow0 * 80 + aq, W_b + (size_t)arow0 * Ktot + k0 + aqe);
        CP_COMMIT();
    };

    stage_load(0, 0);

    for (int k = 0; k < NK; k++) {
        if (k + 1 < NK) {
            stage_load((k + 1) & 1, (k + 1) << 5);
            CP_WAIT(1);
        } else {
            CP_WAIT(0);
        }
        __syncthreads();

        const uint32_t soff = sb + (k & 1) * STAGE;
        const uint32_t aaddr = soff + SA_OFF + a_off;
        const uint32_t baddr = soff + SB_OFF + b_off;

#pragma unroll
        for (int ki = 0; ki < 2; ki++) {
            uint32_t a0[4], a1[4];
            ldmat4(a0, aaddr + ki * 32);
            ldmat4(a1, aaddr + 16 * 80 + ki * 32);
#pragma unroll
            for (int ng = 0; ng < 2; ng++) {
                uint32_t bh[4];
                ldmat4(bh, baddr + ng * 16 * 80 + ki * 32);
#pragma unroll
                for (int q = 0; q < 2; q++) {
                    int ni = ng * 2 + q;
                    mma16816(acc[0][ni], a0, bh + 2 * q);
                    mma16816(acc[1][ni], a1, bh + 2 * q);
                }
            }
        }
        __syncthreads();
    }

    // ---------------- epilogue ----------------
    const int lrow = lane >> 2, lcol = (lane & 3) * 2;
#pragma unroll
    for (int mi = 0; mi < 2; mi++) {
        int m0 = bm + warpM * 32 + mi * 16 + lrow;
        int m1 = m0 + 8;
        size_t r0, r1;
        if (EPI == EPI_PROJ) { r0 = proj_row(m0); r1 = proj_row(m1); }
        else { r0 = (size_t)m0 * Nn; r1 = (size_t)m1 * Nn; }
#pragma unroll
        for (int ni = 0; ni < 4; ni++) {
            int n = bn + warpN * 32 + ni * 8 + lcol;
            float bx = bias[n], by = bias[n + 1];
            float v0x = acc[mi][ni][0] + bx, v0y = acc[mi][ni][1] + by;
            float v1x = acc[mi][ni][2] + bx, v1y = acc[mi][ni][3] + by;
            if (EPI == EPI_QKV) {
                *(uint32_t*)(obf + r0 + n) = pack_bf2(v0x, v0y);
                *(uint32_t*)(obf + r1 + n) = pack_bf2(v1x, v1y);
            } else if (EPI == EPI_GELU) {
                *(uint32_t*)(obf + r0 + n) = pack_bf2(gelu_exact(v0x), gelu_exact(v0y));
                *(uint32_t*)(obf + r1 + n) = pack_bf2(gelu_exact(v1x), gelu_exact(v1y));
            } else {
                float2 e0 = *(const float2*)(extra + r0 + n);
                float2 e1 = *(const float2*)(extra + r1 + n);
                *(float2*)(Cout + r0 + n) = make_float2(v0x + e0.x, v0y + e0.y);
                *(float2*)(Cout + r1 + n) = make_float2(v1x + e1.x, v1y + e1.y);
            }
        }
    }
}

// ---------------- launch ----------------
extern "C" void kernel_launch(void* const* d_in, const int* in_sizes, int n_in,
                              void* d_out, int out_size) {
    const float* x      = (const float*)d_in[0];
    const float* g1     = (const float*)d_in[1];
    const float* b1     = (const float*)d_in[2];
    const float* qkv_w  = (const float*)d_in[3];
    const float* qkv_b  = (const float*)d_in[4];
    const float* proj_w = (const float*)d_in[5];
    const float* proj_b = (const float*)d_in[6];
    const float* bias_t = (const float*)d_in[7];
    const float* g2     = (const float*)d_in[8];
    const float* b2     = (const float*)d_in[9];
    const float* fc1_w  = (const float*)d_in[10];
    const float* fc1_b  = (const float*)d_in[11];
    const float* fc2_w  = (const float*)d_in[12];
    const float* fc2_b  = (const float*)d_in[13];
    float* out = (float*)d_out;

    float *p_x1, *p_battn;
    __nv_bfloat16 *p_qkv, *p_xw, *p_at, *p_x2, *p_h1, *p_wq, *p_wp, *p_w1, *p_w2;
    cudaGetSymbolAddress((void**)&p_qkv, g_qkv);
    cudaGetSymbolAddress((void**)&p_x1,  g_x1);
    cudaGetSymbolAddress((void**)&p_xw,  g_xw);
    cudaGetSymbolAddress((void**)&p_at,  g_at);
    cudaGetSymbolAddress((void**)&p_x2,  g_x2);
    cudaGetSymbolAddress((void**)&p_h1,  g_h1);
    cudaGetSymbolAddress((void**)&p_wq,  g_wq);
    cudaGetSymbolAddress((void**)&p_wp,  g_wp);
    cudaGetSymbolAddress((void**)&p_w1,  g_w1);
    cudaGetSymbolAddress((void**)&p_w2,  g_w2);
    cudaGetSymbolAddress((void**)&p_battn, g_battn);

    cudaFuncSetAttribute(gemm_mma<EPI_QKV>,  cudaFuncAttributeMaxDynamicSharedMemorySize, SM_TOT);
    cudaFuncSetAttribute(gemm_mma<EPI_PROJ>, cudaFuncAttributeMaxDynamicSharedMemorySize, SM_TOT);
    cudaFuncSetAttribute(gemm_mma<EPI_GELU>, cudaFuncAttributeMaxDynamicSharedMemorySize, SM_TOT);
    cudaFuncSetAttribute(gemm_mma<EPI_RES>,  cudaFuncAttributeMaxDynamicSharedMemorySize, SM_TOT);

    const int MB = MROWS / 128;  // 784

    // 0: weight conversions
    convert_all<<<SEG3 / 256, 256>>>(qkv_w, proj_w, fc1_w, fc2_w, p_wq, p_wp, p_w1, p_w2);
    // 1: bias+mask tables
    build_battn<<<24, 256>>>(bias_t, p_battn);
    // 2: LN1 + shift + partition
    ln_partition_kernel<<<MROWS / 8, 256>>>(x, g1, b1, p_xw);
    // 3: QKV GEMM -> bf16
    gemm_mma<EPI_QKV><<<dim3(576 / 64, MB), 256, SM_TOT>>>(p_xw, p_wq, qkv_b, nullptr, 576, 192, nullptr, p_qkv);
    // 4: attention (HMMA)
    attn_kernel<<<NWTOT * NHEAD, 128>>>(p_qkv, p_battn, p_at);
    // 5: proj GEMM + scatter + residual -> fp32 x1
    gemm_mma<EPI_PROJ><<<dim3(192 / 64, MB), 256, SM_TOT>>>(p_at, p_wp, proj_b, p_x1, 192, 192, x, nullptr);
    // 6: LN2
    ln_plain_kernel<<<MROWS / 8, 256>>>(p_x1, g2, b2, p_x2);
    // 7: fc1 GEMM + GELU -> bf16
    gemm_mma<EPI_GELU><<<dim3(768 / 64, MB), 256, SM_TOT>>>(p_x2, p_w1, fc1_b, nullptr, 768, 192, nullptr, p_h1);
    // 8: fc2 GEMM + residual -> out
    gemm_mma<EPI_RES><<<dim3(192 / 64, MB), 256, SM_TOT>>>(p_h1, p_w2, fc2_b, out, 192, 768, p_x1, nullptr);
}

// round 8
// speedup vs baseline: 4.9817x; 1.1421x over previous
#include <cuda_runtime.h>
#include <cuda_bf16.h>
#include <math.h>
#include <stdint.h>

// ---------------- problem constants ----------------
#define C_     192
#define NHEAD  6
#define HID_   768
#define BATCH  32
#define NWTOT  2048
#define MROWS  100352      // NWTOT * 49

// ---------------- scratch (device globals) ----------------
__device__ __nv_bfloat16  g_qkv [(size_t)MROWS * 3 * C_];
__device__ float          g_x1  [(size_t)MROWS * C_];
__device__ __nv_bfloat16  g_xw  [(size_t)MROWS * C_];
__device__ __nv_bfloat16  g_at  [(size_t)MROWS * C_];
__device__ __nv_bfloat16  g_x2  [(size_t)MROWS * C_];
__device__ __nv_bfloat16  g_h1  [(size_t)MROWS * HID_];
__device__ __nv_bfloat16  g_wq[576 * 192];
__device__ __nv_bfloat16  g_wp[192 * 192];
__device__ __nv_bfloat16  g_w1[768 * 192];
__device__ __nv_bfloat16  g_w2[192 * 768];
__device__ float          g_battn[24 * 4096];   // [class(4) x head(6)][64x64] bias+mask

// ---------------- helpers ----------------
__device__ __forceinline__ uint32_t smem_u32(const void* p) {
    uint32_t a;
    asm("{ .reg .u64 t; cvta.to.shared.u64 t, %1; cvt.u32.u64 %0, t; }" : "=r"(a) : "l"(p));
    return a;
}
__device__ __forceinline__ float warp_sum(float v) {
#pragma unroll
    for (int o = 16; o; o >>= 1) v += __shfl_xor_sync(0xffffffffu, v, o);
    return v;
}
__device__ __forceinline__ float gelu_exact(float x) {
    return 0.5f * x * (1.0f + erff(x * 0.70710678118654752f));
}
__device__ __forceinline__ uint32_t pack_bf2(float a, float b) {
    __nv_bfloat162 t = __floats2bfloat162_rn(a, b);
    return *(uint32_t*)&t;
}
// FMA-only exp (exp2 poly)
__device__ __forceinline__ float fast_exp(float x) {
    float t = fmaxf(x * 1.4426950408889634f, -126.0f);
    float n = floorf(t);
    float f = t - n;
    float p = 1.8775767e-3f;
    p = fmaf(p, f, 8.9893397e-3f);
    p = fmaf(p, f, 5.5804084e-2f);
    p = fmaf(p, f, 2.4013971e-1f);
    p = fmaf(p, f, 6.9314718e-1f);
    p = fmaf(p, f, 1.0f);
    return p * __int_as_float(((int)n + 127) << 23);
}

__device__ __forceinline__ void ldmat4(uint32_t* r, uint32_t addr) {
    asm volatile("ldmatrix.sync.aligned.m8n8.x4.shared.b16 {%0,%1,%2,%3}, [%4];"
        : "=r"(r[0]), "=r"(r[1]), "=r"(r[2]), "=r"(r[3]) : "r"(addr));
}
__device__ __forceinline__ void ldmat2(uint32_t* r, uint32_t addr) {
    asm volatile("ldmatrix.sync.aligned.m8n8.x2.shared.b16 {%0,%1}, [%2];"
        : "=r"(r[0]), "=r"(r[1]) : "r"(addr));
}
__device__ __forceinline__ void ldmat2t(uint32_t* r, uint32_t addr) {
    asm volatile("ldmatrix.sync.aligned.m8n8.x2.trans.shared.b16 {%0,%1}, [%2];"
        : "=r"(r[0]), "=r"(r[1]) : "r"(addr));
}
__device__ __forceinline__ void mma16816(float* d, const uint32_t* a, const uint32_t* b) {
    asm volatile("mma.sync.aligned.m16n8k16.row.col.f32.bf16.bf16.f32 "
        "{%0,%1,%2,%3}, {%4,%5,%6,%7}, {%8,%9}, {%0,%1,%2,%3};"
        : "+f"(d[0]), "+f"(d[1]), "+f"(d[2]), "+f"(d[3])
        : "r"(a[0]), "r"(a[1]), "r"(a[2]), "r"(a[3]), "r"(b[0]), "r"(b[1]));
}
#define CP16(dst, src) \
    asm volatile("cp.async.cg.shared.global [%0], [%1], 16;" :: "r"(dst), "l"(src))
#define CP_COMMIT() asm volatile("cp.async.commit_group;" ::: "memory")
#define CP_WAIT(n)  asm volatile("cp.async.wait_group %0;" :: "n"(n) : "memory")

// ---------------- all weights fp32 -> bf16, one launch ----------------
#define SEG0 110592
#define SEG1 147456
#define SEG2 294912
#define SEG3 442368
__global__ void convert_all(const float* __restrict__ qkv_w, const float* __restrict__ proj_w,
                            const float* __restrict__ fc1_w, const float* __restrict__ fc2_w,
                            __nv_bfloat16* __restrict__ wq, __nv_bfloat16* __restrict__ wp,
                            __nv_bfloat16* __restrict__ w1, __nv_bfloat16* __restrict__ w2) {
    int i = blockIdx.x * blockDim.x + threadIdx.x;
    if (i < SEG0)       wq[i]        = __float2bfloat16(qkv_w[i]);
    else if (i < SEG1)  wp[i - SEG0] = __float2bfloat16(proj_w[i - SEG0]);
    else if (i < SEG2)  w1[i - SEG1] = __float2bfloat16(fc1_w[i - SEG1]);
    else if (i < SEG3)  w2[i - SEG2] = __float2bfloat16(fc2_w[i - SEG2]);
}

// ---------------- build attention bias+mask tables ----------------
__global__ void build_battn(const float* __restrict__ bt, float* __restrict__ battn) {
    int cls  = blockIdx.x / NHEAD;
    int head = blockIdx.x % NHEAD;
    float* T = battn + (size_t)blockIdx.x * 4096;
    for (int i = threadIdx.x; i < 4096; i += 256) {
        int r = i >> 6, c = i & 63;
        float v = -1e30f;
        if (r < 49 && c < 49) {
            int rr = ((cls & 1) ? ((r / 7 < 4) ? 1 : 2) : 0) * 3
                   + ((cls & 2) ? ((r % 7 < 4) ? 1 : 2) : 0);
            int rc = ((cls & 1) ? ((c / 7 < 4) ? 1 : 2) : 0) * 3
                   + ((cls & 2) ? ((c % 7 < 4) ? 1 : 2) : 0);
            int rel = (r / 7 - c / 7 + 6) * 13 + (r % 7 - c % 7 + 6);
            v = bt[rel * NHEAD + head] + ((rr != rc) ? -100.0f : 0.0f);
        }
        T[i] = v;
    }
}

// ---------------- LN1 + cyclic shift + window partition -> bf16 ----------------
__global__ void ln_partition_kernel(const float* __restrict__ x,
                                    const float* __restrict__ g,
                                    const float* __restrict__ bt,
                                    __nv_bfloat16* __restrict__ o) {
    int warp = (blockIdx.x * blockDim.x + threadIdx.x) >> 5;
    int lane = threadIdx.x & 31;
    if (warp >= MROWS) return;
    int n = warp % 49;
    int window = warp / 49;
    int wi = window & 63;
    int b  = window >> 6;
    int wh = wi >> 3, ww = wi & 7;
    int h = wh * 7 + n / 7 + 3; if (h >= 56) h -= 56;
    int w = ww * 7 + n % 7 + 3; if (w >= 56) w -= 56;
    const float* xi = x + ((size_t)b * 3136 + h * 56 + w) * 192;

    float v[6]; float s1 = 0.f;
#pragma unroll
    for (int j = 0; j < 6; j++) { v[j] = xi[lane + 32 * j]; s1 += v[j]; }
    s1 = warp_sum(s1);
    float mean = s1 * (1.0f / 192.0f);
    float s2 = 0.f;
#pragma unroll
    for (int j = 0; j < 6; j++) { float d = v[j] - mean; s2 += d * d; }
    s2 = warp_sum(s2);
    float inv = rsqrtf(s2 * (1.0f / 192.0f) + 1e-5f);
    size_t base = (size_t)warp * 192;
#pragma unroll
    for (int j = 0; j < 6; j++) {
        int c = lane + 32 * j;
        o[base + c] = __float2bfloat16((v[j] - mean) * inv * g[c] + bt[c]);
    }
}

// ---------------- LN2 -> bf16 ----------------
__global__ void ln_plain_kernel(const float* __restrict__ x,
                                const float* __restrict__ g,
                                const float* __restrict__ bt,
                                __nv_bfloat16* __restrict__ o) {
    int warp = (blockIdx.x * blockDim.x + threadIdx.x) >> 5;
    int lane = threadIdx.x & 31;
    if (warp >= MROWS) return;
    const float* xi = x + (size_t)warp * 192;
    float v[6]; float s1 = 0.f;
#pragma unroll
    for (int j = 0; j < 6; j++) { v[j] = xi[lane + 32 * j]; s1 += v[j]; }
    s1 = warp_sum(s1);
    float mean = s1 * (1.0f / 192.0f);
    float s2 = 0.f;
#pragma unroll
    for (int j = 0; j < 6; j++) { float d = v[j] - mean; s2 += d * d; }
    s2 = warp_sum(s2);
    float inv = rsqrtf(s2 * (1.0f / 192.0f) + 1e-5f);
    size_t base = (size_t)warp * 192;
#pragma unroll
    for (int j = 0; j < 6; j++) {
        int c = lane + 32 * j;
        o[base + c] = __float2bfloat16((v[j] - mean) * inv * g[c] + bt[c]);
    }
}

// ---------------- attention v3: HMMA (mma.sync bf16), one block per (window, head) ----------------
__global__ void __launch_bounds__(128)
attn_kernel(const __nv_bfloat16* __restrict__ qkv,
            const float* __restrict__ battn,
            __nv_bfloat16* __restrict__ outp) {
    __shared__ __align__(16) char sQ[64 * 80];
    __shared__ __align__(16) char sK[64 * 80];
    __shared__ __align__(16) char sV[64 * 80];
    __shared__ __align__(16) float sT[4096];

    const int head   = blockIdx.x % NHEAD;
    const int window = blockIdx.x / NHEAD;
    const int tid  = threadIdx.x;
    const int wrp  = tid >> 5;
    const int lane = tid & 31;

    const __nv_bfloat16* wbase = qkv + (size_t)window * 49 * 576 + head * 32;
    for (int i = tid; i < 588; i += 128) {
        int mat = i / 196, rem = i - mat * 196;
        int row = rem >> 2, ch = rem & 3;
        uint4 v = *(const uint4*)(wbase + (size_t)row * 576 + mat * 192 + ch * 8);
        char* dst = (mat == 0) ? sQ : (mat == 1) ? sK : sV;
        *(uint4*)(dst + row * 80 + ch * 16) = v;
    }
    for (int t = tid; t < 225; t += 128) {
        int mat = t / 75, rr = t - mat * 75;
        int row = 49 + rr / 5, ch = rr % 5;
        char* dst = (mat == 0) ? sQ : (mat == 1) ? sK : sV;
        *(uint4*)(dst + row * 80 + ch * 16) = make_uint4(0, 0, 0, 0);
    }
    {
        int wi = window & 63;
        int cls = ((wi >> 3) == 7 ? 1 : 0) + ((wi & 7) == 7 ? 2 : 0);
        const float* gT = battn + (size_t)(cls * NHEAD + head) * 4096;
        for (int i = tid; i < 1024; i += 128)
            *(float4*)(sT + i * 4) = *(const float4*)(gT + i * 4);
    }
    __syncthreads();

    const uint32_t sQu = smem_u32(sQ), sKu = smem_u32(sK), sVu = smem_u32(sV);

    uint32_t qa[2][4];
    {
        uint32_t qaddr = sQu + (uint32_t)(16 * wrp + (lane & 15)) * 80 + ((lane >> 4) * 16);
        ldmat4(qa[0], qaddr);
        ldmat4(qa[1], qaddr + 32);
    }
    float acc[8][4];
#pragma unroll
    for (int nt = 0; nt < 8; nt++)
#pragma unroll
        for (int q = 0; q < 4; q++) acc[nt][q] = 0.f;

    const uint32_t krow = (uint32_t)(lane & 7) * 80 + ((lane & 8) ? 16 : 0);
#pragma unroll
    for (int nt = 0; nt < 8; nt++) {
#pragma unroll
        for (int kk = 0; kk < 2; kk++) {
            uint32_t b[2];
            ldmat2(b, sKu + nt * 640 + kk * 32 + krow);
            mma16816(acc[nt], qa[kk], b);
        }
    }

    const float scale = 0.17677669529663687f;
    const int tr = lane >> 2;
    const int tc = (lane & 3) * 2;
    const float* T0 = sT + (16 * wrp + tr) * 64;
    const float* T1 = T0 + 8 * 64;
#pragma unroll
    for (int nt = 0; nt < 8; nt++) {
        int c = 8 * nt + tc;
        acc[nt][0] = fmaf(acc[nt][0], scale, T0[c]);
        acc[nt][1] = fmaf(acc[nt][1], scale, T0[c + 1]);
        acc[nt][2] = fmaf(acc[nt][2], scale, T1[c]);
        acc[nt][3] = fmaf(acc[nt][3], scale, T1[c + 1]);
    }

    float m0 = -1e30f, m1 = -1e30f;
#pragma unroll
    for (int nt = 0; nt < 8; nt++) {
        m0 = fmaxf(m0, fmaxf(acc[nt][0], acc[nt][1]));
        m1 = fmaxf(m1, fmaxf(acc[nt][2], acc[nt][3]));
    }
    m0 = fmaxf(m0, __shfl_xor_sync(0xffffffffu, m0, 1));
    m0 = fmaxf(m0, __shfl_xor_sync(0xffffffffu, m0, 2));
    m1 = fmaxf(m1, __shfl_xor_sync(0xffffffffu, m1, 1));
    m1 = fmaxf(m1, __shfl_xor_sync(0xffffffffu, m1, 2));
    float s0 = 0.f, s1 = 0.f;
#pragma unroll
    for (int nt = 0; nt < 8; nt++) {
        acc[nt][0] = fast_exp(acc[nt][0] - m0); s0 += acc[nt][0];
        acc[nt][1] = fast_exp(acc[nt][1] - m0); s0 += acc[nt][1];
        acc[nt][2] = fast_exp(acc[nt][2] - m1); s1 += acc[nt][2];
        acc[nt][3] = fast_exp(acc[nt][3] - m1); s1 += acc[nt][3];
    }
    s0 += __shfl_xor_sync(0xffffffffu, s0, 1);
    s0 += __shfl_xor_sync(0xffffffffu, s0, 2);
    s1 += __shfl_xor_sync(0xffffffffu, s1, 1);
    s1 += __shfl_xor_sync(0xffffffffu, s1, 2);
    const float i0 = __frcp_rn(s0), i1 = __frcp_rn(s1);

    uint32_t pa[4][4];
#pragma unroll
    for (int kk = 0; kk < 4; kk++) {
        pa[kk][0] = pack_bf2(acc[2 * kk][0] * i0, acc[2 * kk][1] * i0);
        pa[kk][1] = pack_bf2(acc[2 * kk][2] * i1, acc[2 * kk][3] * i1);
        pa[kk][2] = pack_bf2(acc[2 * kk + 1][0] * i0, acc[2 * kk + 1][1] * i0);
        pa[kk][3] = pack_bf2(acc[2 * kk + 1][2] * i1, acc[2 * kk + 1][3] * i1);
    }

    float o[4][4];
#pragma unroll
    for (int nt = 0; nt < 4; nt++)
#pragma unroll
        for (int q = 0; q < 4; q++) o[nt][q] = 0.f;

    const uint32_t vrow = sVu + (uint32_t)(lane & 15) * 80;
#pragma unroll
    for (int kk = 0; kk < 4; kk++) {
#pragma unroll
        for (int nt = 0; nt < 4; nt++) {
            uint32_t b[2];
            ldmat2t(b, vrow + kk * (16 * 80) + nt * 16);
            mma16816(o[nt], pa[kk], b);
        }
    }

    const int gr0 = 16 * wrp + tr, gr1 = gr0 + 8;
    __nv_bfloat16* ob = outp + (size_t)window * 49 * 192 + head * 32;
#pragma unroll
    for (int nt = 0; nt < 4; nt++) {
        int d = 8 * nt + tc;
        if (gr0 < 49) *(uint32_t*)(ob + (size_t)gr0 * 192 + d) = pack_bf2(o[nt][0], o[nt][1]);
        if (gr1 < 49) *(uint32_t*)(ob + (size_t)gr1 * 192 + d) = pack_bf2(o[nt][2], o[nt][3]);
    }
}

// ---------------- bf16 mma GEMM: BK=64, 3-stage cp.async, 1 sync/iter ----------------
// pitch 144B (36 words == 4 mod 32 -> ldmatrix conflict-free)
#define PITCH  144
#define SA_OFF 0
#define SB_OFF (128 * PITCH)                 // 18432
#define STAGE  (128 * PITCH + 64 * PITCH)    // 27648
#define SM_TOT (3 * STAGE)                   // 82944

enum { EPI_QKV = 0, EPI_PROJ = 1, EPI_GELU = 2, EPI_RES = 3 };

__device__ __forceinline__ size_t proj_row(int m) {
    int n = m % 49, window = m / 49;
    int wi = window & 63, b = window >> 6;
    int wh = wi >> 3, ww = wi & 7;
    int hh = wh * 7 + n / 7 + 3; if (hh >= 56) hh -= 56;
    int wc = ww * 7 + n % 7 + 3; if (wc >= 56) wc -= 56;
    return ((size_t)b * 3136 + (size_t)hh * 56 + wc) * 192;
}

template<int EPI>
__global__ void __launch_bounds__(256, 2)
gemm_mma(const __nv_bfloat16* __restrict__ A, const __nv_bfloat16* __restrict__ W,
         const float* __restrict__ bias, float* __restrict__ Cout,
         int Nn, int Ktot, const float* __restrict__ extra,
         __nv_bfloat16* __restrict__ obf) {
    extern __shared__ __align__(16) char sm[];
    const uint32_t sb = smem_u32(sm);
    const int tid  = threadIdx.x;
    const int wid  = tid >> 5;
    const int lane = tid & 31;
    const int warpM = wid >> 1;
    const int warpN = wid & 1;
    const int bm = blockIdx.y * 128;
    const int bn = blockIdx.x * 64;

    const __nv_bfloat16* A_b = A + (size_t)bm * Ktot;
    const __nv_bfloat16* W_b = W + (size_t)bn * Ktot;

    const uint32_t a_off = (uint32_t)(warpM * 32 + (lane & 15)) * PITCH + ((lane >> 4) * 16);
    const uint32_t b_off = (uint32_t)(warpN * 32 + ((lane >> 4) & 1) * 8 + (lane & 7)) * PITCH
                         + (((lane >> 3) & 1) * 16);

    float acc[2][4][4];
#pragma unroll
    for (int i = 0; i < 2; i++)
#pragma unroll
        for (int j = 0; j < 4; j++)
#pragma unroll
            for (int k = 0; k < 4; k++) acc[i][j][k] = 0.f;

    const int NK = Ktot >> 6;   // K / 64

    // stage loader: A 128x64 bf16 (1024x16B), B 64x64 (512x16B)
    auto stage_load = [&](int buf, int k0) {
        uint32_t d = sb + buf * STAGE;
#pragma unroll
        for (int i = 0; i < 4; i++) {
            int idx = tid + 256 * i;
            int row = idx >> 3, ch = idx & 7;
            CP16(d + SA_OFF + row * PITCH + ch * 16, A_b + (size_t)row * Ktot + k0 + ch * 8);
        }
#pragma unroll
        for (int i = 0; i < 2; i++) {
            int idx = tid + 256 * i;
            int row = idx >> 3, ch = idx & 7;
            CP16(d + SB_OFF + row * PITCH + ch * 16, W_b + (size_t)row * Ktot + k0 + ch * 8);
        }
        CP_COMMIT();
    };

    stage_load(0, 0);
    if (NK > 1) stage_load(1, 64);

    int buf = 0;
    for (int k = 0; k < NK; k++) {
        if (k + 1 < NK) { CP_WAIT(1); } else { CP_WAIT(0); }
        __syncthreads();
        if (k + 2 < NK) stage_load((buf + 2 >= 3) ? buf - 1 : buf + 2, (k + 2) << 6);

        const uint32_t soff = sb + buf * STAGE;
        const uint32_t aaddr = soff + SA_OFF + a_off;
        const uint32_t baddr = soff + SB_OFF + b_off;

#pragma unroll
        for (int kk = 0; kk < 4; kk++) {
            uint32_t a0[4], a1[4];
            ldmat4(a0, aaddr + kk * 32);
            ldmat4(a1, aaddr + 16 * PITCH + kk * 32);
#pragma unroll
            for (int ng = 0; ng < 2; ng++) {
                uint32_t bh[4];
                ldmat4(bh, baddr + ng * 16 * PITCH + kk * 32);
#pragma unroll
                for (int q = 0; q < 2; q++) {
                    int ni = ng * 2 + q;
                    mma16816(acc[0][ni], a0, bh + 2 * q);
                    mma16816(acc[1][ni], a1, bh + 2 * q);
                }
            }
        }
        buf = (buf + 1 >= 3) ? 0 : buf + 1;
    }

    // ---------------- epilogue ----------------
    const int lrow = lane >> 2, lcol = (lane & 3) * 2;
#pragma unroll
    for (int mi = 0; mi < 2; mi++) {
        int m0 = bm + warpM * 32 + mi * 16 + lrow;
        int m1 = m0 + 8;
        size_t r0, r1;
        if (EPI == EPI_PROJ) { r0 = proj_row(m0); r1 = proj_row(m1); }
        else { r0 = (size_t)m0 * Nn; r1 = (size_t)m1 * Nn; }
#pragma unroll
        for (int ni = 0; ni < 4; ni++) {
            int n = bn + warpN * 32 + ni * 8 + lcol;
            float bx = bias[n], by = bias[n + 1];
            float v0x = acc[mi][ni][0] + bx, v0y = acc[mi][ni][1] + by;
            float v1x = acc[mi][ni][2] + bx, v1y = acc[mi][ni][3] + by;
            if (EPI == EPI_QKV) {
                *(uint32_t*)(obf + r0 + n) = pack_bf2(v0x, v0y);
                *(uint32_t*)(obf + r1 + n) = pack_bf2(v1x, v1y);
            } else if (EPI == EPI_GELU) {
                *(uint32_t*)(obf + r0 + n) = pack_bf2(gelu_exact(v0x), gelu_exact(v0y));
                *(uint32_t*)(obf + r1 + n) = pack_bf2(gelu_exact(v1x), gelu_exact(v1y));
            } else {
                float2 e0 = *(const float2*)(extra + r0 + n);
                float2 e1 = *(const float2*)(extra + r1 + n);
                *(float2*)(Cout + r0 + n) = make_float2(v0x + e0.x, v0y + e0.y);
                *(float2*)(Cout + r1 + n) = make_float2(v1x + e1.x, v1y + e1.y);
            }
        }
    }
}

// ---------------- launch ----------------
extern "C" void kernel_launch(void* const* d_in, const int* in_sizes, int n_in,
                              void* d_out, int out_size) {
    const float* x      = (const float*)d_in[0];
    const float* g1     = (const float*)d_in[1];
    const float* b1     = (const float*)d_in[2];
    const float* qkv_w  = (const float*)d_in[3];
    const float* qkv_b  = (const float*)d_in[4];
    const float* proj_w = (const float*)d_in[5];
    const float* proj_b = (const float*)d_in[6];
    const float* bias_t = (const float*)d_in[7];
    const float* g2     = (const float*)d_in[8];
    const float* b2     = (const float*)d_in[9];
    const float* fc1_w  = (const float*)d_in[10];
    const float* fc1_b  = (const float*)d_in[11];
    const float* fc2_w  = (const float*)d_in[12];
    const float* fc2_b  = (const float*)d_in[13];
    float* out = (float*)d_out;

    float *p_x1, *p_battn;
    __nv_bfloat16 *p_qkv, *p_xw, *p_at, *p_x2, *p_h1, *p_wq, *p_wp, *p_w1, *p_w2;
    cudaGetSymbolAddress((void**)&p_qkv, g_qkv);
    cudaGetSymbolAddress((void**)&p_x1,  g_x1);
    cudaGetSymbolAddress((void**)&p_xw,  g_xw);
    cudaGetSymbolAddress((void**)&p_at,  g_at);
    cudaGetSymbolAddress((void**)&p_x2,  g_x2);
    cudaGetSymbolAddress((void**)&p_h1,  g_h1);
    cudaGetSymbolAddress((void**)&p_wq,  g_wq);
    cudaGetSymbolAddress((void**)&p_wp,  g_wp);
    cudaGetSymbolAddress((void**)&p_w1,  g_w1);
    cudaGetSymbolAddress((void**)&p_w2,  g_w2);
    cudaGetSymbolAddress((void**)&p_battn, g_battn);

    cudaFuncSetAttribute(gemm_mma<EPI_QKV>,  cudaFuncAttributeMaxDynamicSharedMemorySize, SM_TOT);
    cudaFuncSetAttribute(gemm_mma<EPI_PROJ>, cudaFuncAttributeMaxDynamicSharedMemorySize, SM_TOT);
    cudaFuncSetAttribute(gemm_mma<EPI_GELU>, cudaFuncAttributeMaxDynamicSharedMemorySize, SM_TOT);
    cudaFuncSetAttribute(gemm_mma<EPI_RES>,  cudaFuncAttributeMaxDynamicSharedMemorySize, SM_TOT);

    const int MB = MROWS / 128;  // 784

    convert_all<<<SEG3 / 256, 256>>>(qkv_w, proj_w, fc1_w, fc2_w, p_wq, p_wp, p_w1, p_w2);
    build_battn<<<24, 256>>>(bias_t, p_battn);
    ln_partition_kernel<<<MROWS / 8, 256>>>(x, g1, b1, p_xw);
    gemm_mma<EPI_QKV><<<dim3(576 / 64, MB), 256, SM_TOT>>>(p_xw, p_wq, qkv_b, nullptr, 576, 192, nullptr, p_qkv);
    attn_kernel<<<NWTOT * NHEAD, 128>>>(p_qkv, p_battn, p_at);
    gemm_mma<EPI_PROJ><<<dim3(192 / 64, MB), 256, SM_TOT>>>(p_at, p_wp, proj_b, p_x1, 192, 192, x, nullptr);
    ln_plain_kernel<<<MROWS / 8, 256>>>(p_x1, g2, b2, p_x2);
    gemm_mma<EPI_GELU><<<dim3(768 / 64, MB), 256, SM_TOT>>>(p_x2, p_w1, fc1_b, nullptr, 768, 192, nullptr, p_h1);
    gemm_mma<EPI_RES><<<dim3(192 / 64, MB), 256, SM_TOT>>>(p_h1, p_w2, fc2_b, out, 192, 768, p_x1, nullptr);
}

// round 9
// speedup vs baseline: 5.4406x; 1.0921x over previous
#include <cuda_runtime.h>
#include <cuda_bf16.h>
#include <math.h>
#include <stdint.h>

// ---------------- problem constants ----------------
#define C_     192
#define NHEAD  6
#define HID_   768
#define BATCH  32
#define NWTOT  2048
#define MROWS  100352      // NWTOT * 49

// ---------------- scratch (device globals) ----------------
__device__ __nv_bfloat16  g_qkv [(size_t)MROWS * 3 * C_];
__device__ float          g_x1  [(size_t)MROWS * C_];
__device__ __nv_bfloat16  g_xw  [(size_t)MROWS * C_];
__device__ __nv_bfloat16  g_at  [(size_t)MROWS * C_];
__device__ __nv_bfloat16  g_x2  [(size_t)MROWS * C_];
__device__ __nv_bfloat16  g_h1  [(size_t)MROWS * HID_];
__device__ __nv_bfloat16  g_wq[576 * 192];
__device__ __nv_bfloat16  g_wp[192 * 192];
__device__ __nv_bfloat16  g_w1[768 * 192];
__device__ __nv_bfloat16  g_w2[192 * 768];
__device__ float          g_battn[24 * 4096];   // [class(4) x head(6)][64x64] bias+mask

// ---------------- helpers ----------------
__device__ __forceinline__ uint32_t smem_u32(const void* p) {
    uint32_t a;
    asm("{ .reg .u64 t; cvta.to.shared.u64 t, %1; cvt.u32.u64 %0, t; }" : "=r"(a) : "l"(p));
    return a;
}
__device__ __forceinline__ float warp_sum(float v) {
#pragma unroll
    for (int o = 16; o; o >>= 1) v += __shfl_xor_sync(0xffffffffu, v, o);
    return v;
}
__device__ __forceinline__ float gelu_exact(float x) {
    return 0.5f * x * (1.0f + erff(x * 0.70710678118654752f));
}
__device__ __forceinline__ uint32_t pack_bf2(float a, float b) {
    __nv_bfloat162 t = __floats2bfloat162_rn(a, b);
    return *(uint32_t*)&t;
}
// FMA-only exp (exp2 poly)
__device__ __forceinline__ float fast_exp(float x) {
    float t = fmaxf(x * 1.4426950408889634f, -126.0f);
    float n = floorf(t);
    float f = t - n;
    float p = 1.8775767e-3f;
    p = fmaf(p, f, 8.9893397e-3f);
    p = fmaf(p, f, 5.5804084e-2f);
    p = fmaf(p, f, 2.4013971e-1f);
    p = fmaf(p, f, 6.9314718e-1f);
    p = fmaf(p, f, 1.0f);
    return p * __int_as_float(((int)n + 127) << 23);
}

__device__ __forceinline__ void ldmat4(uint32_t* r, uint32_t addr) {
    asm volatile("ldmatrix.sync.aligned.m8n8.x4.shared.b16 {%0,%1,%2,%3}, [%4];"
        : "=r"(r[0]), "=r"(r[1]), "=r"(r[2]), "=r"(r[3]) : "r"(addr));
}
__device__ __forceinline__ void ldmat2(uint32_t* r, uint32_t addr) {
    asm volatile("ldmatrix.sync.aligned.m8n8.x2.shared.b16 {%0,%1}, [%2];"
        : "=r"(r[0]), "=r"(r[1]) : "r"(addr));
}
__device__ __forceinline__ void ldmat2t(uint32_t* r, uint32_t addr) {
    asm volatile("ldmatrix.sync.aligned.m8n8.x2.trans.shared.b16 {%0,%1}, [%2];"
        : "=r"(r[0]), "=r"(r[1]) : "r"(addr));
}
__device__ __forceinline__ void mma16816(float* d, const uint32_t* a, const uint32_t* b) {
    asm volatile("mma.sync.aligned.m16n8k16.row.col.f32.bf16.bf16.f32 "
        "{%0,%1,%2,%3}, {%4,%5,%6,%7}, {%8,%9}, {%0,%1,%2,%3};"
        : "+f"(d[0]), "+f"(d[1]), "+f"(d[2]), "+f"(d[3])
        : "r"(a[0]), "r"(a[1]), "r"(a[2]), "r"(a[3]), "r"(b[0]), "r"(b[1]));
}
#define CP16(dst, src) \
    asm volatile("cp.async.cg.shared.global [%0], [%1], 16;" :: "r"(dst), "l"(src))
#define CP_COMMIT() asm volatile("cp.async.commit_group;" ::: "memory")
#define CP_WAIT(n)  asm volatile("cp.async.wait_group %0;" :: "n"(n) : "memory")

// ---------------- all weights fp32 -> bf16, one launch ----------------
#define SEG0 110592
#define SEG1 147456
#define SEG2 294912
#define SEG3 442368
__global__ void convert_all(const float* __restrict__ qkv_w, const float* __restrict__ proj_w,
                            const float* __restrict__ fc1_w, const float* __restrict__ fc2_w,
                            __nv_bfloat16* __restrict__ wq, __nv_bfloat16* __restrict__ wp,
                            __nv_bfloat16* __restrict__ w1, __nv_bfloat16* __restrict__ w2) {
    int i = blockIdx.x * blockDim.x + threadIdx.x;
    if (i < SEG0)       wq[i]        = __float2bfloat16(qkv_w[i]);
    else if (i < SEG1)  wp[i - SEG0] = __float2bfloat16(proj_w[i - SEG0]);
    else if (i < SEG2)  w1[i - SEG1] = __float2bfloat16(fc1_w[i - SEG1]);
    else if (i < SEG3)  w2[i - SEG2] = __float2bfloat16(fc2_w[i - SEG2]);
}

// ---------------- build attention bias+mask tables ----------------
__global__ void build_battn(const float* __restrict__ bt, float* __restrict__ battn) {
    int cls  = blockIdx.x / NHEAD;
    int head = blockIdx.x % NHEAD;
    float* T = battn + (size_t)blockIdx.x * 4096;
    for (int i = threadIdx.x; i < 4096; i += 256) {
        int r = i >> 6, c = i & 63;
        float v = -1e30f;
        if (r < 49 && c < 49) {
            int rr = ((cls & 1) ? ((r / 7 < 4) ? 1 : 2) : 0) * 3
                   + ((cls & 2) ? ((r % 7 < 4) ? 1 : 2) : 0);
            int rc = ((cls & 1) ? ((c / 7 < 4) ? 1 : 2) : 0) * 3
                   + ((cls & 2) ? ((c % 7 < 4) ? 1 : 2) : 0);
            int rel = (r / 7 - c / 7 + 6) * 13 + (r % 7 - c % 7 + 6);
            v = bt[rel * NHEAD + head] + ((rr != rc) ? -100.0f : 0.0f);
        }
        T[i] = v;
    }
}

// ---------------- LN1 + cyclic shift + window partition -> bf16 ----------------
__global__ void ln_partition_kernel(const float* __restrict__ x,
                                    const float* __restrict__ g,
                                    const float* __restrict__ bt,
                                    __nv_bfloat16* __restrict__ o) {
    int warp = (blockIdx.x * blockDim.x + threadIdx.x) >> 5;
    int lane = threadIdx.x & 31;
    if (warp >= MROWS) return;
    int n = warp % 49;
    int window = warp / 49;
    int wi = window & 63;
    int b  = window >> 6;
    int wh = wi >> 3, ww = wi & 7;
    int h = wh * 7 + n / 7 + 3; if (h >= 56) h -= 56;
    int w = ww * 7 + n % 7 + 3; if (w >= 56) w -= 56;
    const float* xi = x + ((size_t)b * 3136 + h * 56 + w) * 192;

    float v[6]; float s1 = 0.f;
#pragma unroll
    for (int j = 0; j < 6; j++) { v[j] = xi[lane + 32 * j]; s1 += v[j]; }
    s1 = warp_sum(s1);
    float mean = s1 * (1.0f / 192.0f);
    float s2 = 0.f;
#pragma unroll
    for (int j = 0; j < 6; j++) { float d = v[j] - mean; s2 += d * d; }
    s2 = warp_sum(s2);
    float inv = rsqrtf(s2 * (1.0f / 192.0f) + 1e-5f);
    size_t base = (size_t)warp * 192;
#pragma unroll
    for (int j = 0; j < 6; j++) {
        int c = lane + 32 * j;
        o[base + c] = __float2bfloat16((v[j] - mean) * inv * g[c] + bt[c]);
    }
}

// ---------------- LN2 -> bf16 ----------------
__global__ void ln_plain_kernel(const float* __restrict__ x,
                                const float* __restrict__ g,
                                const float* __restrict__ bt,
                                __nv_bfloat16* __restrict__ o) {
    int warp = (blockIdx.x * blockDim.x + threadIdx.x) >> 5;
    int lane = threadIdx.x & 31;
    if (warp >= MROWS) return;
    const float* xi = x + (size_t)warp * 192;
    float v[6]; float s1 = 0.f;
#pragma unroll
    for (int j = 0; j < 6; j++) { v[j] = xi[lane + 32 * j]; s1 += v[j]; }
    s1 = warp_sum(s1);
    float mean = s1 * (1.0f / 192.0f);
    float s2 = 0.f;
#pragma unroll
    for (int j = 0; j < 6; j++) { float d = v[j] - mean; s2 += d * d; }
    s2 = warp_sum(s2);
    float inv = rsqrtf(s2 * (1.0f / 192.0f) + 1e-5f);
    size_t base = (size_t)warp * 192;
#pragma unroll
    for (int j = 0; j < 6; j++) {
        int c = lane + 32 * j;
        o[base + c] = __float2bfloat16((v[j] - mean) * inv * g[c] + bt[c]);
    }
}

// ---------------- attention: HMMA (mma.sync bf16), one block per (window, head) ----------------
__global__ void __launch_bounds__(128)
attn_kernel(const __nv_bfloat16* __restrict__ qkv,
            const float* __restrict__ battn,
            __nv_bfloat16* __restrict__ outp) {
    __shared__ __align__(16) char sQ[64 * 80];
    __shared__ __align__(16) char sK[64 * 80];
    __shared__ __align__(16) char sV[64 * 80];
    __shared__ __align__(16) float sT[4096];

    const int head   = blockIdx.x % NHEAD;
    const int window = blockIdx.x / NHEAD;
    const int tid  = threadIdx.x;
    const int wrp  = tid >> 5;
    const int lane = tid & 31;

    const __nv_bfloat16* wbase = qkv + (size_t)window * 49 * 576 + head * 32;
    for (int i = tid; i < 588; i += 128) {
        int mat = i / 196, rem = i - mat * 196;
        int row = rem >> 2, ch = rem & 3;
        uint4 v = *(const uint4*)(wbase + (size_t)row * 576 + mat * 192 + ch * 8);
        char* dst = (mat == 0) ? sQ : (mat == 1) ? sK : sV;
        *(uint4*)(dst + row * 80 + ch * 16) = v;
    }
    for (int t = tid; t < 225; t += 128) {
        int mat = t / 75, rr = t - mat * 75;
        int row = 49 + rr / 5, ch = rr % 5;
        char* dst = (mat == 0) ? sQ : (mat == 1) ? sK : sV;
        *(uint4*)(dst + row * 80 + ch * 16) = make_uint4(0, 0, 0, 0);
    }
    {
        int wi = window & 63;
        int cls = ((wi >> 3) == 7 ? 1 : 0) + ((wi & 7) == 7 ? 2 : 0);
        const float* gT = battn + (size_t)(cls * NHEAD + head) * 4096;
        for (int i = tid; i < 1024; i += 128)
            *(float4*)(sT + i * 4) = *(const float4*)(gT + i * 4);
    }
    __syncthreads();

    const uint32_t sQu = smem_u32(sQ), sKu = smem_u32(sK), sVu = smem_u32(sV);

    uint32_t qa[2][4];
    {
        uint32_t qaddr = sQu + (uint32_t)(16 * wrp + (lane & 15)) * 80 + ((lane >> 4) * 16);
        ldmat4(qa[0], qaddr);
        ldmat4(qa[1], qaddr + 32);
    }
    float acc[8][4];
#pragma unroll
    for (int nt = 0; nt < 8; nt++)
#pragma unroll
        for (int q = 0; q < 4; q++) acc[nt][q] = 0.f;

    const uint32_t krow = (uint32_t)(lane & 7) * 80 + ((lane & 8) ? 16 : 0);
#pragma unroll
    for (int nt = 0; nt < 8; nt++) {
#pragma unroll
        for (int kk = 0; kk < 2; kk++) {
            uint32_t b[2];
            ldmat2(b, sKu + nt * 640 + kk * 32 + krow);
            mma16816(acc[nt], qa[kk], b);
        }
    }

    const float scale = 0.17677669529663687f;
    const int tr = lane >> 2;
    const int tc = (lane & 3) * 2;
    const float* T0 = sT + (16 * wrp + tr) * 64;
    const float* T1 = T0 + 8 * 64;
#pragma unroll
    for (int nt = 0; nt < 8; nt++) {
        int c = 8 * nt + tc;
        acc[nt][0] = fmaf(acc[nt][0], scale, T0[c]);
        acc[nt][1] = fmaf(acc[nt][1], scale, T0[c + 1]);
        acc[nt][2] = fmaf(acc[nt][2], scale, T1[c]);
        acc[nt][3] = fmaf(acc[nt][3], scale, T1[c + 1]);
    }

    float m0 = -1e30f, m1 = -1e30f;
#pragma unroll
    for (int nt = 0; nt < 8; nt++) {
        m0 = fmaxf(m0, fmaxf(acc[nt][0], acc[nt][1]));
        m1 = fmaxf(m1, fmaxf(acc[nt][2], acc[nt][3]));
    }
    m0 = fmaxf(m0, __shfl_xor_sync(0xffffffffu, m0, 1));
    m0 = fmaxf(m0, __shfl_xor_sync(0xffffffffu, m0, 2));
    m1 = fmaxf(m1, __shfl_xor_sync(0xffffffffu, m1, 1));
    m1 = fmaxf(m1, __shfl_xor_sync(0xffffffffu, m1, 2));
    float s0 = 0.f, s1 = 0.f;
#pragma unroll
    for (int nt = 0; nt < 8; nt++) {
        acc[nt][0] = fast_exp(acc[nt][0] - m0); s0 += acc[nt][0];
        acc[nt][1] = fast_exp(acc[nt][1] - m0); s0 += acc[nt][1];
        acc[nt][2] = fast_exp(acc[nt][2] - m1); s1 += acc[nt][2];
        acc[nt][3] = fast_exp(acc[nt][3] - m1); s1 += acc[nt][3];
    }
    s0 += __shfl_xor_sync(0xffffffffu, s0, 1);
    s0 += __shfl_xor_sync(0xffffffffu, s0, 2);
    s1 += __shfl_xor_sync(0xffffffffu, s1, 1);
    s1 += __shfl_xor_sync(0xffffffffu, s1, 2);
    const float i0 = __frcp_rn(s0), i1 = __frcp_rn(s1);

    uint32_t pa[4][4];
#pragma unroll
    for (int kk = 0; kk < 4; kk++) {
        pa[kk][0] = pack_bf2(acc[2 * kk][0] * i0, acc[2 * kk][1] * i0);
        pa[kk][1] = pack_bf2(acc[2 * kk][2] * i1, acc[2 * kk][3] * i1);
        pa[kk][2] = pack_bf2(acc[2 * kk + 1][0] * i0, acc[2 * kk + 1][1] * i0);
        pa[kk][3] = pack_bf2(acc[2 * kk + 1][2] * i1, acc[2 * kk + 1][3] * i1);
    }

    float o[4][4];
#pragma unroll
    for (int nt = 0; nt < 4; nt++)
#pragma unroll
        for (int q = 0; q < 4; q++) o[nt][q] = 0.f;

    const uint32_t vrow = sVu + (uint32_t)(lane & 15) * 80;
#pragma unroll
    for (int kk = 0; kk < 4; kk++) {
#pragma unroll
        for (int nt = 0; nt < 4; nt++) {
            uint32_t b[2];
            ldmat2t(b, vrow + kk * (16 * 80) + nt * 16);
            mma16816(o[nt], pa[kk], b);
        }
    }

    const int gr0 = 16 * wrp + tr, gr1 = gr0 + 8;
    __nv_bfloat16* ob = outp + (size_t)window * 49 * 192 + head * 32;
#pragma unroll
    for (int nt = 0; nt < 4; nt++) {
        int d = 8 * nt + tc;
        if (gr0 < 49) *(uint32_t*)(ob + (size_t)gr0 * 192 + d) = pack_bf2(o[nt][0], o[nt][1]);
        if (gr1 < 49) *(uint32_t*)(ob + (size_t)gr1 * 192 + d) = pack_bf2(o[nt][2], o[nt][3]);
    }
}

// ---------------- bf16 mma GEMM: BK=64, 3-stage, swizzled 128B pitch, 3 CTAs/SM ----------------
// physical 16B chunk = ch ^ (row & 7): ldmatrix conflict-free at 128B pitch
#define SB_OFF 16384                  // 128 rows * 128B
#define STAGE  24576                  // + 64 rows * 128B
#define SM_TOT (3 * STAGE)            // 73728

enum { EPI_QKV = 0, EPI_PROJ = 1, EPI_GELU = 2, EPI_RES = 3 };

__device__ __forceinline__ size_t proj_row(int m) {
    int n = m % 49, window = m / 49;
    int wi = window & 63, b = window >> 6;
    int wh = wi >> 3, ww = wi & 7;
    int hh = wh * 7 + n / 7 + 3; if (hh >= 56) hh -= 56;
    int wc = ww * 7 + n % 7 + 3; if (wc >= 56) wc -= 56;
    return ((size_t)b * 3136 + (size_t)hh * 56 + wc) * 192;
}

template<int EPI>
__global__ void __launch_bounds__(256, 3)
gemm_mma(const __nv_bfloat16* __restrict__ A, const __nv_bfloat16* __restrict__ W,
         const float* __restrict__ bias, float* __restrict__ Cout,
         int Nn, int Ktot, const float* __restrict__ extra,
         __nv_bfloat16* __restrict__ obf) {
    extern __shared__ __align__(16) char sm[];
    const uint32_t sb = smem_u32(sm);
    const int tid  = threadIdx.x;
    const int wid  = tid >> 5;
    const int lane = tid & 31;
    const int warpM = wid >> 1;
    const int warpN = wid & 1;
    const int bm = blockIdx.y * 128;
    const int bn = blockIdx.x * 64;

    const __nv_bfloat16* A_b = A + (size_t)bm * Ktot;
    const __nv_bfloat16* W_b = W + (size_t)bn * Ktot;

    // ldmatrix bases (swizzled): row*128 + ((chunk ^ (row&7)) << 4)
    const int rowA = warpM * 32 + (lane & 15);
    const uint32_t aBase = (uint32_t)rowA * 128;
    const int axp = (lane >> 4) ^ (rowA & 7);         // chunk-xor for A (hi-bit folded)
    const int rowB = warpN * 32 + ((lane >> 4) & 1) * 8 + (lane & 7);
    const uint32_t bBase = SB_OFF + (uint32_t)rowB * 128;
    const int bxp = ((lane >> 3) & 1) ^ (lane & 7);   // chunk-xor for B (row&7 == lane&7)

    float acc[2][4][4];
#pragma unroll
    for (int i = 0; i < 2; i++)
#pragma unroll
        for (int j = 0; j < 4; j++)
#pragma unroll
            for (int k = 0; k < 4; k++) acc[i][j][k] = 0.f;

    const int NK = Ktot >> 6;   // K / 64

    // stage loader: A 128x64 bf16 (1024x16B), B 64x64 (512x16B), swizzled
    auto stage_load = [&](int buf, int k0) {
        uint32_t d = sb + buf * STAGE;
#pragma unroll
        for (int i = 0; i < 4; i++) {
            int idx = tid + 256 * i;
            int row = idx >> 3, ch = idx & 7;
            CP16(d + row * 128 + ((ch ^ (row & 7)) << 4), A_b + (size_t)row * Ktot + k0 + ch * 8);
        }
#pragma unroll
        for (int i = 0; i < 2; i++) {
            int idx = tid + 256 * i;
            int row = idx >> 3, ch = idx & 7;
            CP16(d + SB_OFF + row * 128 + ((ch ^ (row & 7)) << 4), W_b + (size_t)row * Ktot + k0 + ch * 8);
        }
        CP_COMMIT();
    };

    stage_load(0, 0);
    if (NK > 1) stage_load(1, 64);

    int buf = 0;
    for (int k = 0; k < NK; k++) {
        if (k + 1 < NK) { CP_WAIT(1); } else { CP_WAIT(0); }
        __syncthreads();
        if (k + 2 < NK) stage_load((buf + 2 >= 3) ? buf - 1 : buf + 2, (k + 2) << 6);

        const uint32_t soff = sb + buf * STAGE;
        const uint32_t aaddr = soff + aBase;
        const uint32_t baddr = soff + bBase;

#pragma unroll
        for (int kk = 0; kk < 4; kk++) {
            const uint32_t xa = (uint32_t)((2 * kk) ^ axp) << 4;   // compile-time 2kk folds into LOP
            const uint32_t xb = (uint32_t)((2 * kk) ^ bxp) << 4;
            uint32_t a0[4], a1[4];
            ldmat4(a0, aaddr + xa);
            ldmat4(a1, aaddr + 2048 + xa);          // +16 rows (swizzle invariant: 16 % 8 == 0)
#pragma unroll
            for (int ng = 0; ng < 2; ng++) {
                uint32_t bh[4];
                ldmat4(bh, baddr + ng * 2048 + xb);
#pragma unroll
                for (int q = 0; q < 2; q++) {
                    int ni = ng * 2 + q;
                    mma16816(acc[0][ni], a0, bh + 2 * q);
                    mma16816(acc[1][ni], a1, bh + 2 * q);
                }
            }
        }
        buf = (buf + 1 >= 3) ? 0 : buf + 1;
    }

    // ---------------- epilogue ----------------
    const int lrow = lane >> 2, lcol = (lane & 3) * 2;
#pragma unroll
    for (int mi = 0; mi < 2; mi++) {
        int m0 = bm + warpM * 32 + mi * 16 + lrow;
        int m1 = m0 + 8;
        size_t r0, r1;
        if (EPI == EPI_PROJ) { r0 = proj_row(m0); r1 = proj_row(m1); }
        else { r0 = (size_t)m0 * Nn; r1 = (size_t)m1 * Nn; }
#pragma unroll
        for (int ni = 0; ni < 4; ni++) {
            int n = bn + warpN * 32 + ni * 8 + lcol;
            float bx = bias[n], by = bias[n + 1];
            float v0x = acc[mi][ni][0] + bx, v0y = acc[mi][ni][1] + by;
            float v1x = acc[mi][ni][2] + bx, v1y = acc[mi][ni][3] + by;
            if (EPI == EPI_QKV) {
                *(uint32_t*)(obf + r0 + n) = pack_bf2(v0x, v0y);
                *(uint32_t*)(obf + r1 + n) = pack_bf2(v1x, v1y);
            } else if (EPI == EPI_GELU) {
                *(uint32_t*)(obf + r0 + n) = pack_bf2(gelu_exact(v0x), gelu_exact(v0y));
                *(uint32_t*)(obf + r1 + n) = pack_bf2(gelu_exact(v1x), gelu_exact(v1y));
            } else {
                float2 e0 = *(const float2*)(extra + r0 + n);
                float2 e1 = *(const float2*)(extra + r1 + n);
                *(float2*)(Cout + r0 + n) = make_float2(v0x + e0.x, v0y + e0.y);
                *(float2*)(Cout + r1 + n) = make_float2(v1x + e1.x, v1y + e1.y);
            }
        }
    }
}

// ---------------- launch ----------------
extern "C" void kernel_launch(void* const* d_in, const int* in_sizes, int n_in,
                              void* d_out, int out_size) {
    const float* x      = (const float*)d_in[0];
    const float* g1     = (const float*)d_in[1];
    const float* b1     = (const float*)d_in[2];
    const float* qkv_w  = (const float*)d_in[3];
    const float* qkv_b  = (const float*)d_in[4];
    const float* proj_w = (const float*)d_in[5];
    const float* proj_b = (const float*)d_in[6];
    const float* bias_t = (const float*)d_in[7];
    const float* g2     = (const float*)d_in[8];
    const float* b2     = (const float*)d_in[9];
    const float* fc1_w  = (const float*)d_in[10];
    const float* fc1_b  = (const float*)d_in[11];
    const float* fc2_w  = (const float*)d_in[12];
    const float* fc2_b  = (const float*)d_in[13];
    float* out = (float*)d_out;

    float *p_x1, *p_battn;
    __nv_bfloat16 *p_qkv, *p_xw, *p_at, *p_x2, *p_h1, *p_wq, *p_wp, *p_w1, *p_w2;
    cudaGetSymbolAddress((void**)&p_qkv, g_qkv);
    cudaGetSymbolAddress((void**)&p_x1,  g_x1);
    cudaGetSymbolAddress((void**)&p_xw,  g_xw);
    cudaGetSymbolAddress((void**)&p_at,  g_at);
    cudaGetSymbolAddress((void**)&p_x2,  g_x2);
    cudaGetSymbolAddress((void**)&p_h1,  g_h1);
    cudaGetSymbolAddress((void**)&p_wq,  g_wq);
    cudaGetSymbolAddress((void**)&p_wp,  g_wp);
    cudaGetSymbolAddress((void**)&p_w1,  g_w1);
    cudaGetSymbolAddress((void**)&p_w2,  g_w2);
    cudaGetSymbolAddress((void**)&p_battn, g_battn);

    cudaFuncSetAttribute(gemm_mma<EPI_QKV>,  cudaFuncAttributeMaxDynamicSharedMemorySize, SM_TOT);
    cudaFuncSetAttribute(gemm_mma<EPI_PROJ>, cudaFuncAttributeMaxDynamicSharedMemorySize, SM_TOT);
    cudaFuncSetAttribute(gemm_mma<EPI_GELU>, cudaFuncAttributeMaxDynamicSharedMemorySize, SM_TOT);
    cudaFuncSetAttribute(gemm_mma<EPI_RES>,  cudaFuncAttributeMaxDynamicSharedMemorySize, SM_TOT);

    const int MB = MROWS / 128;  // 784

    convert_all<<<SEG3 / 256, 256>>>(qkv_w, proj_w, fc1_w, fc2_w, p_wq, p_wp, p_w1, p_w2);
    build_battn<<<24, 256>>>(bias_t, p_battn);
    ln_partition_kernel<<<MROWS / 8, 256>>>(x, g1, b1, p_xw);
    gemm_mma<EPI_QKV><<<dim3(576 / 64, MB), 256, SM_TOT>>>(p_xw, p_wq, qkv_b, nullptr, 576, 192, nullptr, p_qkv);
    attn_kernel<<<NWTOT * NHEAD, 128>>>(p_qkv, p_battn, p_at);
    gemm_mma<EPI_PROJ><<<dim3(192 / 64, MB), 256, SM_TOT>>>(p_at, p_wp, proj_b, p_x1, 192, 192, x, nullptr);
    ln_plain_kernel<<<MROWS / 8, 256>>>(p_x1, g2, b2, p_x2);
    gemm_mma<EPI_GELU><<<dim3(768 / 64, MB), 256, SM_TOT>>>(p_x2, p_w1, fc1_b, nullptr, 768, 192, nullptr, p_h1);
    gemm_mma<EPI_RES><<<dim3(192 / 64, MB), 256, SM_TOT>>>(p_h1, p_w2, fc2_b, out, 192, 768, p_x1, nullptr);
}

// round 10
// speedup vs baseline: 5.7662x; 1.0598x over previous
#include <cuda_runtime.h>
#include <cuda_bf16.h>
#include <math.h>
#include <stdint.h>

// ---------------- problem constants ----------------
#define C_     192
#define NHEAD  6
#define HID_   768
#define BATCH  32
#define NWTOT  2048
#define MROWS  100352      // NWTOT * 49

// ---------------- scratch (device globals) ----------------
__device__ __nv_bfloat16  g_qkv [(size_t)MROWS * 3 * C_];
__device__ float          g_x1  [(size_t)MROWS * C_];
__device__ __nv_bfloat16  g_xw  [(size_t)MROWS * C_];
__device__ __nv_bfloat16  g_at  [(size_t)MROWS * C_];
__device__ __nv_bfloat16  g_x2  [(size_t)MROWS * C_];
__device__ __nv_bfloat16  g_h1  [(size_t)MROWS * HID_];
__device__ __nv_bfloat16  g_wq[576 * 192];
__device__ __nv_bfloat16  g_wp[192 * 192];
__device__ __nv_bfloat16  g_w1[768 * 192];
__device__ __nv_bfloat16  g_w2[192 * 768];
__device__ __nv_bfloat16  g_battn[24 * 4096];   // [class(4) x head(6)][64x64] bias+mask (bf16)

// ---------------- helpers ----------------
__device__ __forceinline__ uint32_t smem_u32(const void* p) {
    uint32_t a;
    asm("{ .reg .u64 t; cvta.to.shared.u64 t, %1; cvt.u32.u64 %0, t; }" : "=r"(a) : "l"(p));
    return a;
}
__device__ __forceinline__ float warp_sum(float v) {
#pragma unroll
    for (int o = 16; o; o >>= 1) v += __shfl_xor_sync(0xffffffffu, v, o);
    return v;
}
__device__ __forceinline__ float gelu_exact(float x) {
    return 0.5f * x * (1.0f + erff(x * 0.70710678118654752f));
}
__device__ __forceinline__ uint32_t pack_bf2(float a, float b) {
    __nv_bfloat162 t = __floats2bfloat162_rn(a, b);
    return *(uint32_t*)&t;
}
// FMA-only exp (exp2 poly)
__device__ __forceinline__ float fast_exp(float x) {
    float t = fmaxf(x * 1.4426950408889634f, -126.0f);
    float n = floorf(t);
    float f = t - n;
    float p = 1.8775767e-3f;
    p = fmaf(p, f, 8.9893397e-3f);
    p = fmaf(p, f, 5.5804084e-2f);
    p = fmaf(p, f, 2.4013971e-1f);
    p = fmaf(p, f, 6.9314718e-1f);
    p = fmaf(p, f, 1.0f);
    return p * __int_as_float(((int)n + 127) << 23);
}

__device__ __forceinline__ void ldmat4(uint32_t* r, uint32_t addr) {
    asm volatile("ldmatrix.sync.aligned.m8n8.x4.shared.b16 {%0,%1,%2,%3}, [%4];"
        : "=r"(r[0]), "=r"(r[1]), "=r"(r[2]), "=r"(r[3]) : "r"(addr));
}
__device__ __forceinline__ void ldmat2(uint32_t* r, uint32_t addr) {
    asm volatile("ldmatrix.sync.aligned.m8n8.x2.shared.b16 {%0,%1}, [%2];"
        : "=r"(r[0]), "=r"(r[1]) : "r"(addr));
}
__device__ __forceinline__ void ldmat2t(uint32_t* r, uint32_t addr) {
    asm volatile("ldmatrix.sync.aligned.m8n8.x2.trans.shared.b16 {%0,%1}, [%2];"
        : "=r"(r[0]), "=r"(r[1]) : "r"(addr));
}
__device__ __forceinline__ void mma16816(float* d, const uint32_t* a, const uint32_t* b) {
    asm volatile("mma.sync.aligned.m16n8k16.row.col.f32.bf16.bf16.f32 "
        "{%0,%1,%2,%3}, {%4,%5,%6,%7}, {%8,%9}, {%0,%1,%2,%3};"
        : "+f"(d[0]), "+f"(d[1]), "+f"(d[2]), "+f"(d[3])
        : "r"(a[0]), "r"(a[1]), "r"(a[2]), "r"(a[3]), "r"(b[0]), "r"(b[1]));
}
#define CP16(dst, src) \
    asm volatile("cp.async.cg.shared.global [%0], [%1], 16;" :: "r"(dst), "l"(src))
#define CP_COMMIT() asm volatile("cp.async.commit_group;" ::: "memory")
#define CP_WAIT(n)  asm volatile("cp.async.wait_group %0;" :: "n"(n) : "memory")

// ---------------- all weights fp32 -> bf16, one launch ----------------
#define SEG0 110592
#define SEG1 147456
#define SEG2 294912
#define SEG3 442368
__global__ void convert_all(const float* __restrict__ qkv_w, const float* __restrict__ proj_w,
                            const float* __restrict__ fc1_w, const float* __restrict__ fc2_w,
                            __nv_bfloat16* __restrict__ wq, __nv_bfloat16* __restrict__ wp,
                            __nv_bfloat16* __restrict__ w1, __nv_bfloat16* __restrict__ w2) {
    int i = blockIdx.x * blockDim.x + threadIdx.x;
    if (i < SEG0)       wq[i]        = __float2bfloat16(qkv_w[i]);
    else if (i < SEG1)  wp[i - SEG0] = __float2bfloat16(proj_w[i - SEG0]);
    else if (i < SEG2)  w1[i - SEG1] = __float2bfloat16(fc1_w[i - SEG1]);
    else if (i < SEG3)  w2[i - SEG2] = __float2bfloat16(fc2_w[i - SEG2]);
}

// ---------------- build attention bias+mask tables (bf16) ----------------
__global__ void build_battn(const float* __restrict__ bt, __nv_bfloat16* __restrict__ battn) {
    int cls  = blockIdx.x / NHEAD;
    int head = blockIdx.x % NHEAD;
    __nv_bfloat16* T = battn + (size_t)blockIdx.x * 4096;
    for (int i = threadIdx.x; i < 4096; i += 256) {
        int r = i >> 6, c = i & 63;
        float v = -1e30f;
        if (r < 49 && c < 49) {
            int rr = ((cls & 1) ? ((r / 7 < 4) ? 1 : 2) : 0) * 3
                   + ((cls & 2) ? ((r % 7 < 4) ? 1 : 2) : 0);
            int rc = ((cls & 1) ? ((c / 7 < 4) ? 1 : 2) : 0) * 3
                   + ((cls & 2) ? ((c % 7 < 4) ? 1 : 2) : 0);
            int rel = (r / 7 - c / 7 + 6) * 13 + (r % 7 - c % 7 + 6);
            v = bt[rel * NHEAD + head] + ((rr != rc) ? -100.0f : 0.0f);
        }
        T[i] = __float2bfloat16(v);
    }
}

// ---------------- LN1 + cyclic shift + window partition -> bf16 ----------------
__global__ void ln_partition_kernel(const float* __restrict__ x,
                                    const float* __restrict__ g,
                                    const float* __restrict__ bt,
                                    __nv_bfloat16* __restrict__ o) {
    int warp = (blockIdx.x * blockDim.x + threadIdx.x) >> 5;
    int lane = threadIdx.x & 31;
    if (warp >= MROWS) return;
    int n = warp % 49;
    int window = warp / 49;
    int wi = window & 63;
    int b  = window >> 6;
    int wh = wi >> 3, ww = wi & 7;
    int h = wh * 7 + n / 7 + 3; if (h >= 56) h -= 56;
    int w = ww * 7 + n % 7 + 3; if (w >= 56) w -= 56;
    const float* xi = x + ((size_t)b * 3136 + h * 56 + w) * 192;

    float v[6]; float s1 = 0.f;
#pragma unroll
    for (int j = 0; j < 6; j++) { v[j] = xi[lane + 32 * j]; s1 += v[j]; }
    s1 = warp_sum(s1);
    float mean = s1 * (1.0f / 192.0f);
    float s2 = 0.f;
#pragma unroll
    for (int j = 0; j < 6; j++) { float d = v[j] - mean; s2 += d * d; }
    s2 = warp_sum(s2);
    float inv = rsqrtf(s2 * (1.0f / 192.0f) + 1e-5f);
    size_t base = (size_t)warp * 192;
#pragma unroll
    for (int j = 0; j < 6; j++) {
        int c = lane + 32 * j;
        o[base + c] = __float2bfloat16((v[j] - mean) * inv * g[c] + bt[c]);
    }
}

// ---------------- LN2 -> bf16 ----------------
__global__ void ln_plain_kernel(const float* __restrict__ x,
                                const float* __restrict__ g,
                                const float* __restrict__ bt,
                                __nv_bfloat16* __restrict__ o) {
    int warp = (blockIdx.x * blockDim.x + threadIdx.x) >> 5;
    int lane = threadIdx.x & 31;
    if (warp >= MROWS) return;
    const float* xi = x + (size_t)warp * 192;
    float v[6]; float s1 = 0.f;
#pragma unroll
    for (int j = 0; j < 6; j++) { v[j] = xi[lane + 32 * j]; s1 += v[j]; }
    s1 = warp_sum(s1);
    float mean = s1 * (1.0f / 192.0f);
    float s2 = 0.f;
#pragma unroll
    for (int j = 0; j < 6; j++) { float d = v[j] - mean; s2 += d * d; }
    s2 = warp_sum(s2);
    float inv = rsqrtf(s2 * (1.0f / 192.0f) + 1e-5f);
    size_t base = (size_t)warp * 192;
#pragma unroll
    for (int j = 0; j < 6; j++) {
        int c = lane + 32 * j;
        o[base + c] = __float2bfloat16((v[j] - mean) * inv * g[c] + bt[c]);
    }
}

// ---------------- attention: HMMA (mma.sync bf16), one block per (window, head) ----------------
__global__ void __launch_bounds__(128)
attn_kernel(const __nv_bfloat16* __restrict__ qkv,
            const __nv_bfloat16* __restrict__ battn,
            __nv_bfloat16* __restrict__ outp) {
    __shared__ __align__(16) char sQ[64 * 80];
    __shared__ __align__(16) char sK[64 * 80];
    __shared__ __align__(16) char sV[64 * 80];
    __shared__ __align__(16) __nv_bfloat16 sT[4096];

    const int head   = blockIdx.x % NHEAD;
    const int window = blockIdx.x / NHEAD;
    const int tid  = threadIdx.x;
    const int wrp  = tid >> 5;
    const int lane = tid & 31;

    const __nv_bfloat16* wbase = qkv + (size_t)window * 49 * 576 + head * 32;
    for (int i = tid; i < 588; i += 128) {
        int mat = i / 196, rem = i - mat * 196;
        int row = rem >> 2, ch = rem & 3;
        uint4 v = *(const uint4*)(wbase + (size_t)row * 576 + mat * 192 + ch * 8);
        char* dst = (mat == 0) ? sQ : (mat == 1) ? sK : sV;
        *(uint4*)(dst + row * 80 + ch * 16) = v;
    }
    for (int t = tid; t < 225; t += 128) {
        int mat = t / 75, rr = t - mat * 75;
        int row = 49 + rr / 5, ch = rr % 5;
        char* dst = (mat == 0) ? sQ : (mat == 1) ? sK : sV;
        *(uint4*)(dst + row * 80 + ch * 16) = make_uint4(0, 0, 0, 0);
    }
    {
        int wi = window & 63;
        int cls = ((wi >> 3) == 7 ? 1 : 0) + ((wi & 7) == 7 ? 2 : 0);
        const __nv_bfloat16* gT = battn + (size_t)(cls * NHEAD + head) * 4096;
        for (int i = tid; i < 512; i += 128)
            *(uint4*)(sT + i * 8) = *(const uint4*)(gT + i * 8);
    }
    __syncthreads();

    const uint32_t sQu = smem_u32(sQ), sKu = smem_u32(sK), sVu = smem_u32(sV);

    uint32_t qa[2][4];
    {
        uint32_t qaddr = sQu + (uint32_t)(16 * wrp + (lane & 15)) * 80 + ((lane >> 4) * 16);
        ldmat4(qa[0], qaddr);
        ldmat4(qa[1], qaddr + 32);
    }
    float acc[8][4];
#pragma unroll
    for (int nt = 0; nt < 8; nt++)
#pragma unroll
        for (int q = 0; q < 4; q++) acc[nt][q] = 0.f;

    const uint32_t krow = (uint32_t)(lane & 7) * 80 + ((lane & 8) ? 16 : 0);
#pragma unroll
    for (int nt = 0; nt < 8; nt++) {
#pragma unroll
        for (int kk = 0; kk < 2; kk++) {
            uint32_t b[2];
            ldmat2(b, sKu + nt * 640 + kk * 32 + krow);
            mma16816(acc[nt], qa[kk], b);
        }
    }

    const float scale = 0.17677669529663687f;
    const int tr = lane >> 2;
    const int tc = (lane & 3) * 2;
    const __nv_bfloat16* T0 = sT + (16 * wrp + tr) * 64;
    const __nv_bfloat16* T1 = T0 + 8 * 64;
#pragma unroll
    for (int nt = 0; nt < 8; nt++) {
        int c = 8 * nt + tc;
        float2 t0 = __bfloat1622float2(*(const __nv_bfloat162*)(T0 + c));
        float2 t1 = __bfloat1622float2(*(const __nv_bfloat162*)(T1 + c));
        acc[nt][0] = fmaf(acc[nt][0], scale, t0.x);
        acc[nt][1] = fmaf(acc[nt][1], scale, t0.y);
        acc[nt][2] = fmaf(acc[nt][2], scale, t1.x);
        acc[nt][3] = fmaf(acc[nt][3], scale, t1.y);
    }

    float m0 = -1e30f, m1 = -1e30f;
#pragma unroll
    for (int nt = 0; nt < 8; nt++) {
        m0 = fmaxf(m0, fmaxf(acc[nt][0], acc[nt][1]));
        m1 = fmaxf(m1, fmaxf(acc[nt][2], acc[nt][3]));
    }
    m0 = fmaxf(m0, __shfl_xor_sync(0xffffffffu, m0, 1));
    m0 = fmaxf(m0, __shfl_xor_sync(0xffffffffu, m0, 2));
    m1 = fmaxf(m1, __shfl_xor_sync(0xffffffffu, m1, 1));
    m1 = fmaxf(m1, __shfl_xor_sync(0xffffffffu, m1, 2));
    float s0 = 0.f, s1 = 0.f;
#pragma unroll
    for (int nt = 0; nt < 8; nt++) {
        acc[nt][0] = fast_exp(acc[nt][0] - m0); s0 += acc[nt][0];
        acc[nt][1] = fast_exp(acc[nt][1] - m0); s0 += acc[nt][1];
        acc[nt][2] = fast_exp(acc[nt][2] - m1); s1 += acc[nt][2];
        acc[nt][3] = fast_exp(acc[nt][3] - m1); s1 += acc[nt][3];
    }
    s0 += __shfl_xor_sync(0xffffffffu, s0, 1);
    s0 += __shfl_xor_sync(0xffffffffu, s0, 2);
    s1 += __shfl_xor_sync(0xffffffffu, s1, 1);
    s1 += __shfl_xor_sync(0xffffffffu, s1, 2);
    const float i0 = __frcp_rn(s0), i1 = __frcp_rn(s1);

    uint32_t pa[4][4];
#pragma unroll
    for (int kk = 0; kk < 4; kk++) {
        pa[kk][0] = pack_bf2(acc[2 * kk][0] * i0, acc[2 * kk][1] * i0);
        pa[kk][1] = pack_bf2(acc[2 * kk][2] * i1, acc[2 * kk][3] * i1);
        pa[kk][2] = pack_bf2(acc[2 * kk + 1][0] * i0, acc[2 * kk + 1][1] * i0);
        pa[kk][3] = pack_bf2(acc[2 * kk + 1][2] * i1, acc[2 * kk + 1][3] * i1);
    }

    float o[4][4];
#pragma unroll
    for (int nt = 0; nt < 4; nt++)
#pragma unroll
        for (int q = 0; q < 4; q++) o[nt][q] = 0.f;

    const uint32_t vrow = sVu + (uint32_t)(lane & 15) * 80;
#pragma unroll
    for (int kk = 0; kk < 4; kk++) {
#pragma unroll
        for (int nt = 0; nt < 4; nt++) {
            uint32_t b[2];
            ldmat2t(b, vrow + kk * (16 * 80) + nt * 16);
            mma16816(o[nt], pa[kk], b);
        }
    }

    const int gr0 = 16 * wrp + tr, gr1 = gr0 + 8;
    __nv_bfloat16* ob = outp + (size_t)window * 49 * 192 + head * 32;
#pragma unroll
    for (int nt = 0; nt < 4; nt++) {
        int d = 8 * nt + tc;
        if (gr0 < 49) *(uint32_t*)(ob + (size_t)gr0 * 192 + d) = pack_bf2(o[nt][0], o[nt][1]);
        if (gr1 < 49) *(uint32_t*)(ob + (size_t)gr1 * 192 + d) = pack_bf2(o[nt][2], o[nt][3]);
    }
}

// ---------------- bf16 mma GEMM: BM=256, BK=64, warp 64x32, 2-stage swizzled ----------------
#define SB_OFF 32768                  // 256 rows * 128B
#define STAGE  40960                  // + 64 rows * 128B
#define SM_TOT (2 * STAGE)            // 81920

enum { EPI_QKV = 0, EPI_PROJ = 1, EPI_GELU = 2, EPI_RES = 3 };

__device__ __forceinline__ size_t proj_row(int m) {
    int n = m % 49, window = m / 49;
    int wi = window & 63, b = window >> 6;
    int wh = wi >> 3, ww = wi & 7;
    int hh = wh * 7 + n / 7 + 3; if (hh >= 56) hh -= 56;
    int wc = ww * 7 + n % 7 + 3; if (wc >= 56) wc -= 56;
    return ((size_t)b * 3136 + (size_t)hh * 56 + wc) * 192;
}

template<int EPI>
__global__ void __launch_bounds__(256, 2)
gemm_mma(const __nv_bfloat16* __restrict__ A, const __nv_bfloat16* __restrict__ W,
         const float* __restrict__ bias, float* __restrict__ Cout,
         int Nn, int Ktot, const float* __restrict__ extra,
         __nv_bfloat16* __restrict__ obf) {
    extern __shared__ __align__(16) char sm[];
    const uint32_t sb = smem_u32(sm);
    const int tid  = threadIdx.x;
    const int wid  = tid >> 5;
    const int lane = tid & 31;
    const int warpM = wid >> 1;          // 0..3, 64 rows each
    const int warpN = wid & 1;           // 0..1, 32 cols each
    const int bm = blockIdx.y * 256;
    const int bn = blockIdx.x * 64;

    const __nv_bfloat16* A_b = A + (size_t)bm * Ktot;
    const __nv_bfloat16* W_b = W + (size_t)bn * Ktot;

    // ldmatrix bases (swizzled): row*128 + ((chunk ^ (row&7)) << 4)
    const int rowA = warpM * 64 + (lane & 15);
    const uint32_t aBase = (uint32_t)rowA * 128;
    const int axp = (lane >> 4) ^ (rowA & 7);
    const int rowB = warpN * 32 + ((lane >> 4) & 1) * 8 + (lane & 7);
    const uint32_t bBase = SB_OFF + (uint32_t)rowB * 128;
    const int bxp = ((lane >> 3) & 1) ^ (lane & 7);

    float acc[4][4][4];
#pragma unroll
    for (int i = 0; i < 4; i++)
#pragma unroll
        for (int j = 0; j < 4; j++)
#pragma unroll
            for (int k = 0; k < 4; k++) acc[i][j][k] = 0.f;

    const int NK = Ktot >> 6;   // K / 64

    // stage loader: A 256x64 bf16 (2048x16B), B 64x64 (512x16B), swizzled
    auto stage_load = [&](int buf, int k0) {
        uint32_t d = sb + buf * STAGE;
#pragma unroll
        for (int i = 0; i < 8; i++) {
            int idx = tid + 256 * i;
            int row = idx >> 3, ch = idx & 7;
            CP16(d + row * 128 + ((ch ^ (row & 7)) << 4), A_b + (size_t)row * Ktot + k0 + ch * 8);
        }
#pragma unroll
        for (int i = 0; i < 2; i++) {
            int idx = tid + 256 * i;
            int row = idx >> 3, ch = idx & 7;
            CP16(d + SB_OFF + row * 128 + ((ch ^ (row & 7)) << 4), W_b + (size_t)row * Ktot + k0 + ch * 8);
        }
        CP_COMMIT();
    };

    stage_load(0, 0);
    if (NK > 1) stage_load(1, 64);

    for (int k = 0; k < NK; k++) {
        if (k + 1 < NK) { CP_WAIT(1); } else { CP_WAIT(0); }
        __syncthreads();

        const int buf = k & 1;
        const uint32_t soff = sb + buf * STAGE;
        const uint32_t aaddr = soff + aBase;
        const uint32_t baddr = soff + bBase;

#pragma unroll
        for (int kk = 0; kk < 4; kk++) {
            const uint32_t xa = (uint32_t)((2 * kk) ^ axp) << 4;
            const uint32_t xb = (uint32_t)((2 * kk) ^ bxp) << 4;
            uint32_t a0[4], a1[4], a2[4], a3[4];
            ldmat4(a0, aaddr + xa);
            ldmat4(a1, aaddr + 2048 + xa);
            ldmat4(a2, aaddr + 4096 + xa);
            ldmat4(a3, aaddr + 6144 + xa);
#pragma unroll
            for (int ng = 0; ng < 2; ng++) {
                uint32_t bh[4];
                ldmat4(bh, baddr + ng * 2048 + xb);
#pragma unroll
                for (int q = 0; q < 2; q++) {
                    int ni = ng * 2 + q;
                    mma16816(acc[0][ni], a0, bh + 2 * q);
                    mma16816(acc[1][ni], a1, bh + 2 * q);
                    mma16816(acc[2][ni], a2, bh + 2 * q);
                    mma16816(acc[3][ni], a3, bh + 2 * q);
                }
            }
        }
        __syncthreads();
        if (k + 2 < NK) stage_load(buf, (k + 2) << 6);
    }

    // ---------------- epilogue ----------------
    const int lrow = lane >> 2, lcol = (lane & 3) * 2;
#pragma unroll
    for (int mi = 0; mi < 4; mi++) {
        int m0 = bm + warpM * 64 + mi * 16 + lrow;
        int m1 = m0 + 8;
        size_t r0, r1;
        if (EPI == EPI_PROJ) { r0 = proj_row(m0); r1 = proj_row(m1); }
        else { r0 = (size_t)m0 * Nn; r1 = (size_t)m1 * Nn; }
#pragma unroll
        for (int ni = 0; ni < 4; ni++) {
            int n = bn + warpN * 32 + ni * 8 + lcol;
            float bx = bias[n], by = bias[n + 1];
            float v0x = acc[mi][ni][0] + bx, v0y = acc[mi][ni][1] + by;
            float v1x = acc[mi][ni][2] + bx, v1y = acc[mi][ni][3] + by;
            if (EPI == EPI_QKV) {
                *(uint32_t*)(obf + r0 + n) = pack_bf2(v0x, v0y);
                *(uint32_t*)(obf + r1 + n) = pack_bf2(v1x, v1y);
            } else if (EPI == EPI_GELU) {
                *(uint32_t*)(obf + r0 + n) = pack_bf2(gelu_exact(v0x), gelu_exact(v0y));
                *(uint32_t*)(obf + r1 + n) = pack_bf2(gelu_exact(v1x), gelu_exact(v1y));
            } else {
                float2 e0 = *(const float2*)(extra + r0 + n);
                float2 e1 = *(const float2*)(extra + r1 + n);
                *(float2*)(Cout + r0 + n) = make_float2(v0x + e0.x, v0y + e0.y);
                *(float2*)(Cout + r1 + n) = make_float2(v1x + e1.x, v1y + e1.y);
            }
        }
    }
}

// ---------------- launch ----------------
extern "C" void kernel_launch(void* const* d_in, const int* in_sizes, int n_in,
                              void* d_out, int out_size) {
    const float* x      = (const float*)d_in[0];
    const float* g1     = (const float*)d_in[1];
    const float* b1     = (const float*)d_in[2];
    const float* qkv_w  = (const float*)d_in[3];
    const float* qkv_b  = (const float*)d_in[4];
    const float* proj_w = (const float*)d_in[5];
    const float* proj_b = (const float*)d_in[6];
    const float* bias_t = (const float*)d_in[7];
    const float* g2     = (const float*)d_in[8];
    const float* b2     = (const float*)d_in[9];
    const float* fc1_w  = (const float*)d_in[10];
    const float* fc1_b  = (const float*)d_in[11];
    const float* fc2_w  = (const float*)d_in[12];
    const float* fc2_b  = (const float*)d_in[13];
    float* out = (float*)d_out;

    float* p_x1;
    __nv_bfloat16 *p_qkv, *p_xw, *p_at, *p_x2, *p_h1, *p_wq, *p_wp, *p_w1, *p_w2, *p_battn;
    cudaGetSymbolAddress((void**)&p_qkv, g_qkv);
    cudaGetSymbolAddress((void**)&p_x1,  g_x1);
    cudaGetSymbolAddress((void**)&p_xw,  g_xw);
    cudaGetSymbolAddress((void**)&p_at,  g_at);
    cudaGetSymbolAddress((void**)&p_x2,  g_x2);
    cudaGetSymbolAddress((void**)&p_h1,  g_h1);
    cudaGetSymbolAddress((void**)&p_wq,  g_wq);
    cudaGetSymbolAddress((void**)&p_wp,  g_wp);
    cudaGetSymbolAddress((void**)&p_w1,  g_w1);
    cudaGetSymbolAddress((void**)&p_w2,  g_w2);
    cudaGetSymbolAddress((void**)&p_battn, g_battn);

    cudaFuncSetAttribute(gemm_mma<EPI_QKV>,  cudaFuncAttributeMaxDynamicSharedMemorySize, SM_TOT);
    cudaFuncSetAttribute(gemm_mma<EPI_PROJ>, cudaFuncAttributeMaxDynamicSharedMemorySize, SM_TOT);
    cudaFuncSetAttribute(gemm_mma<EPI_GELU>, cudaFuncAttributeMaxDynamicSharedMemorySize, SM_TOT);
    cudaFuncSetAttribute(gemm_mma<EPI_RES>,  cudaFuncAttributeMaxDynamicSharedMemorySize, SM_TOT);

    const int MB = MROWS / 256;  // 392

    convert_all<<<SEG3 / 256, 256>>>(qkv_w, proj_w, fc1_w, fc2_w, p_wq, p_wp, p_w1, p_w2);
    build_battn<<<24, 256>>>(bias_t, p_battn);
    ln_partition_kernel<<<MROWS / 8, 256>>>(x, g1, b1, p_xw);
    gemm_mma<EPI_QKV><<<dim3(576 / 64, MB), 256, SM_TOT>>>(p_xw, p_wq, qkv_b, nullptr, 576, 192, nullptr, p_qkv);
    attn_kernel<<<NWTOT * NHEAD, 128>>>(p_qkv, p_battn, p_at);
    gemm_mma<EPI_PROJ><<<dim3(192 / 64, MB), 256, SM_TOT>>>(p_at, p_wp, proj_b, p_x1, 192, 192, x, nullptr);
    ln_plain_kernel<<<MROWS / 8, 256>>>(p_x1, g2, b2, p_x2);
    gemm_mma<EPI_GELU><<<dim3(768 / 64, MB), 256, SM_TOT>>>(p_x2, p_w1, fc1_b, nullptr, 768, 192, nullptr, p_h1);
    gemm_mma<EPI_RES><<<dim3(192 / 64, MB), 256, SM_TOT>>>(p_h1, p_w2, fc2_b, out, 192, 768, p_x1, nullptr);
}

// round 11
// speedup vs baseline: 6.0130x; 1.0428x over previous
#include <cuda_runtime.h>
#include <cuda_bf16.h>
#include <math.h>
#include <stdint.h>

// ---------------- problem constants ----------------
#define C_     192
#define NHEAD  6
#define HID_   768
#define BATCH  32
#define NWTOT  2048
#define MROWS  100352      // NWTOT * 49

// ---------------- scratch (device globals) ----------------
__device__ __nv_bfloat16  g_qkv [(size_t)MROWS * 3 * C_];
__device__ float          g_x1  [(size_t)MROWS * C_];
__device__ __nv_bfloat16  g_xw  [(size_t)MROWS * C_];
__device__ __nv_bfloat16  g_at  [(size_t)MROWS * C_];
__device__ __nv_bfloat16  g_x2  [(size_t)MROWS * C_];
__device__ __nv_bfloat16  g_h1  [(size_t)MROWS * HID_];
__device__ __nv_bfloat16  g_wq[576 * 192];
__device__ __nv_bfloat16  g_wp[192 * 192];
__device__ __nv_bfloat16  g_w1[768 * 192];
__device__ __nv_bfloat16  g_w2[192 * 768];
__device__ __nv_bfloat16  g_battn[24 * 4096];   // [class(4) x head(6)][64x64] bias+mask (bf16)

// ---------------- helpers ----------------
__device__ __forceinline__ uint32_t smem_u32(const void* p) {
    uint32_t a;
    asm("{ .reg .u64 t; cvta.to.shared.u64 t, %1; cvt.u32.u64 %0, t; }" : "=r"(a) : "l"(p));
    return a;
}
__device__ __forceinline__ float warp_sum(float v) {
#pragma unroll
    for (int o = 16; o; o >>= 1) v += __shfl_xor_sync(0xffffffffu, v, o);
    return v;
}
__device__ __forceinline__ float gelu_exact(float x) {
    return 0.5f * x * (1.0f + erff(x * 0.70710678118654752f));
}
__device__ __forceinline__ uint32_t pack_bf2(float a, float b) {
    __nv_bfloat162 t = __floats2bfloat162_rn(a, b);
    return *(uint32_t*)&t;
}
// FMA-only exp (exp2 poly)
__device__ __forceinline__ float fast_exp(float x) {
    float t = fmaxf(x * 1.4426950408889634f, -126.0f);
    float n = floorf(t);
    float f = t - n;
    float p = 1.8775767e-3f;
    p = fmaf(p, f, 8.9893397e-3f);
    p = fmaf(p, f, 5.5804084e-2f);
    p = fmaf(p, f, 2.4013971e-1f);
    p = fmaf(p, f, 6.9314718e-1f);
    p = fmaf(p, f, 1.0f);
    return p * __int_as_float(((int)n + 127) << 23);
}

__device__ __forceinline__ void ldmat4(uint32_t* r, uint32_t addr) {
    asm volatile("ldmatrix.sync.aligned.m8n8.x4.shared.b16 {%0,%1,%2,%3}, [%4];"
        : "=r"(r[0]), "=r"(r[1]), "=r"(r[2]), "=r"(r[3]) : "r"(addr));
}
__device__ __forceinline__ void ldmat2(uint32_t* r, uint32_t addr) {
    asm volatile("ldmatrix.sync.aligned.m8n8.x2.shared.b16 {%0,%1}, [%2];"
        : "=r"(r[0]), "=r"(r[1]) : "r"(addr));
}
__device__ __forceinline__ void ldmat2t(uint32_t* r, uint32_t addr) {
    asm volatile("ldmatrix.sync.aligned.m8n8.x2.trans.shared.b16 {%0,%1}, [%2];"
        : "=r"(r[0]), "=r"(r[1]) : "r"(addr));
}
__device__ __forceinline__ void mma16816(float* d, const uint32_t* a, const uint32_t* b) {
    asm volatile("mma.sync.aligned.m16n8k16.row.col.f32.bf16.bf16.f32 "
        "{%0,%1,%2,%3}, {%4,%5,%6,%7}, {%8,%9}, {%0,%1,%2,%3};"
        : "+f"(d[0]), "+f"(d[1]), "+f"(d[2]), "+f"(d[3])
        : "r"(a[0]), "r"(a[1]), "r"(a[2]), "r"(a[3]), "r"(b[0]), "r"(b[1]));
}
#define CP16(dst, src) \
    asm volatile("cp.async.cg.shared.global [%0], [%1], 16;" :: "r"(dst), "l"(src))
#define CP_COMMIT() asm volatile("cp.async.commit_group;" ::: "memory")
#define CP_WAIT(n)  asm volatile("cp.async.wait_group %0;" :: "n"(n) : "memory")

// ---------------- all weights fp32 -> bf16, one launch ----------------
#define SEG0 110592
#define SEG1 147456
#define SEG2 294912
#define SEG3 442368
__global__ void convert_all(const float* __restrict__ qkv_w, const float* __restrict__ proj_w,
                            const float* __restrict__ fc1_w, const float* __restrict__ fc2_w,
                            __nv_bfloat16* __restrict__ wq, __nv_bfloat16* __restrict__ wp,
                            __nv_bfloat16* __restrict__ w1, __nv_bfloat16* __restrict__ w2) {
    int i = blockIdx.x * blockDim.x + threadIdx.x;
    if (i < SEG0)       wq[i]        = __float2bfloat16(qkv_w[i]);
    else if (i < SEG1)  wp[i - SEG0] = __float2bfloat16(proj_w[i - SEG0]);
    else if (i < SEG2)  w1[i - SEG1] = __float2bfloat16(fc1_w[i - SEG1]);
    else if (i < SEG3)  w2[i - SEG2] = __float2bfloat16(fc2_w[i - SEG2]);
}

// ---------------- build attention bias+mask tables (bf16) ----------------
__global__ void build_battn(const float* __restrict__ bt, __nv_bfloat16* __restrict__ battn) {
    int cls  = blockIdx.x / NHEAD;
    int head = blockIdx.x % NHEAD;
    __nv_bfloat16* T = battn + (size_t)blockIdx.x * 4096;
    for (int i = threadIdx.x; i < 4096; i += 256) {
        int r = i >> 6, c = i & 63;
        float v = -1e30f;
        if (r < 49 && c < 49) {
            int rr = ((cls & 1) ? ((r / 7 < 4) ? 1 : 2) : 0) * 3
                   + ((cls & 2) ? ((r % 7 < 4) ? 1 : 2) : 0);
            int rc = ((cls & 1) ? ((c / 7 < 4) ? 1 : 2) : 0) * 3
                   + ((cls & 2) ? ((c % 7 < 4) ? 1 : 2) : 0);
            int rel = (r / 7 - c / 7 + 6) * 13 + (r % 7 - c % 7 + 6);
            v = bt[rel * NHEAD + head] + ((rr != rc) ? -100.0f : 0.0f);
        }
        T[i] = __float2bfloat16(v);
    }
}

// ---------------- LN1 + cyclic shift + window partition -> bf16 ----------------
__global__ void ln_partition_kernel(const float* __restrict__ x,
                                    const float* __restrict__ g,
                                    const float* __restrict__ bt,
                                    __nv_bfloat16* __restrict__ o) {
    int warp = (blockIdx.x * blockDim.x + threadIdx.x) >> 5;
    int lane = threadIdx.x & 31;
    if (warp >= MROWS) return;
    int n = warp % 49;
    int window = warp / 49;
    int wi = window & 63;
    int b  = window >> 6;
    int wh = wi >> 3, ww = wi & 7;
    int h = wh * 7 + n / 7 + 3; if (h >= 56) h -= 56;
    int w = ww * 7 + n % 7 + 3; if (w >= 56) w -= 56;
    const float* xi = x + ((size_t)b * 3136 + h * 56 + w) * 192;

    float v[6]; float s1 = 0.f;
#pragma unroll
    for (int j = 0; j < 6; j++) { v[j] = xi[lane + 32 * j]; s1 += v[j]; }
    s1 = warp_sum(s1);
    float mean = s1 * (1.0f / 192.0f);
    float s2 = 0.f;
#pragma unroll
    for (int j = 0; j < 6; j++) { float d = v[j] - mean; s2 += d * d; }
    s2 = warp_sum(s2);
    float inv = rsqrtf(s2 * (1.0f / 192.0f) + 1e-5f);
    size_t base = (size_t)warp * 192;
#pragma unroll
    for (int j = 0; j < 6; j++) {
        int c = lane + 32 * j;
        o[base + c] = __float2bfloat16((v[j] - mean) * inv * g[c] + bt[c]);
    }
}

// ---------------- LN2 -> bf16 ----------------
__global__ void ln_plain_kernel(const float* __restrict__ x,
                                const float* __restrict__ g,
                                const float* __restrict__ bt,
                                __nv_bfloat16* __restrict__ o) {
    int warp = (blockIdx.x * blockDim.x + threadIdx.x) >> 5;
    int lane = threadIdx.x & 31;
    if (warp >= MROWS) return;
    const float* xi = x + (size_t)warp * 192;
    float v[6]; float s1 = 0.f;
#pragma unroll
    for (int j = 0; j < 6; j++) { v[j] = xi[lane + 32 * j]; s1 += v[j]; }
    s1 = warp_sum(s1);
    float mean = s1 * (1.0f / 192.0f);
    float s2 = 0.f;
#pragma unroll
    for (int j = 0; j < 6; j++) { float d = v[j] - mean; s2 += d * d; }
    s2 = warp_sum(s2);
    float inv = rsqrtf(s2 * (1.0f / 192.0f) + 1e-5f);
    size_t base = (size_t)warp * 192;
#pragma unroll
    for (int j = 0; j < 6; j++) {
        int c = lane + 32 * j;
        o[base + c] = __float2bfloat16((v[j] - mean) * inv * g[c] + bt[c]);
    }
}

// ---------------- attention: HMMA, 2 windows (same class) x 1 head per block ----------------
__global__ void __launch_bounds__(256)
attn_kernel(const __nv_bfloat16* __restrict__ qkv,
            const __nv_bfloat16* __restrict__ battn,
            __nv_bfloat16* __restrict__ outp) {
    __shared__ __align__(16) char sQ[2][64 * 80];
    __shared__ __align__(16) char sK[2][64 * 80];
    __shared__ __align__(16) char sV[2][64 * 80];
    __shared__ __align__(16) __nv_bfloat16 sT[4096];

    const int head = blockIdx.x % NHEAD;
    const int t    = blockIdx.x / NHEAD;       // 0..1023
    const int qp   = t >> 6;                   // batch pair 0..15
    const int wi   = t & 63;
    const int tid  = threadIdx.x;
    const int sub  = tid >> 7;                 // 0/1: window within pair
    const int ltid = tid & 127;
    const int wrp  = ltid >> 5;
    const int lane = tid & 31;
    const int window = 128 * qp + sub * 64 + wi;   // batches 2qp, 2qp+1: same wi -> same class

    // ---- stage QKV for this sub's window ----
    const __nv_bfloat16* wbase = qkv + (size_t)window * 49 * 576 + head * 32;
    for (int i = ltid; i < 588; i += 128) {
        int mat = i / 196, rem = i - mat * 196;
        int row = rem >> 2, ch = rem & 3;
        uint4 v = *(const uint4*)(wbase + (size_t)row * 576 + mat * 192 + ch * 8);
        char* dst = (mat == 0) ? sQ[sub] : (mat == 1) ? sK[sub] : sV[sub];
        *(uint4*)(dst + row * 80 + ch * 16) = v;
    }
    for (int i = ltid; i < 225; i += 128) {
        int mat = i / 75, rr = i - mat * 75;
        int row = 49 + rr / 5, ch = rr % 5;
        char* dst = (mat == 0) ? sQ[sub] : (mat == 1) ? sK[sub] : sV[sub];
        *(uint4*)(dst + row * 80 + ch * 16) = make_uint4(0, 0, 0, 0);
    }
    {
        int cls = ((wi >> 3) == 7 ? 1 : 0) + ((wi & 7) == 7 ? 2 : 0);
        const __nv_bfloat16* gT = battn + (size_t)(cls * NHEAD + head) * 4096;
        for (int i = tid; i < 512; i += 256)
            *(uint4*)(sT + i * 8) = *(const uint4*)(gT + i * 8);
    }
    __syncthreads();

    const uint32_t sQu = smem_u32(sQ[sub]), sKu = smem_u32(sK[sub]), sVu = smem_u32(sV[sub]);

    uint32_t qa[2][4];
    {
        uint32_t qaddr = sQu + (uint32_t)(16 * wrp + (lane & 15)) * 80 + ((lane >> 4) * 16);
        ldmat4(qa[0], qaddr);
        ldmat4(qa[1], qaddr + 32);
    }
    float acc[8][4];
#pragma unroll
    for (int nt = 0; nt < 8; nt++)
#pragma unroll
        for (int q = 0; q < 4; q++) acc[nt][q] = 0.f;

    const uint32_t krow = (uint32_t)(lane & 7) * 80 + ((lane & 8) ? 16 : 0);
#pragma unroll
    for (int nt = 0; nt < 8; nt++) {
#pragma unroll
        for (int kk = 0; kk < 2; kk++) {
            uint32_t b[2];
            ldmat2(b, sKu + nt * 640 + kk * 32 + krow);
            mma16816(acc[nt], qa[kk], b);
        }
    }

    const float scale = 0.17677669529663687f;
    const int tr = lane >> 2;
    const int tc = (lane & 3) * 2;
    const __nv_bfloat16* T0 = sT + (16 * wrp + tr) * 64;
    const __nv_bfloat16* T1 = T0 + 8 * 64;
#pragma unroll
    for (int nt = 0; nt < 8; nt++) {
        int c = 8 * nt + tc;
        float2 t0 = __bfloat1622float2(*(const __nv_bfloat162*)(T0 + c));
        float2 t1 = __bfloat1622float2(*(const __nv_bfloat162*)(T1 + c));
        acc[nt][0] = fmaf(acc[nt][0], scale, t0.x);
        acc[nt][1] = fmaf(acc[nt][1], scale, t0.y);
        acc[nt][2] = fmaf(acc[nt][2], scale, t1.x);
        acc[nt][3] = fmaf(acc[nt][3], scale, t1.y);
    }

    float m0 = -1e30f, m1 = -1e30f;
#pragma unroll
    for (int nt = 0; nt < 8; nt++) {
        m0 = fmaxf(m0, fmaxf(acc[nt][0], acc[nt][1]));
        m1 = fmaxf(m1, fmaxf(acc[nt][2], acc[nt][3]));
    }
    m0 = fmaxf(m0, __shfl_xor_sync(0xffffffffu, m0, 1));
    m0 = fmaxf(m0, __shfl_xor_sync(0xffffffffu, m0, 2));
    m1 = fmaxf(m1, __shfl_xor_sync(0xffffffffu, m1, 1));
    m1 = fmaxf(m1, __shfl_xor_sync(0xffffffffu, m1, 2));
    float s0 = 0.f, s1 = 0.f;
#pragma unroll
    for (int nt = 0; nt < 8; nt++) {
        acc[nt][0] = fast_exp(acc[nt][0] - m0); s0 += acc[nt][0];
        acc[nt][1] = fast_exp(acc[nt][1] - m0); s0 += acc[nt][1];
        acc[nt][2] = fast_exp(acc[nt][2] - m1); s1 += acc[nt][2];
        acc[nt][3] = fast_exp(acc[nt][3] - m1); s1 += acc[nt][3];
    }
    s0 += __shfl_xor_sync(0xffffffffu, s0, 1);
    s0 += __shfl_xor_sync(0xffffffffu, s0, 2);
    s1 += __shfl_xor_sync(0xffffffffu, s1, 1);
    s1 += __shfl_xor_sync(0xffffffffu, s1, 2);
    const float i0 = __frcp_rn(s0), i1 = __frcp_rn(s1);

    uint32_t pa[4][4];
#pragma unroll
    for (int kk = 0; kk < 4; kk++) {
        pa[kk][0] = pack_bf2(acc[2 * kk][0] * i0, acc[2 * kk][1] * i0);
        pa[kk][1] = pack_bf2(acc[2 * kk][2] * i1, acc[2 * kk][3] * i1);
        pa[kk][2] = pack_bf2(acc[2 * kk + 1][0] * i0, acc[2 * kk + 1][1] * i0);
        pa[kk][3] = pack_bf2(acc[2 * kk + 1][2] * i1, acc[2 * kk + 1][3] * i1);
    }

    float o[4][4];
#pragma unroll
    for (int nt = 0; nt < 4; nt++)
#pragma unroll
        for (int q = 0; q < 4; q++) o[nt][q] = 0.f;

    const uint32_t vrow = sVu + (uint32_t)(lane & 15) * 80;
#pragma unroll
    for (int kk = 0; kk < 4; kk++) {
#pragma unroll
        for (int nt = 0; nt < 4; nt++) {
            uint32_t b[2];
            ldmat2t(b, vrow + kk * (16 * 80) + nt * 16);
            mma16816(o[nt], pa[kk], b);
        }
    }

    const int gr0 = 16 * wrp + tr, gr1 = gr0 + 8;
    __nv_bfloat16* ob = outp + (size_t)window * 49 * 192 + head * 32;
#pragma unroll
    for (int nt = 0; nt < 4; nt++) {
        int d = 8 * nt + tc;
        if (gr0 < 49) *(uint32_t*)(ob + (size_t)gr0 * 192 + d) = pack_bf2(o[nt][0], o[nt][1]);
        if (gr1 < 49) *(uint32_t*)(ob + (size_t)gr1 * 192 + d) = pack_bf2(o[nt][2], o[nt][3]);
    }
}

// ---------------- bf16 mma GEMM: BM=128, BN=64, 4 warps of 64x32, 2-stage swizzled, 4 CTAs/SM ----
#define SB_OFF 16384                  // 128 rows * 128B
#define STAGE  24576                  // + 64 rows * 128B
#define SM_TOT (2 * STAGE)            // 49152

enum { EPI_QKV = 0, EPI_PROJ = 1, EPI_GELU = 2, EPI_RES = 3 };

__device__ __forceinline__ size_t proj_row(int m) {
    int n = m % 49, window = m / 49;
    int wi = window & 63, b = window >> 6;
    int wh = wi >> 3, ww = wi & 7;
    int hh = wh * 7 + n / 7 + 3; if (hh >= 56) hh -= 56;
    int wc = ww * 7 + n % 7 + 3; if (wc >= 56) wc -= 56;
    return ((size_t)b * 3136 + (size_t)hh * 56 + wc) * 192;
}

template<int EPI>
__global__ void __launch_bounds__(128, 4)
gemm_mma(const __nv_bfloat16* __restrict__ A, const __nv_bfloat16* __restrict__ W,
         const float* __restrict__ bias, float* __restrict__ Cout,
         int Nn, int Ktot, const float* __restrict__ extra,
         __nv_bfloat16* __restrict__ obf) {
    extern __shared__ __align__(16) char sm[];
    const uint32_t sb = smem_u32(sm);
    const int tid  = threadIdx.x;
    const int wid  = tid >> 5;
    const int lane = tid & 31;
    const int warpM = wid >> 1;          // 0..1, 64 rows each
    const int warpN = wid & 1;           // 0..1, 32 cols each
    const int bm = blockIdx.y * 128;
    const int bn = blockIdx.x * 64;

    const __nv_bfloat16* A_b = A + (size_t)bm * Ktot;
    const __nv_bfloat16* W_b = W + (size_t)bn * Ktot;

    // ldmatrix bases (swizzled): row*128 + ((chunk ^ (row&7)) << 4)
    const int rowA = warpM * 64 + (lane & 15);
    const uint32_t aBase = (uint32_t)rowA * 128;
    const int axp = (lane >> 4) ^ (rowA & 7);
    const int rowB = warpN * 32 + ((lane >> 4) & 1) * 8 + (lane & 7);
    const uint32_t bBase = SB_OFF + (uint32_t)rowB * 128;
    const int bxp = ((lane >> 3) & 1) ^ (lane & 7);

    float acc[4][4][4];
#pragma unroll
    for (int i = 0; i < 4; i++)
#pragma unroll
        for (int j = 0; j < 4; j++)
#pragma unroll
            for (int k = 0; k < 4; k++) acc[i][j][k] = 0.f;

    const int NK = Ktot >> 6;   // K / 64

    // stage loader: A 128x64 bf16 (1024x16B), B 64x64 (512x16B), swizzled, 128 threads
    auto stage_load = [&](int buf, int k0) {
        uint32_t d = sb + buf * STAGE;
#pragma unroll
        for (int i = 0; i < 8; i++) {
            int idx = tid + 128 * i;
            int row = idx >> 3, ch = idx & 7;
            CP16(d + row * 128 + ((ch ^ (row & 7)) << 4), A_b + (size_t)row * Ktot + k0 + ch * 8);
        }
#pragma unroll
        for (int i = 0; i < 4; i++) {
            int idx = tid + 128 * i;
            int row = idx >> 3, ch = idx & 7;
            CP16(d + SB_OFF + row * 128 + ((ch ^ (row & 7)) << 4), W_b + (size_t)row * Ktot + k0 + ch * 8);
        }
        CP_COMMIT();
    };

    stage_load(0, 0);
    if (NK > 1) stage_load(1, 64);

    for (int k = 0; k < NK; k++) {
        if (k + 1 < NK) { CP_WAIT(1); } else { CP_WAIT(0); }
        __syncthreads();

        const int buf = k & 1;
        const uint32_t soff = sb + buf * STAGE;
        const uint32_t aaddr = soff + aBase;
        const uint32_t baddr = soff + bBase;

#pragma unroll
        for (int kk = 0; kk < 4; kk++) {
            const uint32_t xa = (uint32_t)((2 * kk) ^ axp) << 4;
            const uint32_t xb = (uint32_t)((2 * kk) ^ bxp) << 4;
            uint32_t a0[4], a1[4], a2[4], a3[4];
            ldmat4(a0, aaddr + xa);
            ldmat4(a1, aaddr + 2048 + xa);
            ldmat4(a2, aaddr + 4096 + xa);
            ldmat4(a3, aaddr + 6144 + xa);
#pragma unroll
            for (int ng = 0; ng < 2; ng++) {
                uint32_t bh[4];
                ldmat4(bh, baddr + ng * 2048 + xb);
#pragma unroll
                for (int q = 0; q < 2; q++) {
                    int ni = ng * 2 + q;
                    mma16816(acc[0][ni], a0, bh + 2 * q);
                    mma16816(acc[1][ni], a1, bh + 2 * q);
                    mma16816(acc[2][ni], a2, bh + 2 * q);
                    mma16816(acc[3][ni], a3, bh + 2 * q);
                }
            }
        }
        __syncthreads();
        if (k + 2 < NK) stage_load(buf, (k + 2) << 6);
    }

    // ---------------- epilogue ----------------
    const int lrow = lane >> 2, lcol = (lane & 3) * 2;
#pragma unroll
    for (int mi = 0; mi < 4; mi++) {
        int m0 = bm + warpM * 64 + mi * 16 + lrow;
        int m1 = m0 + 8;
        size_t r0, r1;
        if (EPI == EPI_PROJ) { r0 = proj_row(m0); r1 = proj_row(m1); }
        else { r0 = (size_t)m0 * Nn; r1 = (size_t)m1 * Nn; }
#pragma unroll
        for (int ni = 0; ni < 4; ni++) {
            int n = bn + warpN * 32 + ni * 8 + lcol;
            float bx = bias[n], by = bias[n + 1];
            float v0x = acc[mi][ni][0] + bx, v0y = acc[mi][ni][1] + by;
            float v1x = acc[mi][ni][2] + bx, v1y = acc[mi][ni][3] + by;
            if (EPI == EPI_QKV) {
                *(uint32_t*)(obf + r0 + n) = pack_bf2(v0x, v0y);
                *(uint32_t*)(obf + r1 + n) = pack_bf2(v1x, v1y);
            } else if (EPI == EPI_GELU) {
                *(uint32_t*)(obf + r0 + n) = pack_bf2(gelu_exact(v0x), gelu_exact(v0y));
                *(uint32_t*)(obf + r1 + n) = pack_bf2(gelu_exact(v1x), gelu_exact(v1y));
            } else {
                float2 e0 = *(const float2*)(extra + r0 + n);
                float2 e1 = *(const float2*)(extra + r1 + n);
                *(float2*)(Cout + r0 + n) = make_float2(v0x + e0.x, v0y + e0.y);
                *(float2*)(Cout + r1 + n) = make_float2(v1x + e1.x, v1y + e1.y);
            }
        }
    }
}

// ---------------- launch ----------------
extern "C" void kernel_launch(void* const* d_in, const int* in_sizes, int n_in,
                              void* d_out, int out_size) {
    const float* x      = (const float*)d_in[0];
    const float* g1     = (const float*)d_in[1];
    const float* b1     = (const float*)d_in[2];
    const float* qkv_w  = (const float*)d_in[3];
    const float* qkv_b  = (const float*)d_in[4];
    const float* proj_w = (const float*)d_in[5];
    const float* proj_b = (const float*)d_in[6];
    const float* bias_t = (const float*)d_in[7];
    const float* g2     = (const float*)d_in[8];
    const float* b2     = (const float*)d_in[9];
    const float* fc1_w  = (const float*)d_in[10];
    const float* fc1_b  = (const float*)d_in[11];
    const float* fc2_w  = (const float*)d_in[12];
    const float* fc2_b  = (const float*)d_in[13];
    float* out = (float*)d_out;

    float* p_x1;
    __nv_bfloat16 *p_qkv, *p_xw, *p_at, *p_x2, *p_h1, *p_wq, *p_wp, *p_w1, *p_w2, *p_battn;
    cudaGetSymbolAddress((void**)&p_qkv, g_qkv);
    cudaGetSymbolAddress((void**)&p_x1,  g_x1);
    cudaGetSymbolAddress((void**)&p_xw,  g_xw);
    cudaGetSymbolAddress((void**)&p_at,  g_at);
    cudaGetSymbolAddress((void**)&p_x2,  g_x2);
    cudaGetSymbolAddress((void**)&p_h1,  g_h1);
    cudaGetSymbolAddress((void**)&p_wq,  g_wq);
    cudaGetSymbolAddress((void**)&p_wp,  g_wp);
    cudaGetSymbolAddress((void**)&p_w1,  g_w1);
    cudaGetSymbolAddress((void**)&p_w2,  g_w2);
    cudaGetSymbolAddress((void**)&p_battn, g_battn);

    cudaFuncSetAttribute(gemm_mma<EPI_QKV>,  cudaFuncAttributeMaxDynamicSharedMemorySize, SM_TOT);
    cudaFuncSetAttribute(gemm_mma<EPI_PROJ>, cudaFuncAttributeMaxDynamicSharedMemorySize, SM_TOT);
    cudaFuncSetAttribute(gemm_mma<EPI_GELU>, cudaFuncAttributeMaxDynamicSharedMemorySize, SM_TOT);
    cudaFuncSetAttribute(gemm_mma<EPI_RES>,  cudaFuncAttributeMaxDynamicSharedMemorySize, SM_TOT);

    const int MB = MROWS / 128;  // 784

    convert_all<<<SEG3 / 256, 256>>>(qkv_w, proj_w, fc1_w, fc2_w, p_wq, p_wp, p_w1, p_w2);
    build_battn<<<24, 256>>>(bias_t, p_battn);
    ln_partition_kernel<<<MROWS / 8, 256>>>(x, g1, b1, p_xw);
    gemm_mma<EPI_QKV><<<dim3(576 / 64, MB), 128, SM_TOT>>>(p_xw, p_wq, qkv_b, nullptr, 576, 192, nullptr, p_qkv);
    attn_kernel<<<NWTOT * NHEAD / 2, 256>>>(p_qkv, p_battn, p_at);
    gemm_mma<EPI_PROJ><<<dim3(192 / 64, MB), 128, SM_TOT>>>(p_at, p_wp, proj_b, p_x1, 192, 192, x, nullptr);
    ln_plain_kernel<<<MROWS / 8, 256>>>(p_x1, g2, b2, p_x2);
    gemm_mma<EPI_GELU><<<dim3(768 / 64, MB), 128, SM_TOT>>>(p_x2, p_w1, fc1_b, nullptr, 768, 192, nullptr, p_h1);
    gemm_mma<EPI_RES><<<dim3(192 / 64, MB), 128, SM_TOT>>>(p_h1, p_w2, fc2_b, out, 192, 768, p_x1, nullptr);
}

// round 12
// speedup vs baseline: 6.0371x; 1.0040x over previous
#include <cuda_runtime.h>
#include <cuda_bf16.h>
#include <math.h>
#include <stdint.h>

// ---------------- problem constants ----------------
#define C_     192
#define NHEAD  6
#define HID_   768
#define BATCH  32
#define NWTOT  2048
#define MROWS  100352      // NWTOT * 49

// ---------------- scratch (device globals) ----------------
__device__ __nv_bfloat16  g_qkv [(size_t)MROWS * 3 * C_];
__device__ float          g_x1  [(size_t)MROWS * C_];
__device__ __nv_bfloat16  g_xw  [(size_t)MROWS * C_];
__device__ __nv_bfloat16  g_at  [(size_t)MROWS * C_];
__device__ __nv_bfloat16  g_x2  [(size_t)MROWS * C_];
__device__ __nv_bfloat16  g_h1  [(size_t)MROWS * HID_];
__device__ __nv_bfloat16  g_wq[576 * 192];
__device__ __nv_bfloat16  g_wp[192 * 192];
__device__ __nv_bfloat16  g_w1[768 * 192];
__device__ __nv_bfloat16  g_w2[192 * 768];
__device__ __nv_bfloat16  g_battn[24 * 4096];   // [class(4) x head(6)][64x64] bias+mask (bf16)

// ---------------- helpers ----------------
__device__ __forceinline__ uint32_t smem_u32(const void* p) {
    uint32_t a;
    asm("{ .reg .u64 t; cvta.to.shared.u64 t, %1; cvt.u32.u64 %0, t; }" : "=r"(a) : "l"(p));
    return a;
}
__device__ __forceinline__ float warp_sum(float v) {
#pragma unroll
    for (int o = 16; o; o >>= 1) v += __shfl_xor_sync(0xffffffffu, v, o);
    return v;
}
__device__ __forceinline__ float gelu_exact(float x) {
    return 0.5f * x * (1.0f + erff(x * 0.70710678118654752f));
}
__device__ __forceinline__ uint32_t pack_bf2(float a, float b) {
    __nv_bfloat162 t = __floats2bfloat162_rn(a, b);
    return *(uint32_t*)&t;
}
// FMA-only exp (exp2 poly)
__device__ __forceinline__ float fast_exp(float x) {
    float t = fmaxf(x * 1.4426950408889634f, -126.0f);
    float n = floorf(t);
    float f = t - n;
    float p = 1.8775767e-3f;
    p = fmaf(p, f, 8.9893397e-3f);
    p = fmaf(p, f, 5.5804084e-2f);
    p = fmaf(p, f, 2.4013971e-1f);
    p = fmaf(p, f, 6.9314718e-1f);
    p = fmaf(p, f, 1.0f);
    return p * __int_as_float(((int)n + 127) << 23);
}

__device__ __forceinline__ void ldmat4(uint32_t* r, uint32_t addr) {
    asm volatile("ldmatrix.sync.aligned.m8n8.x4.shared.b16 {%0,%1,%2,%3}, [%4];"
        : "=r"(r[0]), "=r"(r[1]), "=r"(r[2]), "=r"(r[3]) : "r"(addr));
}
__device__ __forceinline__ void ldmat2(uint32_t* r, uint32_t addr) {
    asm volatile("ldmatrix.sync.aligned.m8n8.x2.shared.b16 {%0,%1}, [%2];"
        : "=r"(r[0]), "=r"(r[1]) : "r"(addr));
}
__device__ __forceinline__ void ldmat2t(uint32_t* r, uint32_t addr) {
    asm volatile("ldmatrix.sync.aligned.m8n8.x2.trans.shared.b16 {%0,%1}, [%2];"
        : "=r"(r[0]), "=r"(r[1]) : "r"(addr));
}
__device__ __forceinline__ void mma16816(float* d, const uint32_t* a, const uint32_t* b) {
    asm volatile("mma.sync.aligned.m16n8k16.row.col.f32.bf16.bf16.f32 "
        "{%0,%1,%2,%3}, {%4,%5,%6,%7}, {%8,%9}, {%0,%1,%2,%3};"
        : "+f"(d[0]), "+f"(d[1]), "+f"(d[2]), "+f"(d[3])
        : "r"(a[0]), "r"(a[1]), "r"(a[2]), "r"(a[3]), "r"(b[0]), "r"(b[1]));
}
#define CP16(dst, src) \
    asm volatile("cp.async.cg.shared.global [%0], [%1], 16;" :: "r"(dst), "l"(src))
#define CP_COMMIT() asm volatile("cp.async.commit_group;" ::: "memory")
#define CP_WAIT(n)  asm volatile("cp.async.wait_group %0;" :: "n"(n) : "memory")

// ---------------- all weights fp32 -> bf16, one launch ----------------
#define SEG0 110592
#define SEG1 147456
#define SEG2 294912
#define SEG3 442368
__global__ void convert_all(const float* __restrict__ qkv_w, const float* __restrict__ proj_w,
                            const float* __restrict__ fc1_w, const float* __restrict__ fc2_w,
                            __nv_bfloat16* __restrict__ wq, __nv_bfloat16* __restrict__ wp,
                            __nv_bfloat16* __restrict__ w1, __nv_bfloat16* __restrict__ w2) {
    int i = blockIdx.x * blockDim.x + threadIdx.x;
    if (i < SEG0)       wq[i]        = __float2bfloat16(qkv_w[i]);
    else if (i < SEG1)  wp[i - SEG0] = __float2bfloat16(proj_w[i - SEG0]);
    else if (i < SEG2)  w1[i - SEG1] = __float2bfloat16(fc1_w[i - SEG1]);
    else if (i < SEG3)  w2[i - SEG2] = __float2bfloat16(fc2_w[i - SEG2]);
}

// ---------------- build attention bias+mask tables (bf16) ----------------
__global__ void build_battn(const float* __restrict__ bt, __nv_bfloat16* __restrict__ battn) {
    int cls  = blockIdx.x / NHEAD;
    int head = blockIdx.x % NHEAD;
    __nv_bfloat16* T = battn + (size_t)blockIdx.x * 4096;
    for (int i = threadIdx.x; i < 4096; i += 256) {
        int r = i >> 6, c = i & 63;
        float v = -1e30f;
        if (r < 49 && c < 49) {
            int rr = ((cls & 1) ? ((r / 7 < 4) ? 1 : 2) : 0) * 3
                   + ((cls & 2) ? ((r % 7 < 4) ? 1 : 2) : 0);
            int rc = ((cls & 1) ? ((c / 7 < 4) ? 1 : 2) : 0) * 3
                   + ((cls & 2) ? ((c % 7 < 4) ? 1 : 2) : 0);
            int rel = (r / 7 - c / 7 + 6) * 13 + (r % 7 - c % 7 + 6);
            v = bt[rel * NHEAD + head] + ((rr != rc) ? -100.0f : 0.0f);
        }
        T[i] = __float2bfloat16(v);
    }
}

// ---------------- LN1 + cyclic shift + window partition -> bf16 ----------------
__global__ void ln_partition_kernel(const float* __restrict__ x,
                                    const float* __restrict__ g,
                                    const float* __restrict__ bt,
                                    __nv_bfloat16* __restrict__ o) {
    int warp = (blockIdx.x * blockDim.x + threadIdx.x) >> 5;
    int lane = threadIdx.x & 31;
    if (warp >= MROWS) return;
    int n = warp % 49;
    int window = warp / 49;
    int wi = window & 63;
    int b  = window >> 6;
    int wh = wi >> 3, ww = wi & 7;
    int h = wh * 7 + n / 7 + 3; if (h >= 56) h -= 56;
    int w = ww * 7 + n % 7 + 3; if (w >= 56) w -= 56;
    const float* xi = x + ((size_t)b * 3136 + h * 56 + w) * 192;

    float v[6]; float s1 = 0.f;
#pragma unroll
    for (int j = 0; j < 6; j++) { v[j] = xi[lane + 32 * j]; s1 += v[j]; }
    s1 = warp_sum(s1);
    float mean = s1 * (1.0f / 192.0f);
    float s2 = 0.f;
#pragma unroll
    for (int j = 0; j < 6; j++) { float d = v[j] - mean; s2 += d * d; }
    s2 = warp_sum(s2);
    float inv = rsqrtf(s2 * (1.0f / 192.0f) + 1e-5f);
    size_t base = (size_t)warp * 192;
#pragma unroll
    for (int j = 0; j < 6; j++) {
        int c = lane + 32 * j;
        o[base + c] = __float2bfloat16((v[j] - mean) * inv * g[c] + bt[c]);
    }
}

// ---------------- LN2 -> bf16 ----------------
__global__ void ln_plain_kernel(const float* __restrict__ x,
                                const float* __restrict__ g,
                                const float* __restrict__ bt,
                                __nv_bfloat16* __restrict__ o) {
    int warp = (blockIdx.x * blockDim.x + threadIdx.x) >> 5;
    int lane = threadIdx.x & 31;
    if (warp >= MROWS) return;
    const float* xi = x + (size_t)warp * 192;
    float v[6]; float s1 = 0.f;
#pragma unroll
    for (int j = 0; j < 6; j++) { v[j] = xi[lane + 32 * j]; s1 += v[j]; }
    s1 = warp_sum(s1);
    float mean = s1 * (1.0f / 192.0f);
    float s2 = 0.f;
#pragma unroll
    for (int j = 0; j < 6; j++) { float d = v[j] - mean; s2 += d * d; }
    s2 = warp_sum(s2);
    float inv = rsqrtf(s2 * (1.0f / 192.0f) + 1e-5f);
    size_t base = (size_t)warp * 192;
#pragma unroll
    for (int j = 0; j < 6; j++) {
        int c = lane + 32 * j;
        o[base + c] = __float2bfloat16((v[j] - mean) * inv * g[c] + bt[c]);
    }
}

// ---------------- attention: HMMA, 2 windows (same class) x 1 head per block ----------------
__global__ void __launch_bounds__(256)
attn_kernel(const __nv_bfloat16* __restrict__ qkv,
            const __nv_bfloat16* __restrict__ battn,
            __nv_bfloat16* __restrict__ outp) {
    __shared__ __align__(16) char sQ[2][64 * 80];
    __shared__ __align__(16) char sK[2][64 * 80];
    __shared__ __align__(16) char sV[2][64 * 80];
    __shared__ __align__(16) __nv_bfloat16 sT[4096];

    const int head = blockIdx.x % NHEAD;
    const int t    = blockIdx.x / NHEAD;       // 0..1023
    const int qp   = t >> 6;                   // batch pair 0..15
    const int wi   = t & 63;
    const int tid  = threadIdx.x;
    const int sub  = tid >> 7;                 // 0/1: window within pair
    const int ltid = tid & 127;
    const int wrp  = ltid >> 5;
    const int lane = tid & 31;
    const int window = 128 * qp + sub * 64 + wi;

    const __nv_bfloat16* wbase = qkv + (size_t)window * 49 * 576 + head * 32;
    for (int i = ltid; i < 588; i += 128) {
        int mat = i / 196, rem = i - mat * 196;
        int row = rem >> 2, ch = rem & 3;
        uint4 v = *(const uint4*)(wbase + (size_t)row * 576 + mat * 192 + ch * 8);
        char* dst = (mat == 0) ? sQ[sub] : (mat == 1) ? sK[sub] : sV[sub];
        *(uint4*)(dst + row * 80 + ch * 16) = v;
    }
    for (int i = ltid; i < 225; i += 128) {
        int mat = i / 75, rr = i - mat * 75;
        int row = 49 + rr / 5, ch = rr % 5;
        char* dst = (mat == 0) ? sQ[sub] : (mat == 1) ? sK[sub] : sV[sub];
        *(uint4*)(dst + row * 80 + ch * 16) = make_uint4(0, 0, 0, 0);
    }
    {
        int cls = ((wi >> 3) == 7 ? 1 : 0) + ((wi & 7) == 7 ? 2 : 0);
        const __nv_bfloat16* gT = battn + (size_t)(cls * NHEAD + head) * 4096;
        for (int i = tid; i < 512; i += 256)
            *(uint4*)(sT + i * 8) = *(const uint4*)(gT + i * 8);
    }
    __syncthreads();

    const uint32_t sQu = smem_u32(sQ[sub]), sKu = smem_u32(sK[sub]), sVu = smem_u32(sV[sub]);

    uint32_t qa[2][4];
    {
        uint32_t qaddr = sQu + (uint32_t)(16 * wrp + (lane & 15)) * 80 + ((lane >> 4) * 16);
        ldmat4(qa[0], qaddr);
        ldmat4(qa[1], qaddr + 32);
    }
    float acc[8][4];
#pragma unroll
    for (int nt = 0; nt < 8; nt++)
#pragma unroll
        for (int q = 0; q < 4; q++) acc[nt][q] = 0.f;

    const uint32_t krow = (uint32_t)(lane & 7) * 80 + ((lane & 8) ? 16 : 0);
#pragma unroll
    for (int nt = 0; nt < 8; nt++) {
#pragma unroll
        for (int kk = 0; kk < 2; kk++) {
            uint32_t b[2];
            ldmat2(b, sKu + nt * 640 + kk * 32 + krow);
            mma16816(acc[nt], qa[kk], b);
        }
    }

    const float scale = 0.17677669529663687f;
    const int tr = lane >> 2;
    const int tc = (lane & 3) * 2;
    const __nv_bfloat16* T0 = sT + (16 * wrp + tr) * 64;
    const __nv_bfloat16* T1 = T0 + 8 * 64;
#pragma unroll
    for (int nt = 0; nt < 8; nt++) {
        int c = 8 * nt + tc;
        float2 t0 = __bfloat1622float2(*(const __nv_bfloat162*)(T0 + c));
        float2 t1 = __bfloat1622float2(*(const __nv_bfloat162*)(T1 + c));
        acc[nt][0] = fmaf(acc[nt][0], scale, t0.x);
        acc[nt][1] = fmaf(acc[nt][1], scale, t0.y);
        acc[nt][2] = fmaf(acc[nt][2], scale, t1.x);
        acc[nt][3] = fmaf(acc[nt][3], scale, t1.y);
    }

    float m0 = -1e30f, m1 = -1e30f;
#pragma unroll
    for (int nt = 0; nt < 8; nt++) {
        m0 = fmaxf(m0, fmaxf(acc[nt][0], acc[nt][1]));
        m1 = fmaxf(m1, fmaxf(acc[nt][2], acc[nt][3]));
    }
    m0 = fmaxf(m0, __shfl_xor_sync(0xffffffffu, m0, 1));
    m0 = fmaxf(m0, __shfl_xor_sync(0xffffffffu, m0, 2));
    m1 = fmaxf(m1, __shfl_xor_sync(0xffffffffu, m1, 1));
    m1 = fmaxf(m1, __shfl_xor_sync(0xffffffffu, m1, 2));
    float s0 = 0.f, s1 = 0.f;
#pragma unroll
    for (int nt = 0; nt < 8; nt++) {
        acc[nt][0] = fast_exp(acc[nt][0] - m0); s0 += acc[nt][0];
        acc[nt][1] = fast_exp(acc[nt][1] - m0); s0 += acc[nt][1];
        acc[nt][2] = fast_exp(acc[nt][2] - m1); s1 += acc[nt][2];
        acc[nt][3] = fast_exp(acc[nt][3] - m1); s1 += acc[nt][3];
    }
    s0 += __shfl_xor_sync(0xffffffffu, s0, 1);
    s0 += __shfl_xor_sync(0xffffffffu, s0, 2);
    s1 += __shfl_xor_sync(0xffffffffu, s1, 1);
    s1 += __shfl_xor_sync(0xffffffffu, s1, 2);
    const float i0 = __frcp_rn(s0), i1 = __frcp_rn(s1);

    uint32_t pa[4][4];
#pragma unroll
    for (int kk = 0; kk < 4; kk++) {
        pa[kk][0] = pack_bf2(acc[2 * kk][0] * i0, acc[2 * kk][1] * i0);
        pa[kk][1] = pack_bf2(acc[2 * kk][2] * i1, acc[2 * kk][3] * i1);
        pa[kk][2] = pack_bf2(acc[2 * kk + 1][0] * i0, acc[2 * kk + 1][1] * i0);
        pa[kk][3] = pack_bf2(acc[2 * kk + 1][2] * i1, acc[2 * kk + 1][3] * i1);
    }

    float o[4][4];
#pragma unroll
    for (int nt = 0; nt < 4; nt++)
#pragma unroll
        for (int q = 0; q < 4; q++) o[nt][q] = 0.f;

    const uint32_t vrow = sVu + (uint32_t)(lane & 15) * 80;
#pragma unroll
    for (int kk = 0; kk < 4; kk++) {
#pragma unroll
        for (int nt = 0; nt < 4; nt++) {
            uint32_t b[2];
            ldmat2t(b, vrow + kk * (16 * 80) + nt * 16);
            mma16816(o[nt], pa[kk], b);
        }
    }

    const int gr0 = 16 * wrp + tr, gr1 = gr0 + 8;
    __nv_bfloat16* ob = outp + (size_t)window * 49 * 192 + head * 32;
#pragma unroll
    for (int nt = 0; nt < 4; nt++) {
        int d = 8 * nt + tc;
        if (gr0 < 49) *(uint32_t*)(ob + (size_t)gr0 * 192 + d) = pack_bf2(o[nt][0], o[nt][1]);
        if (gr1 < 49) *(uint32_t*)(ob + (size_t)gr1 * 192 + d) = pack_bf2(o[nt][2], o[nt][3]);
    }
}

// ---------------- bf16 mma GEMM: BM=128, BN=64, 4 warps, 2-stage, SINGLE sync/iter ----------------
#define SB_OFF 16384                  // 128 rows * 128B
#define STAGE  24576                  // + 64 rows * 128B
#define SM_TOT (2 * STAGE)            // 49152

enum { EPI_QKV = 0, EPI_PROJ = 1, EPI_GELU = 2, EPI_RES = 3 };

__device__ __forceinline__ size_t proj_row(int m) {
    int n = m % 49, window = m / 49;
    int wi = window & 63, b = window >> 6;
    int wh = wi >> 3, ww = wi & 7;
    int hh = wh * 7 + n / 7 + 3; if (hh >= 56) hh -= 56;
    int wc = ww * 7 + n % 7 + 3; if (wc >= 56) wc -= 56;
    return ((size_t)b * 3136 + (size_t)hh * 56 + wc) * 192;
}

template<int EPI>
__global__ void __launch_bounds__(128, 4)
gemm_mma(const __nv_bfloat16* __restrict__ A, const __nv_bfloat16* __restrict__ W,
         const float* __restrict__ bias, float* __restrict__ Cout,
         int Nn, int Ktot, const float* __restrict__ extra,
         __nv_bfloat16* __restrict__ obf) {
    extern __shared__ __align__(16) char sm[];
    const uint32_t sb = smem_u32(sm);
    const int tid  = threadIdx.x;
    const int wid  = tid >> 5;
    const int lane = tid & 31;
    const int warpM = wid >> 1;          // 0..1, 64 rows each
    const int warpN = wid & 1;           // 0..1, 32 cols each
    const int bm = blockIdx.y * 128;
    const int bn = blockIdx.x * 64;

    const __nv_bfloat16* A_b = A + (size_t)bm * Ktot;
    const __nv_bfloat16* W_b = W + (size_t)bn * Ktot;

    const int rowA = warpM * 64 + (lane & 15);
    const uint32_t aBase = (uint32_t)rowA * 128;
    const int axp = (lane >> 4) ^ (rowA & 7);
    const int rowB = warpN * 32 + ((lane >> 4) & 1) * 8 + (lane & 7);
    const uint32_t bBase = SB_OFF + (uint32_t)rowB * 128;
    const int bxp = ((lane >> 3) & 1) ^ (lane & 7);

    float acc[4][4][4];
#pragma unroll
    for (int i = 0; i < 4; i++)
#pragma unroll
        for (int j = 0; j < 4; j++)
#pragma unroll
            for (int k = 0; k < 4; k++) acc[i][j][k] = 0.f;

    const int NK = Ktot >> 6;   // K / 64

    // stage loader: A 128x64 bf16 (1024x16B), B 64x64 (512x16B), swizzled, 128 threads
    auto stage_load = [&](int buf, int k0) {
        uint32_t d = sb + buf * STAGE;
#pragma unroll
        for (int i = 0; i < 8; i++) {
            int idx = tid + 128 * i;
            int row = idx >> 3, ch = idx & 7;
            CP16(d + row * 128 + ((ch ^ (row & 7)) << 4), A_b + (size_t)row * Ktot + k0 + ch * 8);
        }
#pragma unroll
        for (int i = 0; i < 4; i++) {
            int idx = tid + 128 * i;
            int row = idx >> 3, ch = idx & 7;
            CP16(d + SB_OFF + row * 128 + ((ch ^ (row & 7)) << 4), W_b + (size_t)row * Ktot + k0 + ch * 8);
        }
        CP_COMMIT();
    };

    stage_load(0, 0);

    for (int k = 0; k < NK; k++) {
        CP_WAIT(0);             // stage k is resident
        __syncthreads();        // all warps done with the OTHER buffer -> safe to overwrite
        if (k + 1 < NK) stage_load((k + 1) & 1, (k + 1) << 6);  // overlaps the mma body below

        const uint32_t soff = sb + (k & 1) * STAGE;
        const uint32_t aaddr = soff + aBase;
        const uint32_t baddr = soff + bBase;

#pragma unroll
        for (int kk = 0; kk < 4; kk++) {
            const uint32_t xa = (uint32_t)((2 * kk) ^ axp) << 4;
            const uint32_t xb = (uint32_t)((2 * kk) ^ bxp) << 4;
            uint32_t a0[4], a1[4], a2[4], a3[4];
            ldmat4(a0, aaddr + xa);
            ldmat4(a1, aaddr + 2048 + xa);
            ldmat4(a2, aaddr + 4096 + xa);
            ldmat4(a3, aaddr + 6144 + xa);
#pragma unroll
            for (int ng = 0; ng < 2; ng++) {
                uint32_t bh[4];
                ldmat4(bh, baddr + ng * 2048 + xb);
#pragma unroll
                for (int q = 0; q < 2; q++) {
                    int ni = ng * 2 + q;
                    mma16816(acc[0][ni], a0, bh + 2 * q);
                    mma16816(acc[1][ni], a1, bh + 2 * q);
                    mma16816(acc[2][ni], a2, bh + 2 * q);
                    mma16816(acc[3][ni], a3, bh + 2 * q);
                }
            }
        }
    }

    // ---------------- epilogue ----------------
    const int lrow = lane >> 2, lcol = (lane & 3) * 2;
#pragma unroll
    for (int mi = 0; mi < 4; mi++) {
        int m0 = bm + warpM * 64 + mi * 16 + lrow;
        int m1 = m0 + 8;
        size_t r0, r1;
        if (EPI == EPI_PROJ) { r0 = proj_row(m0); r1 = proj_row(m1); }
        else { r0 = (size_t)m0 * Nn; r1 = (size_t)m1 * Nn; }
#pragma unroll
        for (int ni = 0; ni < 4; ni++) {
            int n = bn + warpN * 32 + ni * 8 + lcol;
            float bx = bias[n], by = bias[n + 1];
            float v0x = acc[mi][ni][0] + bx, v0y = acc[mi][ni][1] + by;
            float v1x = acc[mi][ni][2] + bx, v1y = acc[mi][ni][3] + by;
            if (EPI == EPI_QKV) {
                *(uint32_t*)(obf + r0 + n) = pack_bf2(v0x, v0y);
                *(uint32_t*)(obf + r1 + n) = pack_bf2(v1x, v1y);
            } else if (EPI == EPI_GELU) {
                *(uint32_t*)(obf + r0 + n) = pack_bf2(gelu_exact(v0x), gelu_exact(v0y));
                *(uint32_t*)(obf + r1 + n) = pack_bf2(gelu_exact(v1x), gelu_exact(v1y));
            } else {
                float2 e0 = *(const float2*)(extra + r0 + n);
                float2 e1 = *(const float2*)(extra + r1 + n);
                *(float2*)(Cout + r0 + n) = make_float2(v0x + e0.x, v0y + e0.y);
                *(float2*)(Cout + r1 + n) = make_float2(v1x + e1.x, v1y + e1.y);
            }
        }
    }
}

// ---------------- launch ----------------
extern "C" void kernel_launch(void* const* d_in, const int* in_sizes, int n_in,
                              void* d_out, int out_size) {
    const float* x      = (const float*)d_in[0];
    const float* g1     = (const float*)d_in[1];
    const float* b1     = (const float*)d_in[2];
    const float* qkv_w  = (const float*)d_in[3];
    const float* qkv_b  = (const float*)d_in[4];
    const float* proj_w = (const float*)d_in[5];
    const float* proj_b = (const float*)d_in[6];
    const float* bias_t = (const float*)d_in[7];
    const float* g2     = (const float*)d_in[8];
    const float* b2     = (const float*)d_in[9];
    const float* fc1_w  = (const float*)d_in[10];
    const float* fc1_b  = (const float*)d_in[11];
    const float* fc2_w  = (const float*)d_in[12];
    const float* fc2_b  = (const float*)d_in[13];
    float* out = (float*)d_out;

    float* p_x1;
    __nv_bfloat16 *p_qkv, *p_xw, *p_at, *p_x2, *p_h1, *p_wq, *p_wp, *p_w1, *p_w2, *p_battn;
    cudaGetSymbolAddress((void**)&p_qkv, g_qkv);
    cudaGetSymbolAddress((void**)&p_x1,  g_x1);
    cudaGetSymbolAddress((void**)&p_xw,  g_xw);
    cudaGetSymbolAddress((void**)&p_at,  g_at);
    cudaGetSymbolAddress((void**)&p_x2,  g_x2);
    cudaGetSymbolAddress((void**)&p_h1,  g_h1);
    cudaGetSymbolAddress((void**)&p_wq,  g_wq);
    cudaGetSymbolAddress((void**)&p_wp,  g_wp);
    cudaGetSymbolAddress((void**)&p_w1,  g_w1);
    cudaGetSymbolAddress((void**)&p_w2,  g_w2);
    cudaGetSymbolAddress((void**)&p_battn, g_battn);

    cudaFuncSetAttribute(gemm_mma<EPI_QKV>,  cudaFuncAttributeMaxDynamicSharedMemorySize, SM_TOT);
    cudaFuncSetAttribute(gemm_mma<EPI_PROJ>, cudaFuncAttributeMaxDynamicSharedMemorySize, SM_TOT);
    cudaFuncSetAttribute(gemm_mma<EPI_GELU>, cudaFuncAttributeMaxDynamicSharedMemorySize, SM_TOT);
    cudaFuncSetAttribute(gemm_mma<EPI_RES>,  cudaFuncAttributeMaxDynamicSharedMemorySize, SM_TOT);

    const int MB = MROWS / 128;  // 784

    convert_all<<<SEG3 / 256, 256>>>(qkv_w, proj_w, fc1_w, fc2_w, p_wq, p_wp, p_w1, p_w2);
    build_battn<<<24, 256>>>(bias_t, p_battn);
    ln_partition_kernel<<<MROWS / 8, 256>>>(x, g1, b1, p_xw);
    gemm_mma<EPI_QKV><<<dim3(576 / 64, MB), 128, SM_TOT>>>(p_xw, p_wq, qkv_b, nullptr, 576, 192, nullptr, p_qkv);
    attn_kernel<<<NWTOT * NHEAD / 2, 256>>>(p_qkv, p_battn, p_at);
    gemm_mma<EPI_PROJ><<<dim3(192 / 64, MB), 128, SM_TOT>>>(p_at, p_wp, proj_b, p_x1, 192, 192, x, nullptr);
    ln_plain_kernel<<<MROWS / 8, 256>>>(p_x1, g2, b2, p_x2);
    gemm_mma<EPI_GELU><<<dim3(768 / 64, MB), 128, SM_TOT>>>(p_x2, p_w1, fc1_b, nullptr, 768, 192, nullptr, p_h1);
    gemm_mma<EPI_RES><<<dim3(192 / 64, MB), 128, SM_TOT>>>(p_h1, p_w2, fc2_b, out, 192, 768, p_x1, nullptr);
}